// round 1
// baseline (speedup 1.0000x reference)
#include <cuda_runtime.h>
#include <math.h>

#define BB 32
#define TT 12
#define NN 512
#define HH 64
#define EE 16
#define BTN (BB*TT*NN)
#define BTNH (BTN*HH)

// ---------------- scratch (device globals; no allocation allowed) ----------------
__device__ float g_adj[NN*NN];
__device__ float g_gW[NN*2*128*128];   // gate weights (max layer-1 size)
__device__ float g_gb[NN*128];
__device__ float g_uW[NN*2*128*64];    // update weights (layer-1 persists for hyp)
__device__ float g_ub[NN*64];
__device__ float g_state[BB*NN*HH];
__device__ float g_xs[BB*NN*128];
__device__ float g_xsmix[BB*NN*128];
__device__ float g_zs[BB*NN*HH];
__device__ float g_r[BB*NN*HH];
__device__ float g_hs0[BTNH];
__device__ float g_hs1[BTNH];
__device__ float g_fs[NN*TT];
__device__ float g_hv[BTNH];
__device__ float g_q[BTNH];
__device__ float g_k[BTNH];
__device__ float g_v[BTNH];
__device__ float g_o[BTNH];
__device__ float g_val[BTNH];
__device__ float g_ff1[BTNH];
__device__ float g_ffo[BTNH];
__device__ float g_out2[BTNH];

// ---------------- kernels ----------------

__global__ void k_zero(float* __restrict__ p, int n) {
    int i = blockIdx.x * blockDim.x + threadIdx.x;
    int stride = gridDim.x * blockDim.x;
    for (; i < n; i += stride) p[i] = 0.f;
}

// adj = softmax(relu(E E^T), axis=1). One block per row.
__global__ void k_adj(const float* __restrict__ emb) {
    __shared__ float semb[NN*EE];
    __shared__ float row[NN];
    __shared__ float red[256];
    int n = blockIdx.x;
    for (int i = threadIdx.x; i < NN*EE; i += blockDim.x) semb[i] = emb[i];
    __syncthreads();
    float lmax = -1e30f;
    for (int m = threadIdx.x; m < NN; m += blockDim.x) {
        float s = 0.f;
        #pragma unroll
        for (int e = 0; e < EE; ++e) s += semb[n*EE+e] * semb[m*EE+e];
        s = fmaxf(s, 0.f);
        row[m] = s;
        lmax = fmaxf(lmax, s);
    }
    red[threadIdx.x] = lmax; __syncthreads();
    for (int s = 128; s > 0; s >>= 1) {
        if (threadIdx.x < s) red[threadIdx.x] = fmaxf(red[threadIdx.x], red[threadIdx.x+s]);
        __syncthreads();
    }
    float mx = red[0];
    __syncthreads();
    float lsum = 0.f;
    for (int m = threadIdx.x; m < NN; m += blockDim.x) {
        float v = expf(row[m] - mx);
        row[m] = v; lsum += v;
    }
    red[threadIdx.x] = lsum; __syncthreads();
    for (int s = 128; s > 0; s >>= 1) {
        if (threadIdx.x < s) red[threadIdx.x] += red[threadIdx.x+s];
        __syncthreads();
    }
    float inv = 1.f / red[0];
    for (int m = threadIdx.x; m < NN; m += blockDim.x) g_adj[n*NN + m] = row[m] * inv;
}

// out[n*S + i] = sum_e emb[n,e] * pool[e*S + i]
__global__ void k_matpool(const float* __restrict__ emb, const float* __restrict__ pool,
                          float* __restrict__ out, int S) {
    int total = NN * S;
    int stride = gridDim.x * blockDim.x;
    for (int idx = blockIdx.x*blockDim.x + threadIdx.x; idx < total; idx += stride) {
        int n = idx / S, i = idx - n*S;
        float a = 0.f;
        #pragma unroll
        for (int e = 0; e < EE; ++e) a += emb[n*EE+e] * pool[e*S + i];
        out[idx] = a;
    }
}

// xs[b,m,0:Cin] = xt[b,t,m,:]; xs[b,m,Cin:Cin+H] = tail[b,m,:]
__global__ void k_concat(const float* __restrict__ xt, int t, int Cin,
                         const float* __restrict__ tail, float* __restrict__ xs) {
    int C = Cin + HH;
    int total = BB * NN * C;
    int stride = gridDim.x * blockDim.x;
    for (int idx = blockIdx.x*blockDim.x + threadIdx.x; idx < total; idx += stride) {
        int b = idx / (NN*C);
        int rem = idx - b*(NN*C);
        int m = rem / C;
        int c = rem - m*C;
        float v = (c < Cin) ? xt[((b*TT + t)*NN + m)*Cin + c]
                            : tail[(b*NN + m)*HH + (c - Cin)];
        xs[idx] = v;
    }
}

// Y[b,n,c] = sum_m adj[n,m] X[b,m,c]  (64x64 tile GEMM, k-tile 32)
__global__ void k_mix(const float* __restrict__ X, float* __restrict__ Y, int C) {
    __shared__ float As[32][65];
    __shared__ float Bs[32][65];
    int n0 = blockIdx.x * 64;
    int c0 = blockIdx.y * 64;
    int b  = blockIdx.z;
    int tid = threadIdx.x;
    int tx = tid & 15, ty = tid >> 4;
    int i0 = ty * 4, j0 = tx * 4;
    float acc[4][4] = {};
    const float* Xb = X + b * NN * C;
    for (int mt = 0; mt < NN; mt += 32) {
        #pragma unroll
        for (int r = 0; r < 8; ++r) {
            int idx = tid + r * 256;
            int kk = idx & 31, i = idx >> 5;
            As[kk][i] = g_adj[(n0 + i)*NN + mt + kk];
        }
        #pragma unroll
        for (int r = 0; r < 8; ++r) {
            int idx = tid + r * 256;
            int c = idx & 63, kk = idx >> 6;
            int col = c0 + c;
            Bs[kk][c] = (col < C) ? Xb[(mt + kk)*C + col] : 0.f;
        }
        __syncthreads();
        #pragma unroll
        for (int kk = 0; kk < 32; ++kk) {
            float a[4], w[4];
            #pragma unroll
            for (int r = 0; r < 4; ++r) a[r] = As[kk][i0 + r];
            #pragma unroll
            for (int c = 0; c < 4; ++c) w[c] = Bs[kk][j0 + c];
            #pragma unroll
            for (int r = 0; r < 4; ++r)
                #pragma unroll
                for (int c = 0; c < 4; ++c)
                    acc[r][c] = fmaf(a[r], w[c], acc[r][c]);
        }
        __syncthreads();
    }
    float* Yb = Y + b * NN * C;
    #pragma unroll
    for (int r = 0; r < 4; ++r)
        #pragma unroll
        for (int c = 0; c < 4; ++c) {
            int col = c0 + j0 + c;
            if (col < C) Yb[(n0 + i0 + r)*C + col] = acc[r][c];
        }
}

// Gate gconv + sigmoid + split; writes zs = z*state and r. One block per node.
__global__ void k_gate(const float* __restrict__ xs, const float* __restrict__ xsm,
                       const float* __restrict__ gW, const float* __restrict__ gb,
                       int C, int Cin) {
    __shared__ float s0[32][128];
    __shared__ float s1[32][128];
    int n = blockIdx.x;
    int o = threadIdx.x;  // 128 threads, one output channel each
    for (int idx = threadIdx.x; idx < 32*C; idx += 128) {
        int b = idx / C, c = idx - b*C;
        s0[b][c] = xs[(b*NN + n)*C + c];
        s1[b][c] = xsm[(b*NN + n)*C + c];
    }
    __syncthreads();
    float acc[32];
    #pragma unroll
    for (int b = 0; b < 32; ++b) acc[b] = 0.f;
    const float* W0 = gW + (size_t)(n*2)*C*128 + o;
    const float* W1 = gW + (size_t)(n*2 + 1)*C*128 + o;
    for (int c = 0; c < C; c += 2) {
        float w0 = W0[c*128], w1 = W0[c*128 + 128];
        #pragma unroll
        for (int b = 0; b < 32; ++b) {
            float2 x = *reinterpret_cast<const float2*>(&s0[b][c]);
            acc[b] = fmaf(x.x, w0, acc[b]);
            acc[b] = fmaf(x.y, w1, acc[b]);
        }
    }
    for (int c = 0; c < C; c += 2) {
        float w0 = W1[c*128], w1 = W1[c*128 + 128];
        #pragma unroll
        for (int b = 0; b < 32; ++b) {
            float2 x = *reinterpret_cast<const float2*>(&s1[b][c]);
            acc[b] = fmaf(x.x, w0, acc[b]);
            acc[b] = fmaf(x.y, w1, acc[b]);
        }
    }
    float bias = gb[n*128 + o];
    if (o < HH) {
        #pragma unroll
        for (int b = 0; b < 32; ++b) {
            float z = 1.f / (1.f + expf(-(acc[b] + bias)));
            g_zs[(b*NN + n)*HH + o] = z * s0[b][Cin + o];
        }
    } else {
        int oo = o - HH;
        #pragma unroll
        for (int b = 0; b < 32; ++b) {
            float rr = 1.f / (1.f + expf(-(acc[b] + bias)));
            g_r[(b*NN + n)*HH + oo] = rr;
        }
    }
}

// Candidate gconv + tanh + GRU combine; writes new state and hs[:,t].
__global__ void k_upd(const float* __restrict__ xs, const float* __restrict__ xsm,
                      const float* __restrict__ uW, const float* __restrict__ ub,
                      int C, float* __restrict__ hs, int t) {
    __shared__ float s0[32][128];
    __shared__ float s1[32][128];
    int n = blockIdx.x;
    int tid = threadIdx.x;  // 128
    int o = tid & 63, half = tid >> 6;
    for (int idx = tid; idx < 32*C; idx += 128) {
        int b = idx / C, c = idx - b*C;
        s0[b][c] = xs[(b*NN + n)*C + c];
        s1[b][c] = xsm[(b*NN + n)*C + c];
    }
    __syncthreads();
    float acc[16];
    #pragma unroll
    for (int i = 0; i < 16; ++i) acc[i] = 0.f;
    int b0 = half * 16;
    const float* W0 = uW + (size_t)(n*2)*C*64 + o;
    const float* W1 = uW + (size_t)(n*2 + 1)*C*64 + o;
    for (int c = 0; c < C; c += 2) {
        float w0 = W0[c*64], w1 = W0[c*64 + 64];
        #pragma unroll
        for (int i = 0; i < 16; ++i) {
            float2 x = *reinterpret_cast<const float2*>(&s0[b0+i][c]);
            acc[i] = fmaf(x.x, w0, acc[i]);
            acc[i] = fmaf(x.y, w1, acc[i]);
        }
    }
    for (int c = 0; c < C; c += 2) {
        float w0 = W1[c*64], w1 = W1[c*64 + 64];
        #pragma unroll
        for (int i = 0; i < 16; ++i) {
            float2 x = *reinterpret_cast<const float2*>(&s1[b0+i][c]);
            acc[i] = fmaf(x.x, w0, acc[i]);
            acc[i] = fmaf(x.y, w1, acc[i]);
        }
    }
    float bias = ub[n*64 + o];
    #pragma unroll
    for (int i = 0; i < 16; ++i) {
        int b = b0 + i;
        int idx = (b*NN + n)*HH + o;
        float rr = g_r[idx];
        float st = g_state[idx];
        float hc = tanhf(acc[i] + bias);
        float h = rr*st + (1.f - rr)*hc;
        g_state[idx] = h;
        hs[((b*TT + t)*NN + n)*HH + o] = h;
    }
}

// hlin = uW_flat @ hypW + hypb ; fs = group-sum of 4
__global__ void k_hyp(const float* __restrict__ hypW, const float* __restrict__ hypb) {
    __shared__ float part[192];
    __shared__ float hlin[48];
    int n = blockIdx.x;
    int tid = threadIdx.x;  // 192
    int j = tid % 48, sl = tid / 48;
    const float* u = g_uW + (size_t)n * 16384;
    float a = 0.f;
    int i0 = sl * 4096;
    for (int i = i0; i < i0 + 4096; ++i) a += u[i] * hypW[i*48 + j];
    part[tid] = a;
    __syncthreads();
    if (tid < 48) hlin[tid] = part[tid] + part[48+tid] + part[96+tid] + part[144+tid] + hypb[tid];
    __syncthreads();
    if (tid < 12) {
        g_fs[n*TT + tid] = hlin[tid*4] + hlin[tid*4+1] + hlin[tid*4+2] + hlin[tid*4+3];
    }
}

// hv[b,t,n,c] = hs1[b,T-1,n,c] * fs[n,t]
__global__ void k_hv() {
    int idx = blockIdx.x*blockDim.x + threadIdx.x;
    if (idx >= BTNH) return;
    int c = idx & 63;
    int bt_n = idx >> 6;
    int n = bt_n % NN;
    int bt = bt_n / NN;
    int t = bt % TT, b = bt / TT;
    g_hv[idx] = g_hs1[((b*TT + (TT-1))*NN + n)*HH + c] * g_fs[n*TT + t];
}

// Y[M,64] = act(X[M,64] @ W[64,64] + bias)
__global__ void k_gemm64(const float* __restrict__ X, const float* __restrict__ W,
                         const float* __restrict__ bias, float* __restrict__ Y, int relu) {
    __shared__ float Xs[64][65];
    __shared__ float Ws[64][65];
    int row0 = blockIdx.x * 64;
    int tid = threadIdx.x;
    int tx = tid & 15, ty = tid >> 4;
    #pragma unroll
    for (int r = 0; r < 16; ++r) {
        int idx = tid + r*256;
        int i = idx >> 6, k = idx & 63;
        Xs[i][k] = X[(size_t)(row0 + i)*64 + k];
        Ws[i][k] = W[idx];
    }
    __syncthreads();
    float acc[4][4] = {};
    int i0 = ty*4, j0 = tx*4;
    #pragma unroll 16
    for (int kk = 0; kk < 64; ++kk) {
        float a[4], w[4];
        #pragma unroll
        for (int r = 0; r < 4; ++r) a[r] = Xs[i0+r][kk];
        #pragma unroll
        for (int c = 0; c < 4; ++c) w[c] = Ws[kk][j0+c];
        #pragma unroll
        for (int r = 0; r < 4; ++r)
            #pragma unroll
            for (int c = 0; c < 4; ++c)
                acc[r][c] = fmaf(a[r], w[c], acc[r][c]);
    }
    #pragma unroll
    for (int r = 0; r < 4; ++r)
        #pragma unroll
        for (int c = 0; c < 4; ++c) {
            float v = acc[r][c] + bias[j0+c];
            if (relu) v = fmaxf(v, 0.f);
            Y[(size_t)(row0 + i0 + r)*64 + j0 + c] = v;
        }
}

// attention per (b,n): T=12, heads=2, d=32
__global__ void k_attn() {
    __shared__ float qs[12][64], ks[12][64], vs[12][64];
    __shared__ float sc[2][12][12];
    int bn = blockIdx.x;
    int b = bn / NN, n = bn - b*NN;
    int tid = threadIdx.x;  // 128
    for (int idx = tid; idx < 12*64; idx += 128) {
        int t = idx >> 6, c = idx & 63;
        int g = ((b*TT + t)*NN + n)*HH + c;
        qs[t][c] = g_q[g];
        ks[t][c] = g_k[g];
        vs[t][c] = g_v[g];
    }
    __syncthreads();
    for (int idx = tid; idx < 288; idx += 128) {
        int h = idx / 144, rem = idx - h*144;
        int t = rem / 12, s = rem - t*12;
        float d = 0.f;
        #pragma unroll
        for (int k = 0; k < 32; ++k) d += qs[t][h*32 + k] * ks[s][h*32 + k];
        sc[h][t][s] = d * 0.17677669529663687f;
    }
    __syncthreads();
    if (tid < 24) {
        int h = tid / 12, t = tid - h*12;
        float mx = -1e30f;
        #pragma unroll
        for (int s = 0; s < 12; ++s) mx = fmaxf(mx, sc[h][t][s]);
        float sum = 0.f;
        #pragma unroll
        for (int s = 0; s < 12; ++s) { float e = expf(sc[h][t][s] - mx); sc[h][t][s] = e; sum += e; }
        float inv = 1.f / sum;
        #pragma unroll
        for (int s = 0; s < 12; ++s) sc[h][t][s] *= inv;
    }
    __syncthreads();
    for (int idx = tid; idx < 768; idx += 128) {
        int h = idx / 384, rem = idx - h*384;
        int t = rem >> 5, d = rem & 31;
        float a = 0.f;
        #pragma unroll
        for (int s = 0; s < 12; ++s) a += sc[h][t][s] * vs[s][h*32 + d];
        g_o[((b*TT + t)*NN + n)*HH + h*32 + d] = a;
    }
}

// Y = LN(A + Bv) * g + beta (row length 64)
__global__ void k_lnres(const float* __restrict__ A, const float* __restrict__ Bv,
                        const float* __restrict__ g, const float* __restrict__ be,
                        float* __restrict__ Y) {
    __shared__ float red[64];
    size_t row = blockIdx.x;
    int c = threadIdx.x;
    float x = A[row*64 + c] + Bv[row*64 + c];
    red[c] = x; __syncthreads();
    for (int s = 32; s > 0; s >>= 1) { if (c < s) red[c] += red[c+s]; __syncthreads(); }
    float mu = red[0] * (1.f/64.f);
    __syncthreads();
    float d = x - mu;
    red[c] = d*d; __syncthreads();
    for (int s = 32; s > 0; s >>= 1) { if (c < s) red[c] += red[c+s]; __syncthreads(); }
    float var = red[0] * (1.f/64.f);
    Y[row*64 + c] = d * rsqrtf(var + 1e-5f) * g[c] + be[c];
}

// y[row] = dot(X[row,:], fcW) + fcb
__global__ void k_fc(const float* __restrict__ X, const float* __restrict__ w,
                     const float* __restrict__ bp, float* __restrict__ Y) {
    __shared__ float red[64];
    size_t row = blockIdx.x;
    int c = threadIdx.x;
    red[c] = X[row*64 + c] * w[c];
    __syncthreads();
    for (int s = 32; s > 0; s >>= 1) { if (c < s) red[c] += red[c+s]; __syncthreads(); }
    if (c == 0) Y[row] = red[0] + bp[0];
}

// ---------------- host ----------------

static void run_layer_host(const float* xt, int Cin,
                           float* p_gW, float* p_gb, float* p_uW, float* p_ub,
                           float* p_state, float* p_xs, float* p_xsmix,
                           float* hs_out) {
    int C = Cin + HH;
    int colTiles = (C + 63) / 64;
    dim3 mixGrid(NN/64, colTiles, BB);
    int concatBlocks = (BB*NN*C + 255) / 256;
    k_zero<<<1024, 256>>>(p_state, BB*NN*HH);
    for (int t = 0; t < TT; ++t) {
        k_concat<<<concatBlocks, 256>>>(xt, t, Cin, p_state, p_xs);
        k_mix<<<mixGrid, 256>>>(p_xs, p_xsmix, C);
        k_gate<<<NN, 128>>>(p_xs, p_xsmix, p_gW, p_gb, C, Cin);
        float* p_zs; cudaGetSymbolAddress((void**)&p_zs, g_zs);
        k_concat<<<concatBlocks, 256>>>(xt, t, Cin, p_zs, p_xs);
        k_mix<<<mixGrid, 256>>>(p_xs, p_xsmix, C);
        k_upd<<<NN, 128>>>(p_xs, p_xsmix, p_uW, p_ub, C, hs_out, t);
    }
}

extern "C" void kernel_launch(void* const* d_in, const int* in_sizes, int n_in,
                              void* d_out, int out_size) {
    const float* src  = (const float*)d_in[0];
    const float* emb  = (const float*)d_in[2];
    const float* gwp0 = (const float*)d_in[3];
    const float* gbp0 = (const float*)d_in[4];
    const float* uwp0 = (const float*)d_in[5];
    const float* ubp0 = (const float*)d_in[6];
    const float* gwp1 = (const float*)d_in[7];
    const float* gbp1 = (const float*)d_in[8];
    const float* uwp1 = (const float*)d_in[9];
    const float* ubp1 = (const float*)d_in[10];
    const float* hypW = (const float*)d_in[11];
    const float* hypb = (const float*)d_in[12];

    const float *Wq,*Wk,*Wv,*ffW1,*ffW2,*bq,*bk,*bv,*ffb1,*ffb2,*ln1g,*ln1b,*ln2g,*ln2b,*fcW,*fcb;
    if (n_in > 14 && in_sizes[14] == 64) {
        // reference-signature order: Wq,bq,Wk,bk,Wv,bv,ln1_g,ln1_b,ffW1,ffb1,ffW2,ffb2,ln2_g,ln2_b,fc_W,fc_b
        Wq  = (const float*)d_in[13]; bq  = (const float*)d_in[14];
        Wk  = (const float*)d_in[15]; bk  = (const float*)d_in[16];
        Wv  = (const float*)d_in[17]; bv  = (const float*)d_in[18];
        ln1g= (const float*)d_in[19]; ln1b= (const float*)d_in[20];
        ffW1= (const float*)d_in[21]; ffb1= (const float*)d_in[22];
        ffW2= (const float*)d_in[23]; ffb2= (const float*)d_in[24];
        ln2g= (const float*)d_in[25]; ln2b= (const float*)d_in[26];
        fcW = (const float*)d_in[27]; fcb = (const float*)d_in[28];
    } else {
        // setup_inputs dict order: Wq,Wk,Wv,ffW1,ffW2,bq,bk,bv,ffb1,ffb2,ln1_g,ln1_b,ln2_g,ln2_b,fc_W,fc_b
        Wq  = (const float*)d_in[13]; Wk  = (const float*)d_in[14];
        Wv  = (const float*)d_in[15]; ffW1= (const float*)d_in[16];
        ffW2= (const float*)d_in[17]; bq  = (const float*)d_in[18];
        bk  = (const float*)d_in[19]; bv  = (const float*)d_in[20];
        ffb1= (const float*)d_in[21]; ffb2= (const float*)d_in[22];
        ln1g= (const float*)d_in[23]; ln1b= (const float*)d_in[24];
        ln2g= (const float*)d_in[25]; ln2b= (const float*)d_in[26];
        fcW = (const float*)d_in[27]; fcb = (const float*)d_in[28];
    }

    float *p_gW, *p_gb, *p_uW, *p_ub, *p_state, *p_xs, *p_xsmix;
    float *p_hs0, *p_hs1, *p_hv, *p_q, *p_k, *p_v, *p_o, *p_val, *p_ff1, *p_ffo, *p_out2;
    cudaGetSymbolAddress((void**)&p_gW, g_gW);
    cudaGetSymbolAddress((void**)&p_gb, g_gb);
    cudaGetSymbolAddress((void**)&p_uW, g_uW);
    cudaGetSymbolAddress((void**)&p_ub, g_ub);
    cudaGetSymbolAddress((void**)&p_state, g_state);
    cudaGetSymbolAddress((void**)&p_xs, g_xs);
    cudaGetSymbolAddress((void**)&p_xsmix, g_xsmix);
    cudaGetSymbolAddress((void**)&p_hs0, g_hs0);
    cudaGetSymbolAddress((void**)&p_hs1, g_hs1);
    cudaGetSymbolAddress((void**)&p_hv, g_hv);
    cudaGetSymbolAddress((void**)&p_q, g_q);
    cudaGetSymbolAddress((void**)&p_k, g_k);
    cudaGetSymbolAddress((void**)&p_v, g_v);
    cudaGetSymbolAddress((void**)&p_o, g_o);
    cudaGetSymbolAddress((void**)&p_val, g_val);
    cudaGetSymbolAddress((void**)&p_ff1, g_ff1);
    cudaGetSymbolAddress((void**)&p_ffo, g_ffo);
    cudaGetSymbolAddress((void**)&p_out2, g_out2);

    // 1. adjacency
    k_adj<<<NN, 256>>>(emb);

    // 2. layer 0 (Cin=2, C=66)
    k_matpool<<<2048, 256>>>(emb, gwp0, p_gW, 2*66*128);
    k_matpool<<<256,  256>>>(emb, gbp0, p_gb, 128);
    k_matpool<<<2048, 256>>>(emb, uwp0, p_uW, 2*66*64);
    k_matpool<<<128,  256>>>(emb, ubp0, p_ub, 64);
    run_layer_host(src, 2, p_gW, p_gb, p_uW, p_ub, p_state, p_xs, p_xsmix, p_hs0);

    // 3. layer 1 (Cin=64, C=128)
    k_matpool<<<4096, 256>>>(emb, gwp1, p_gW, 2*128*128);
    k_matpool<<<256,  256>>>(emb, gbp1, p_gb, 128);
    k_matpool<<<2048, 256>>>(emb, uwp1, p_uW, 2*128*64);
    k_matpool<<<128,  256>>>(emb, ubp1, p_ub, 64);
    run_layer_host(p_hs0, 64, p_gW, p_gb, p_uW, p_ub, p_state, p_xs, p_xsmix, p_hs1);

    // 4. hypernetwork -> fs, then h (v input)
    k_hyp<<<NN, 192>>>(hypW, hypb);
    k_hv<<<(BTNH + 255)/256, 256>>>();

    // 5. q, k, v projections
    k_gemm64<<<BTN/64, 256>>>(p_hs1, Wq, bq, p_q, 0);
    k_gemm64<<<BTN/64, 256>>>(p_hs1, Wk, bk, p_k, 0);
    k_gemm64<<<BTN/64, 256>>>(p_hv,  Wv, bv, p_v, 0);

    // 6. attention
    k_attn<<<BB*NN, 128>>>();

    // 7. LN1(o + out), FFN, LN2, fc
    k_lnres<<<BTN, 64>>>(p_o, p_hs1, ln1g, ln1b, p_val);
    k_gemm64<<<BTN/64, 256>>>(p_val, ffW1, ffb1, p_ff1, 1);
    k_gemm64<<<BTN/64, 256>>>(p_ff1, ffW2, ffb2, p_ffo, 0);
    k_lnres<<<BTN, 64>>>(p_ffo, p_val, ln2g, ln2b, p_out2);
    k_fc<<<BTN, 64>>>(p_out2, fcW, fcb, (float*)d_out);
}

// round 2
// speedup vs baseline: 1.7824x; 1.7824x over previous
#include <cuda_runtime.h>
#include <math.h>
#include <stdint.h>

#define BB 32
#define TT 12
#define NN 512
#define HH 64
#define EE 16
#define BTN (BB*TT*NN)
#define BTNH (BTN*HH)
#define ZT (BB*TT)          // 384

// ---------------- scratch (device globals; no allocation allowed) ----------------
__device__ float g_adj[NN*NN];
__device__ float g_gW[NN*2*128*128];   // gate weights (max layer-1 size)
__device__ float g_gb[NN*128];
__device__ float g_uW[NN*2*128*64];    // update weights (layer-1 persists for hyp)
__device__ float g_ub[NN*64];
__device__ float g_state[BB*NN*HH];
__device__ float g_mixs[BB*NN*HH];
__device__ float g_zs[BB*NN*HH];
__device__ float g_mixzs[BB*NN*HH];
__device__ float g_r[BB*NN*HH];
__device__ float g_cg[TT*BB*NN*128];   // precomputed gate xt-contrib (+bias)
__device__ float g_cu[TT*BB*NN*64];    // precomputed upd xt-contrib (+bias)
__device__ float g_mxt[ZT*NN*64];      // adj @ xt (column-blocked layout)
__device__ float g_xt0t[TT*NN*64];     // layer0 transposed source (12 z-blocks of [512][64])
__device__ float g_hs0[BTNH];
__device__ float g_hs1[BTNH];
__device__ float g_fs[NN*TT];
__device__ float g_hv[BTNH];
__device__ float g_q[BTNH];
__device__ float g_k[BTNH];
__device__ float g_v[BTNH];
__device__ float g_o[BTNH];
__device__ float g_val[BTNH];
__device__ float g_ff1[BTNH];
__device__ float g_ffo[BTNH];
__device__ float g_out2[BTNH];

// ---------------- helpers ----------------

__device__ __forceinline__ float to_tf32(float x) {
    uint32_t u;
    asm("cvt.rna.tf32.f32 %0, %1;" : "=r"(u) : "f"(x));
    return __uint_as_float(u);
}

__device__ __forceinline__ void mma_tf32(float* c, const uint32_t* a, uint32_t b0, uint32_t b1) {
    asm volatile("mma.sync.aligned.m16n8k8.row.col.f32.tf32.tf32.f32 "
        "{%0,%1,%2,%3}, {%4,%5,%6,%7}, {%8,%9}, {%0,%1,%2,%3};"
        : "+f"(c[0]), "+f"(c[1]), "+f"(c[2]), "+f"(c[3])
        : "r"(a[0]), "r"(a[1]), "r"(a[2]), "r"(a[3]), "r"(b0), "r"(b1));
}

// ---------------- kernels ----------------

__global__ void k_zero(float* __restrict__ p, int n) {
    int i = blockIdx.x * blockDim.x + threadIdx.x;
    int stride = gridDim.x * blockDim.x;
    for (; i < n; i += stride) p[i] = 0.f;
}

// adj = softmax(relu(E E^T), axis=1). One block per row.
__global__ void k_adj(const float* __restrict__ emb) {
    __shared__ float semb[NN*EE];
    __shared__ float row[NN];
    __shared__ float red[256];
    int n = blockIdx.x;
    for (int i = threadIdx.x; i < NN*EE; i += blockDim.x) semb[i] = emb[i];
    __syncthreads();
    float lmax = -1e30f;
    for (int m = threadIdx.x; m < NN; m += blockDim.x) {
        float s = 0.f;
        #pragma unroll
        for (int e = 0; e < EE; ++e) s += semb[n*EE+e] * semb[m*EE+e];
        s = fmaxf(s, 0.f);
        row[m] = s;
        lmax = fmaxf(lmax, s);
    }
    red[threadIdx.x] = lmax; __syncthreads();
    for (int s = 128; s > 0; s >>= 1) {
        if (threadIdx.x < s) red[threadIdx.x] = fmaxf(red[threadIdx.x], red[threadIdx.x+s]);
        __syncthreads();
    }
    float mx = red[0];
    __syncthreads();
    float lsum = 0.f;
    for (int m = threadIdx.x; m < NN; m += blockDim.x) {
        float v = expf(row[m] - mx);
        row[m] = v; lsum += v;
    }
    red[threadIdx.x] = lsum; __syncthreads();
    for (int s = 128; s > 0; s >>= 1) {
        if (threadIdx.x < s) red[threadIdx.x] += red[threadIdx.x+s];
        __syncthreads();
    }
    float inv = 1.f / red[0];
    for (int m = threadIdx.x; m < NN; m += blockDim.x) g_adj[n*NN + m] = row[m] * inv;
}

// out[n*S + i] = sum_e emb[n,e] * pool[e*S + i]
__global__ void k_matpool(const float* __restrict__ emb, const float* __restrict__ pool,
                          float* __restrict__ out, int S) {
    int total = NN * S;
    int stride = gridDim.x * blockDim.x;
    for (int idx = blockIdx.x*blockDim.x + threadIdx.x; idx < total; idx += stride) {
        int n = idx / S, i = idx - n*S;
        float a = 0.f;
        #pragma unroll
        for (int e = 0; e < EE; ++e) a += emb[n*EE+e] * pool[e*S + i];
        out[idx] = a;
    }
}

// layer0 source transpose into column-blocked layout:
// xt0[((g>>6)*512 + m)*64 + (g&63)] = src[(z*512+m)*2 + c],  g = z*2 + c
__global__ void k_transp0(const float* __restrict__ src, float* __restrict__ xt0) {
    int idx = blockIdx.x*blockDim.x + threadIdx.x;
    if (idx >= ZT*NN*2) return;
    int c = idx & 1, m = (idx >> 1) & 511, z = idx >> 10;
    int g = z*2 + c;
    xt0[((size_t)(g>>6)*NN + m)*64 + (g&63)] = src[idx];
}

// Y[z][n][c] = sum_m adj[n][m] * X[z][m][c]   (X,Y: [z][512][64], tf32 tensor cores)
// grid (4, nz), block 128 (4 warps). Each block: 128 rows x 64 cols.
__global__ void __launch_bounds__(128) k_mix_mma(const float* __restrict__ X, float* __restrict__ Y) {
    __shared__ float As[128][36];   // 128 rows x 32 k (pad->36)
    __shared__ float Xs[32][72];    // 32 k x 64 cols (pad->72)
    int z = blockIdx.y;
    int r0 = blockIdx.x * 128;
    int tid = threadIdx.x;
    int warp = tid >> 5, lane = tid & 31;
    const float* Xb = X + (size_t)z * (NN*64);
    float* Yb = Y + (size_t)z * (NN*64);
    float acc[2][8][4];
    #pragma unroll
    for (int mt = 0; mt < 2; ++mt)
        #pragma unroll
        for (int j = 0; j < 8; ++j)
            #pragma unroll
            for (int q = 0; q < 4; ++q) acc[mt][j][q] = 0.f;

    for (int kc = 0; kc < NN; kc += 32) {
        // load A chunk: 128x32 = 1024 float4 / 128 thr = 8 each
        #pragma unroll
        for (int i = 0; i < 8; ++i) {
            int idx = tid + i*128;
            int row = idx >> 3;
            int c4 = (idx & 7) * 4;
            float4 v = *reinterpret_cast<const float4*>(&g_adj[(size_t)(r0+row)*NN + kc + c4]);
            float4 w;
            w.x = to_tf32(v.x); w.y = to_tf32(v.y); w.z = to_tf32(v.z); w.w = to_tf32(v.w);
            *reinterpret_cast<float4*>(&As[row][c4]) = w;
        }
        // load X chunk: 32x64 = 512 float4 / 128 thr = 4 each
        #pragma unroll
        for (int i = 0; i < 4; ++i) {
            int idx = tid + i*128;
            int row = idx >> 4;
            int c4 = (idx & 15) * 4;
            float4 v = *reinterpret_cast<const float4*>(&Xb[(size_t)(kc+row)*64 + c4]);
            float4 w;
            w.x = to_tf32(v.x); w.y = to_tf32(v.y); w.z = to_tf32(v.z); w.w = to_tf32(v.w);
            *reinterpret_cast<float4*>(&Xs[row][c4]) = w;
        }
        __syncthreads();
        #pragma unroll
        for (int k8 = 0; k8 < 32; k8 += 8) {
            uint32_t a[2][4];
            int ar = warp*32 + (lane>>2);
            int ac = k8 + (lane&3);
            #pragma unroll
            for (int mt = 0; mt < 2; ++mt) {
                int rr = ar + mt*16;
                a[mt][0] = __float_as_uint(As[rr][ac]);
                a[mt][1] = __float_as_uint(As[rr+8][ac]);
                a[mt][2] = __float_as_uint(As[rr][ac+4]);
                a[mt][3] = __float_as_uint(As[rr+8][ac+4]);
            }
            #pragma unroll
            for (int j = 0; j < 8; ++j) {
                uint32_t b0 = __float_as_uint(Xs[k8 + (lane&3)][j*8 + (lane>>2)]);
                uint32_t b1 = __float_as_uint(Xs[k8 + (lane&3) + 4][j*8 + (lane>>2)]);
                mma_tf32(acc[0][j], a[0], b0, b1);
                mma_tf32(acc[1][j], a[1], b0, b1);
            }
        }
        __syncthreads();
    }
    #pragma unroll
    for (int mt = 0; mt < 2; ++mt) {
        int row = r0 + warp*32 + mt*16 + (lane>>2);
        #pragma unroll
        for (int j = 0; j < 8; ++j) {
            int col = j*8 + (lane&3)*2;
            Yb[(size_t)row*64 + col]       = acc[mt][j][0];
            Yb[(size_t)row*64 + col + 1]   = acc[mt][j][1];
            Yb[(size_t)(row+8)*64 + col]   = acc[mt][j][2];
            Yb[(size_t)(row+8)*64 + col+1] = acc[mt][j][3];
        }
    }
}

// Precompute xt contributions (+bias) for gate (128 out) and upd (64 out).
// grid (512 nodes, 6 row-chunks of 64), block 192. Rows are z = b*12+t over 384.
__global__ void __launch_bounds__(192) k_precomp(
        const float* __restrict__ xt, const float* __restrict__ mxt,
        const float* __restrict__ gW, const float* __restrict__ uW,
        const float* __restrict__ gb, const float* __restrict__ ub,
        float* __restrict__ cg, float* __restrict__ cu, int Cin) {
    const int C = Cin + HH;
    __shared__ float xs[64][64];
    __shared__ float ms[64][64];
    int n = blockIdx.x;
    int r0 = blockIdx.y * 64;
    int tid = threadIdx.x;
    for (int idx = tid; idx < 64*Cin; idx += 192) {
        int r = idx / Cin, c = idx - r*Cin;
        int z = r0 + r;
        xs[r][c] = xt[((size_t)z*NN + n)*Cin + c];
        int g = z*Cin + c;
        ms[r][c] = mxt[((size_t)(g>>6)*NN + n)*64 + (g&63)];
    }
    __syncthreads();
    float a[64];
    #pragma unroll
    for (int i = 0; i < 64; ++i) a[i] = 0.f;
    if (tid < 128) {
        int o = tid;
        const float* W0 = gW + (size_t)(n*2)*C*128 + o;
        const float* W1 = gW + (size_t)(n*2+1)*C*128 + o;
        if ((Cin & 3) == 0) {
            for (int c = 0; c < Cin; c += 4) {
                float w00=W0[c*128], w01=W0[(c+1)*128], w02=W0[(c+2)*128], w03=W0[(c+3)*128];
                float w10=W1[c*128], w11=W1[(c+1)*128], w12=W1[(c+2)*128], w13=W1[(c+3)*128];
                #pragma unroll
                for (int r = 0; r < 64; ++r) {
                    float4 x = *reinterpret_cast<const float4*>(&xs[r][c]);
                    float4 y = *reinterpret_cast<const float4*>(&ms[r][c]);
                    a[r] += x.x*w00 + x.y*w01 + x.z*w02 + x.w*w03
                          + y.x*w10 + y.y*w11 + y.z*w12 + y.w*w13;
                }
            }
        } else {
            for (int c = 0; c < Cin; ++c) {
                float w0 = W0[c*128], w1 = W1[c*128];
                #pragma unroll
                for (int r = 0; r < 64; ++r) a[r] += xs[r][c]*w0 + ms[r][c]*w1;
            }
        }
        float bias = gb[n*128 + o];
        for (int r = 0; r < 64; ++r) {
            int z = r0 + r; int b = z / 12, t = z - b*12;
            cg[(((size_t)t*BB + b)*NN + n)*128 + o] = a[r] + bias;
        }
    } else {
        int o = tid - 128;
        const float* W0 = uW + (size_t)(n*2)*C*64 + o;
        const float* W1 = uW + (size_t)(n*2+1)*C*64 + o;
        if ((Cin & 3) == 0) {
            for (int c = 0; c < Cin; c += 4) {
                float w00=W0[c*64], w01=W0[(c+1)*64], w02=W0[(c+2)*64], w03=W0[(c+3)*64];
                float w10=W1[c*64], w11=W1[(c+1)*64], w12=W1[(c+2)*64], w13=W1[(c+3)*64];
                #pragma unroll
                for (int r = 0; r < 64; ++r) {
                    float4 x = *reinterpret_cast<const float4*>(&xs[r][c]);
                    float4 y = *reinterpret_cast<const float4*>(&ms[r][c]);
                    a[r] += x.x*w00 + x.y*w01 + x.z*w02 + x.w*w03
                          + y.x*w10 + y.y*w11 + y.z*w12 + y.w*w13;
                }
            }
        } else {
            for (int c = 0; c < Cin; ++c) {
                float w0 = W0[c*64], w1 = W1[c*64];
                #pragma unroll
                for (int r = 0; r < 64; ++r) a[r] += xs[r][c]*w0 + ms[r][c]*w1;
            }
        }
        float bias = ub[n*64 + o];
        for (int r = 0; r < 64; ++r) {
            int z = r0 + r; int b = z / 12, t = z - b*12;
            cu[(((size_t)t*BB + b)*NN + n)*64 + o] = a[r] + bias;
        }
    }
}

// Per-step gate: acc = cg_t + W_state0^T state + W_state1^T (adj@state); sigmoid;
// writes zs = z*state (o<64) and r (o>=64). One block per node, 128 threads.
__global__ void __launch_bounds__(128) k_gate2(
        const float* __restrict__ state, const float* __restrict__ mixs,
        const float* __restrict__ gW, const float* __restrict__ cg_t, int C, int Cin) {
    __shared__ float s0[32][64];
    __shared__ float s1[32][64];
    int n = blockIdx.x;
    int o = threadIdx.x;
    for (int idx = o; idx < 2048; idx += 128) {
        int b = idx >> 6, c = idx & 63;
        s0[b][c] = state[((size_t)b*NN + n)*64 + c];
        s1[b][c] = mixs[((size_t)b*NN + n)*64 + c];
    }
    __syncthreads();
    float acc[32];
    #pragma unroll
    for (int b = 0; b < 32; ++b) acc[b] = cg_t[((size_t)b*NN + n)*128 + o];
    const float* W0 = gW + ((size_t)(n*2)*C + Cin)*128 + o;
    const float* W1 = gW + ((size_t)(n*2+1)*C + Cin)*128 + o;
    for (int c = 0; c < 64; c += 4) {
        float w00=W0[c*128], w01=W0[(c+1)*128], w02=W0[(c+2)*128], w03=W0[(c+3)*128];
        float w10=W1[c*128], w11=W1[(c+1)*128], w12=W1[(c+2)*128], w13=W1[(c+3)*128];
        #pragma unroll
        for (int b = 0; b < 32; ++b) {
            float4 x = *reinterpret_cast<const float4*>(&s0[b][c]);
            float4 y = *reinterpret_cast<const float4*>(&s1[b][c]);
            acc[b] += x.x*w00 + x.y*w01 + x.z*w02 + x.w*w03
                    + y.x*w10 + y.y*w11 + y.z*w12 + y.w*w13;
        }
    }
    if (o < 64) {
        #pragma unroll
        for (int b = 0; b < 32; ++b) {
            float z = 1.f / (1.f + expf(-acc[b]));
            g_zs[((size_t)b*NN + n)*64 + o] = z * s0[b][o];
        }
    } else {
        int oo = o - 64;
        #pragma unroll
        for (int b = 0; b < 32; ++b) {
            g_r[((size_t)b*NN + n)*64 + oo] = 1.f / (1.f + expf(-acc[b]));
        }
    }
}

// Per-step update: hc = tanh(cu_t + W0^T zs + W1^T (adj@zs)); h = r*state + (1-r)*hc.
__global__ void __launch_bounds__(128) k_upd2(
        const float* __restrict__ zs, const float* __restrict__ mixzs,
        const float* __restrict__ uW, const float* __restrict__ cu_t,
        int C, int Cin, float* __restrict__ hs, int t) {
    __shared__ float s0[32][64];
    __shared__ float s1[32][64];
    int n = blockIdx.x;
    int tid = threadIdx.x;
    int o = tid & 63, half = tid >> 6, b0 = half * 16;
    for (int idx = tid; idx < 2048; idx += 128) {
        int b = idx >> 6, c = idx & 63;
        s0[b][c] = zs[((size_t)b*NN + n)*64 + c];
        s1[b][c] = mixzs[((size_t)b*NN + n)*64 + c];
    }
    __syncthreads();
    float acc[16];
    #pragma unroll
    for (int i = 0; i < 16; ++i) acc[i] = cu_t[((size_t)(b0+i)*NN + n)*64 + o];
    const float* W0 = uW + ((size_t)(n*2)*C + Cin)*64 + o;
    const float* W1 = uW + ((size_t)(n*2+1)*C + Cin)*64 + o;
    for (int c = 0; c < 64; c += 4) {
        float w00=W0[c*64], w01=W0[(c+1)*64], w02=W0[(c+2)*64], w03=W0[(c+3)*64];
        float w10=W1[c*64], w11=W1[(c+1)*64], w12=W1[(c+2)*64], w13=W1[(c+3)*64];
        #pragma unroll
        for (int i = 0; i < 16; ++i) {
            float4 x = *reinterpret_cast<const float4*>(&s0[b0+i][c]);
            float4 y = *reinterpret_cast<const float4*>(&s1[b0+i][c]);
            acc[i] += x.x*w00 + x.y*w01 + x.z*w02 + x.w*w03
                    + y.x*w10 + y.y*w11 + y.z*w12 + y.w*w13;
        }
    }
    #pragma unroll
    for (int i = 0; i < 16; ++i) {
        int b = b0 + i;
        size_t idx = ((size_t)b*NN + n)*64 + o;
        float rr = g_r[idx];
        float st = g_state[idx];
        float hc = tanhf(acc[i]);
        float h = rr*st + (1.f - rr)*hc;
        g_state[idx] = h;
        hs[(((size_t)b*TT + t)*NN + n)*64 + o] = h;
    }
}

// hlin = uW_flat @ hypW + hypb ; fs = group-sum of 4
__global__ void k_hyp(const float* __restrict__ hypW, const float* __restrict__ hypb) {
    __shared__ float part[192];
    __shared__ float hlin[48];
    int n = blockIdx.x;
    int tid = threadIdx.x;  // 192
    int j = tid % 48, sl = tid / 48;
    const float* u = g_uW + (size_t)n * 16384;
    float a = 0.f;
    int i0 = sl * 4096;
    for (int i = i0; i < i0 + 4096; ++i) a += u[i] * hypW[i*48 + j];
    part[tid] = a;
    __syncthreads();
    if (tid < 48) hlin[tid] = part[tid] + part[48+tid] + part[96+tid] + part[144+tid] + hypb[tid];
    __syncthreads();
    if (tid < 12) {
        g_fs[n*TT + tid] = hlin[tid*4] + hlin[tid*4+1] + hlin[tid*4+2] + hlin[tid*4+3];
    }
}

// hv[b,t,n,c] = hs1[b,T-1,n,c] * fs[n,t]
__global__ void k_hv() {
    int idx = blockIdx.x*blockDim.x + threadIdx.x;
    if (idx >= BTNH) return;
    int c = idx & 63;
    int bt_n = idx >> 6;
    int n = bt_n % NN;
    int bt = bt_n / NN;
    int t = bt % TT, b = bt / TT;
    g_hv[idx] = g_hs1[(((size_t)b*TT + (TT-1))*NN + n)*HH + c] * g_fs[n*TT + t];
}

// Y[M,64] = act(X[M,64] @ W[64,64] + bias)
__global__ void k_gemm64(const float* __restrict__ X, const float* __restrict__ W,
                         const float* __restrict__ bias, float* __restrict__ Y, int relu) {
    __shared__ float Xs[64][65];
    __shared__ float Ws[64][65];
    int row0 = blockIdx.x * 64;
    int tid = threadIdx.x;
    int tx = tid & 15, ty = tid >> 4;
    #pragma unroll
    for (int r = 0; r < 16; ++r) {
        int idx = tid + r*256;
        int i = idx >> 6, k = idx & 63;
        Xs[i][k] = X[(size_t)(row0 + i)*64 + k];
        Ws[i][k] = W[idx];
    }
    __syncthreads();
    float acc[4][4] = {};
    int i0 = ty*4, j0 = tx*4;
    #pragma unroll 16
    for (int kk = 0; kk < 64; ++kk) {
        float a[4], w[4];
        #pragma unroll
        for (int r = 0; r < 4; ++r) a[r] = Xs[i0+r][kk];
        #pragma unroll
        for (int c = 0; c < 4; ++c) w[c] = Ws[kk][j0+c];
        #pragma unroll
        for (int r = 0; r < 4; ++r)
            #pragma unroll
            for (int c = 0; c < 4; ++c)
                acc[r][c] = fmaf(a[r], w[c], acc[r][c]);
    }
    #pragma unroll
    for (int r = 0; r < 4; ++r)
        #pragma unroll
        for (int c = 0; c < 4; ++c) {
            float v = acc[r][c] + bias[j0+c];
            if (relu) v = fmaxf(v, 0.f);
            Y[(size_t)(row0 + i0 + r)*64 + j0 + c] = v;
        }
}

// attention per (b,n): T=12, heads=2, d=32
__global__ void k_attn() {
    __shared__ float qs[12][64], ks[12][64], vs[12][64];
    __shared__ float sc[2][12][12];
    int bn = blockIdx.x;
    int b = bn / NN, n = bn - b*NN;
    int tid = threadIdx.x;  // 128
    for (int idx = tid; idx < 12*64; idx += 128) {
        int t = idx >> 6, c = idx & 63;
        size_t g = (((size_t)b*TT + t)*NN + n)*HH + c;
        qs[t][c] = g_q[g];
        ks[t][c] = g_k[g];
        vs[t][c] = g_v[g];
    }
    __syncthreads();
    for (int idx = tid; idx < 288; idx += 128) {
        int h = idx / 144, rem = idx - h*144;
        int t = rem / 12, s = rem - t*12;
        float d = 0.f;
        #pragma unroll
        for (int k = 0; k < 32; ++k) d += qs[t][h*32 + k] * ks[s][h*32 + k];
        sc[h][t][s] = d * 0.17677669529663687f;
    }
    __syncthreads();
    if (tid < 24) {
        int h = tid / 12, t = tid - h*12;
        float mx = -1e30f;
        #pragma unroll
        for (int s = 0; s < 12; ++s) mx = fmaxf(mx, sc[h][t][s]);
        float sum = 0.f;
        #pragma unroll
        for (int s = 0; s < 12; ++s) { float e = expf(sc[h][t][s] - mx); sc[h][t][s] = e; sum += e; }
        float inv = 1.f / sum;
        #pragma unroll
        for (int s = 0; s < 12; ++s) sc[h][t][s] *= inv;
    }
    __syncthreads();
    for (int idx = tid; idx < 768; idx += 128) {
        int h = idx / 384, rem = idx - h*384;
        int t = rem >> 5, d = rem & 31;
        float a = 0.f;
        #pragma unroll
        for (int s = 0; s < 12; ++s) a += sc[h][t][s] * vs[s][h*32 + d];
        g_o[(((size_t)b*TT + t)*NN + n)*HH + h*32 + d] = a;
    }
}

// Y = LN(A + Bv) * g + beta (row length 64)
__global__ void k_lnres(const float* __restrict__ A, const float* __restrict__ Bv,
                        const float* __restrict__ g, const float* __restrict__ be,
                        float* __restrict__ Y) {
    __shared__ float red[64];
    size_t row = blockIdx.x;
    int c = threadIdx.x;
    float x = A[row*64 + c] + Bv[row*64 + c];
    red[c] = x; __syncthreads();
    for (int s = 32; s > 0; s >>= 1) { if (c < s) red[c] += red[c+s]; __syncthreads(); }
    float mu = red[0] * (1.f/64.f);
    __syncthreads();
    float d = x - mu;
    red[c] = d*d; __syncthreads();
    for (int s = 32; s > 0; s >>= 1) { if (c < s) red[c] += red[c+s]; __syncthreads(); }
    float var = red[0] * (1.f/64.f);
    Y[row*64 + c] = d * rsqrtf(var + 1e-5f) * g[c] + be[c];
}

// y[row] = dot(X[row,:], fcW) + fcb
__global__ void k_fc(const float* __restrict__ X, const float* __restrict__ w,
                     const float* __restrict__ bp, float* __restrict__ Y) {
    __shared__ float red[64];
    size_t row = blockIdx.x;
    int c = threadIdx.x;
    red[c] = X[row*64 + c] * w[c];
    __syncthreads();
    for (int s = 32; s > 0; s >>= 1) { if (c < s) red[c] += red[c+s]; __syncthreads(); }
    if (c == 0) Y[row] = red[0] + bp[0];
}

// ---------------- host ----------------

extern "C" void kernel_launch(void* const* d_in, const int* in_sizes, int n_in,
                              void* d_out, int out_size) {
    const float* src  = (const float*)d_in[0];
    const float* emb  = (const float*)d_in[2];
    const float* gwp0 = (const float*)d_in[3];
    const float* gbp0 = (const float*)d_in[4];
    const float* uwp0 = (const float*)d_in[5];
    const float* ubp0 = (const float*)d_in[6];
    const float* gwp1 = (const float*)d_in[7];
    const float* gbp1 = (const float*)d_in[8];
    const float* uwp1 = (const float*)d_in[9];
    const float* ubp1 = (const float*)d_in[10];
    const float* hypW = (const float*)d_in[11];
    const float* hypb = (const float*)d_in[12];

    const float *Wq,*Wk,*Wv,*ffW1,*ffW2,*bq,*bk,*bv,*ffb1,*ffb2,*ln1g,*ln1b,*ln2g,*ln2b,*fcW,*fcb;
    if (n_in > 14 && in_sizes[14] == 64) {
        Wq  = (const float*)d_in[13]; bq  = (const float*)d_in[14];
        Wk  = (const float*)d_in[15]; bk  = (const float*)d_in[16];
        Wv  = (const float*)d_in[17]; bv  = (const float*)d_in[18];
        ln1g= (const float*)d_in[19]; ln1b= (const float*)d_in[20];
        ffW1= (const float*)d_in[21]; ffb1= (const float*)d_in[22];
        ffW2= (const float*)d_in[23]; ffb2= (const float*)d_in[24];
        ln2g= (const float*)d_in[25]; ln2b= (const float*)d_in[26];
        fcW = (const float*)d_in[27]; fcb = (const float*)d_in[28];
    } else {
        Wq  = (const float*)d_in[13]; Wk  = (const float*)d_in[14];
        Wv  = (const float*)d_in[15]; ffW1= (const float*)d_in[16];
        ffW2= (const float*)d_in[17]; bq  = (const float*)d_in[18];
        bk  = (const float*)d_in[19]; bv  = (const float*)d_in[20];
        ffb1= (const float*)d_in[21]; ffb2= (const float*)d_in[22];
        ln1g= (const float*)d_in[23]; ln1b= (const float*)d_in[24];
        ln2g= (const float*)d_in[25]; ln2b= (const float*)d_in[26];
        fcW = (const float*)d_in[27]; fcb = (const float*)d_in[28];
    }

    float *p_gW,*p_gb,*p_uW,*p_ub,*p_state,*p_mixs,*p_zs,*p_mixzs,*p_cg,*p_cu,*p_mxt,*p_xt0t;
    float *p_hs0,*p_hs1,*p_hv,*p_q,*p_k,*p_v,*p_o,*p_val,*p_ff1,*p_ffo,*p_out2;
    cudaGetSymbolAddress((void**)&p_gW, g_gW);
    cudaGetSymbolAddress((void**)&p_gb, g_gb);
    cudaGetSymbolAddress((void**)&p_uW, g_uW);
    cudaGetSymbolAddress((void**)&p_ub, g_ub);
    cudaGetSymbolAddress((void**)&p_state, g_state);
    cudaGetSymbolAddress((void**)&p_mixs, g_mixs);
    cudaGetSymbolAddress((void**)&p_zs, g_zs);
    cudaGetSymbolAddress((void**)&p_mixzs, g_mixzs);
    cudaGetSymbolAddress((void**)&p_cg, g_cg);
    cudaGetSymbolAddress((void**)&p_cu, g_cu);
    cudaGetSymbolAddress((void**)&p_mxt, g_mxt);
    cudaGetSymbolAddress((void**)&p_xt0t, g_xt0t);
    cudaGetSymbolAddress((void**)&p_hs0, g_hs0);
    cudaGetSymbolAddress((void**)&p_hs1, g_hs1);
    cudaGetSymbolAddress((void**)&p_hv, g_hv);
    cudaGetSymbolAddress((void**)&p_q, g_q);
    cudaGetSymbolAddress((void**)&p_k, g_k);
    cudaGetSymbolAddress((void**)&p_v, g_v);
    cudaGetSymbolAddress((void**)&p_o, g_o);
    cudaGetSymbolAddress((void**)&p_val, g_val);
    cudaGetSymbolAddress((void**)&p_ff1, g_ff1);
    cudaGetSymbolAddress((void**)&p_ffo, g_ffo);
    cudaGetSymbolAddress((void**)&p_out2, g_out2);

    // 1. adjacency
    k_adj<<<NN, 256>>>(emb);

    for (int layer = 0; layer < 2; ++layer) {
        int Cin = (layer == 0) ? 2 : 64;
        int C = Cin + HH;
        const float* xt;
        float* hs_out;
        if (layer == 0) {
            k_matpool<<<2048, 256>>>(emb, gwp0, p_gW, 2*C*128);
            k_matpool<<<256,  256>>>(emb, gbp0, p_gb, 128);
            k_matpool<<<2048, 256>>>(emb, uwp0, p_uW, 2*C*64);
            k_matpool<<<128,  256>>>(emb, ubp0, p_ub, 64);
            // transpose src into 12 column-blocks, then mix them
            k_transp0<<<(ZT*NN*2 + 255)/256, 256>>>(src, p_xt0t);
            k_mix_mma<<<dim3(4, (ZT*2)/64), 128>>>(p_xt0t, p_mxt);
            xt = src; hs_out = p_hs0;
        } else {
            k_matpool<<<4096, 256>>>(emb, gwp1, p_gW, 2*C*128);
            k_matpool<<<256,  256>>>(emb, gbp1, p_gb, 128);
            k_matpool<<<2048, 256>>>(emb, uwp1, p_uW, 2*C*64);
            k_matpool<<<128,  256>>>(emb, ubp1, p_ub, 64);
            // hs0 is already [z][512][64]; mix all 384 z-batches
            k_mix_mma<<<dim3(4, ZT), 128>>>(p_hs0, p_mxt);
            xt = p_hs0; hs_out = p_hs1;
        }
        // precompute xt-contributions (+bias)
        k_precomp<<<dim3(NN, 6), 192>>>(xt, p_mxt, p_gW, p_uW, p_gb, p_ub, p_cg, p_cu, Cin);
        // recurrence
        k_zero<<<1024, 256>>>(p_state, BB*NN*HH);
        for (int t = 0; t < TT; ++t) {
            const float* cg_t = p_cg + (size_t)t*BB*NN*128;
            const float* cu_t = p_cu + (size_t)t*BB*NN*64;
            k_mix_mma<<<dim3(4, BB), 128>>>(p_state, p_mixs);
            k_gate2<<<NN, 128>>>(p_state, p_mixs, p_gW, cg_t, C, Cin);
            k_mix_mma<<<dim3(4, BB), 128>>>(p_zs, p_mixzs);
            k_upd2<<<NN, 128>>>(p_zs, p_mixzs, p_uW, cu_t, C, Cin, hs_out, t);
        }
    }

    // hypernetwork -> fs, then h (v input)
    k_hyp<<<NN, 192>>>(hypW, hypb);
    k_hv<<<(BTNH + 255)/256, 256>>>();

    // q, k, v projections
    k_gemm64<<<BTN/64, 256>>>(p_hs1, Wq, bq, p_q, 0);
    k_gemm64<<<BTN/64, 256>>>(p_hs1, Wk, bk, p_k, 0);
    k_gemm64<<<BTN/64, 256>>>(p_hv,  Wv, bv, p_v, 0);

    // attention
    k_attn<<<BB*NN, 128>>>();

    // LN1(o + out), FFN, LN2, fc
    k_lnres<<<BTN, 64>>>(p_o, p_hs1, ln1g, ln1b, p_val);
    k_gemm64<<<BTN/64, 256>>>(p_val, ffW1, ffb1, p_ff1, 1);
    k_gemm64<<<BTN/64, 256>>>(p_ff1, ffW2, ffb2, p_ffo, 0);
    k_lnres<<<BTN, 64>>>(p_ffo, p_val, ln2g, ln2b, p_out2);
    k_fc<<<BTN, 64>>>(p_out2, fcW, fcb, (float*)d_out);
}

// round 3
// speedup vs baseline: 2.7419x; 1.5383x over previous
#include <cuda_runtime.h>
#include <math.h>
#include <stdint.h>

#define BB 32
#define TT 12
#define NN 512
#define HH 64
#define EE 16
#define BTN (BB*TT*NN)
#define BTNH (BTN*HH)
#define ZT (BB*TT)          // 384

// ---------------- scratch (device globals) ----------------
__device__ float g_adj[NN*NN];
__device__ float g_gW[NN*2*128*128];
__device__ float g_gb[NN*128];
__device__ float g_uW[NN*2*128*64];
__device__ float g_ub[NN*64];
__device__ float g_state[BB*NN*HH];
__device__ float g_mixs[BB*NN*HH];
__device__ float g_zs[BB*NN*HH];
__device__ float g_mixzs[BB*NN*HH];
__device__ float g_r[BB*NN*HH];
__device__ float g_cg[TT*BB*NN*128];
__device__ float g_cu[TT*BB*NN*64];
__device__ float g_mxt[ZT*NN*64];
__device__ float g_xt0t[TT*NN*64];
__device__ float g_hs0[BTNH];
__device__ float g_hs1[BTNH];
__device__ float g_fs[NN*TT];
__device__ float g_hv[BB*NN*HH];      // last hidden state (compact)
__device__ float g_q[BTNH];
__device__ float g_k[BTNH];
__device__ float g_v[BB*NN*HH];       // vb = hs1_last @ Wv
__device__ float g_o[BTNH];
__device__ float g_val[BTNH];
__device__ float g_ff1[BTNH];
__device__ float g_ffo[BTNH];
__device__ float g_out2[BTNH];

// ---------------- helpers ----------------

__device__ __forceinline__ float to_tf32(float x) {
    uint32_t u;
    asm("cvt.rna.tf32.f32 %0, %1;" : "=r"(u) : "f"(x));
    return __uint_as_float(u);
}
__device__ __forceinline__ uint32_t cvu(float x) {
    uint32_t u;
    asm("cvt.rna.tf32.f32 %0, %1;" : "=r"(u) : "f"(x));
    return u;
}

__device__ __forceinline__ void mma_tf32(float* c, const uint32_t* a, uint32_t b0, uint32_t b1) {
    asm volatile("mma.sync.aligned.m16n8k8.row.col.f32.tf32.tf32.f32 "
        "{%0,%1,%2,%3}, {%4,%5,%6,%7}, {%8,%9}, {%0,%1,%2,%3};"
        : "+f"(c[0]), "+f"(c[1]), "+f"(c[2]), "+f"(c[3])
        : "r"(a[0]), "r"(a[1]), "r"(a[2]), "r"(a[3]), "r"(b0), "r"(b1));
}

__device__ __forceinline__ float sigm(float v) { return 1.f / (1.f + __expf(-v)); }
__device__ __forceinline__ float tanhfast(float v) { return 1.f - 2.f / (__expf(2.f*v) + 1.f); }

// ---------------- kernels ----------------

__global__ void k_zero(float* __restrict__ p, int n) {
    int i = blockIdx.x * blockDim.x + threadIdx.x;
    int stride = gridDim.x * blockDim.x;
    for (; i < n; i += stride) p[i] = 0.f;
}

__global__ void k_adj(const float* __restrict__ emb) {
    __shared__ float semb[NN*EE];
    __shared__ float row[NN];
    __shared__ float red[256];
    int n = blockIdx.x;
    for (int i = threadIdx.x; i < NN*EE; i += blockDim.x) semb[i] = emb[i];
    __syncthreads();
    float lmax = -1e30f;
    for (int m = threadIdx.x; m < NN; m += blockDim.x) {
        float s = 0.f;
        #pragma unroll
        for (int e = 0; e < EE; ++e) s += semb[n*EE+e] * semb[m*EE+e];
        s = fmaxf(s, 0.f);
        row[m] = s;
        lmax = fmaxf(lmax, s);
    }
    red[threadIdx.x] = lmax; __syncthreads();
    for (int s = 128; s > 0; s >>= 1) {
        if (threadIdx.x < s) red[threadIdx.x] = fmaxf(red[threadIdx.x], red[threadIdx.x+s]);
        __syncthreads();
    }
    float mx = red[0];
    __syncthreads();
    float lsum = 0.f;
    for (int m = threadIdx.x; m < NN; m += blockDim.x) {
        float v = expf(row[m] - mx);
        row[m] = v; lsum += v;
    }
    red[threadIdx.x] = lsum; __syncthreads();
    for (int s = 128; s > 0; s >>= 1) {
        if (threadIdx.x < s) red[threadIdx.x] += red[threadIdx.x+s];
        __syncthreads();
    }
    float inv = 1.f / red[0];
    for (int m = threadIdx.x; m < NN; m += blockDim.x) g_adj[n*NN + m] = row[m] * inv;
}

// float4 matpool: out[n][i4] = sum_e emb[n,e]*pool[e][i4]
__global__ void k_matpool4(const float* __restrict__ emb, const float* __restrict__ pool,
                           float* __restrict__ out, int S4) {
    int idx = blockIdx.x*blockDim.x + threadIdx.x;
    if (idx >= NN * S4) return;
    int n = idx / S4, i = idx - n*S4;
    float4 a = make_float4(0.f,0.f,0.f,0.f);
    const float* e = emb + n*EE;
    const float4* p4 = (const float4*)pool;
    #pragma unroll
    for (int k = 0; k < EE; ++k) {
        float w = e[k];
        float4 p = p4[(size_t)k*S4 + i];
        a.x += w*p.x; a.y += w*p.y; a.z += w*p.z; a.w += w*p.w;
    }
    ((float4*)out)[idx] = a;
}

__global__ void k_transp0(const float* __restrict__ src, float* __restrict__ xt0) {
    int idx = blockIdx.x*blockDim.x + threadIdx.x;
    if (idx >= ZT*NN*2) return;
    int c = idx & 1, m = (idx >> 1) & 511, z = idx >> 10;
    int g = z*2 + c;
    xt0[((size_t)(g>>6)*NN + m)*64 + (g&63)] = src[idx];
}

// Y[z][n][c] = sum_m adj[n][m] X[z][m][c], 64-row tiles. grid (8, nz), block 128.
__global__ void __launch_bounds__(128) k_mix64(const float* __restrict__ X, float* __restrict__ Y) {
    __shared__ float As[64][36];
    __shared__ float Xs[32][72];
    int z = blockIdx.y;
    int r0 = blockIdx.x * 64;
    int tid = threadIdx.x;
    int warp = tid >> 5, lane = tid & 31;
    const float* Xb = X + (size_t)z * (NN*64);
    float* Yb = Y + (size_t)z * (NN*64);
    float acc[8][4];
    #pragma unroll
    for (int j = 0; j < 8; ++j)
        #pragma unroll
        for (int q = 0; q < 4; ++q) acc[j][q] = 0.f;

    for (int kc = 0; kc < NN; kc += 32) {
        #pragma unroll
        for (int i = 0; i < 4; ++i) {
            int idx = tid + i*128;
            int row = idx >> 3;
            int c4 = (idx & 7) * 4;
            float4 v = *reinterpret_cast<const float4*>(&g_adj[(size_t)(r0+row)*NN + kc + c4]);
            float4 w; w.x=to_tf32(v.x); w.y=to_tf32(v.y); w.z=to_tf32(v.z); w.w=to_tf32(v.w);
            *reinterpret_cast<float4*>(&As[row][c4]) = w;
        }
        #pragma unroll
        for (int i = 0; i < 4; ++i) {
            int idx = tid + i*128;
            int row = idx >> 4;
            int c4 = (idx & 15) * 4;
            float4 v = *reinterpret_cast<const float4*>(&Xb[(size_t)(kc+row)*64 + c4]);
            float4 w; w.x=to_tf32(v.x); w.y=to_tf32(v.y); w.z=to_tf32(v.z); w.w=to_tf32(v.w);
            *reinterpret_cast<float4*>(&Xs[row][c4]) = w;
        }
        __syncthreads();
        #pragma unroll
        for (int k8 = 0; k8 < 32; k8 += 8) {
            uint32_t a[4];
            int ar = warp*16 + (lane>>2);
            int ac = k8 + (lane&3);
            a[0] = __float_as_uint(As[ar][ac]);
            a[1] = __float_as_uint(As[ar+8][ac]);
            a[2] = __float_as_uint(As[ar][ac+4]);
            a[3] = __float_as_uint(As[ar+8][ac+4]);
            #pragma unroll
            for (int j = 0; j < 8; ++j) {
                uint32_t b0 = __float_as_uint(Xs[k8 + (lane&3)][j*8 + (lane>>2)]);
                uint32_t b1 = __float_as_uint(Xs[k8 + (lane&3) + 4][j*8 + (lane>>2)]);
                mma_tf32(acc[j], a, b0, b1);
            }
        }
        __syncthreads();
    }
    int row = r0 + warp*16 + (lane>>2);
    #pragma unroll
    for (int j = 0; j < 8; ++j) {
        int col = j*8 + (lane&3)*2;
        *reinterpret_cast<float2*>(&Yb[(size_t)row*64 + col]) = make_float2(acc[j][0], acc[j][1]);
        *reinterpret_cast<float2*>(&Yb[(size_t)(row+8)*64 + col]) = make_float2(acc[j][2], acc[j][3]);
    }
}

// Gate via tf32 MMA. Block = 1 node, 128 thr (4 warps). A=[state|mixs] 32x128 fp32 smem,
// B = gate weights (state rows), N=128. Epilogue: +cg_t, sigmoid, zs/r.
__global__ void __launch_bounds__(128) k_gate_mma(
        const float* __restrict__ state, const float* __restrict__ mixs,
        const float* __restrict__ gW, const float* __restrict__ cg_t, int C, int Cin) {
    __shared__ float As[32][132];
    __shared__ float Bs[32][136];
    int n = blockIdx.x;
    int tid = threadIdx.x;
    int warp = tid >> 5, lane = tid & 31;
    // A load: 32x128 floats = 1024 float4, 8 per thread
    #pragma unroll
    for (int i = 0; i < 8; ++i) {
        int idx = tid + i*128;
        int row = idx >> 5;
        int c4 = (idx & 31) * 4;
        float4 v = (c4 < 64)
            ? *reinterpret_cast<const float4*>(&state[((size_t)row*NN + n)*64 + c4])
            : *reinterpret_cast<const float4*>(&mixs[((size_t)row*NN + n)*64 + c4 - 64]);
        *reinterpret_cast<float4*>(&As[row][c4]) = v;
    }
    float acc[2][4][4];
    #pragma unroll
    for (int mt=0; mt<2; ++mt) for (int j=0;j<4;++j) for (int q=0;q<4;++q) acc[mt][j][q]=0.f;

    for (int kc = 0; kc < 128; kc += 32) {
        #pragma unroll
        for (int i = 0; i < 8; ++i) {
            int idx = tid + i*128;
            int krow = idx >> 5;
            int c4 = (idx & 31) * 4;
            int kk = kc + krow;
            const float* src = gW + ((size_t)(2*n + (kk>=64))*C + Cin + (kk&63))*128 + c4;
            float4 v = *reinterpret_cast<const float4*>(src);
            float4 w; w.x=to_tf32(v.x); w.y=to_tf32(v.y); w.z=to_tf32(v.z); w.w=to_tf32(v.w);
            *reinterpret_cast<float4*>(&Bs[krow][c4]) = w;
        }
        __syncthreads();
        #pragma unroll
        for (int k8 = 0; k8 < 32; k8 += 8) {
            int kg = kc + k8;
            int ar = lane>>2, ac = kg + (lane&3);
            uint32_t a[2][4];
            #pragma unroll
            for (int mt = 0; mt < 2; ++mt) {
                int rr = ar + mt*16;
                a[mt][0] = cvu(As[rr][ac]);
                a[mt][1] = cvu(As[rr+8][ac]);
                a[mt][2] = cvu(As[rr][ac+4]);
                a[mt][3] = cvu(As[rr+8][ac+4]);
            }
            #pragma unroll
            for (int j = 0; j < 4; ++j) {
                int col = warp*32 + j*8 + (lane>>2);
                uint32_t b0 = __float_as_uint(Bs[k8 + (lane&3)][col]);
                uint32_t b1 = __float_as_uint(Bs[k8 + (lane&3) + 4][col]);
                mma_tf32(acc[0][j], a[0], b0, b1);
                mma_tf32(acc[1][j], a[1], b0, b1);
            }
        }
        __syncthreads();
    }
    #pragma unroll
    for (int mt = 0; mt < 2; ++mt) {
        #pragma unroll
        for (int j = 0; j < 4; ++j) {
            int col = warp*32 + j*8 + (lane&3)*2;
            #pragma unroll
            for (int half = 0; half < 2; ++half) {
                int b = mt*16 + (lane>>2) + half*8;
                float v0 = acc[mt][j][half*2], v1 = acc[mt][j][half*2+1];
                size_t base = (size_t)b*NN + n;
                float2 cgv = *reinterpret_cast<const float2*>(&cg_t[base*128 + col]);
                v0 += cgv.x; v1 += cgv.y;
                if (col < 64) {
                    float z0 = sigm(v0), z1 = sigm(v1);
                    *reinterpret_cast<float2*>(&g_zs[base*64 + col]) =
                        make_float2(z0 * As[b][col], z1 * As[b][col+1]);
                } else {
                    *reinterpret_cast<float2*>(&g_r[base*64 + col - 64]) =
                        make_float2(sigm(v0), sigm(v1));
                }
            }
        }
    }
}

// Update via tf32 MMA. N=64. Epilogue: +cu_t, tanh, GRU combine, write state & hs.
__global__ void __launch_bounds__(128) k_upd_mma(
        const float* __restrict__ zs, const float* __restrict__ mixzs,
        const float* __restrict__ uW, const float* __restrict__ cu_t,
        int C, int Cin, float* __restrict__ hs, int t) {
    __shared__ float As[32][132];
    __shared__ float Bs[32][72];
    int n = blockIdx.x;
    int tid = threadIdx.x;
    int warp = tid >> 5, lane = tid & 31;
    #pragma unroll
    for (int i = 0; i < 8; ++i) {
        int idx = tid + i*128;
        int row = idx >> 5;
        int c4 = (idx & 31) * 4;
        float4 v = (c4 < 64)
            ? *reinterpret_cast<const float4*>(&zs[((size_t)row*NN + n)*64 + c4])
            : *reinterpret_cast<const float4*>(&mixzs[((size_t)row*NN + n)*64 + c4 - 64]);
        *reinterpret_cast<float4*>(&As[row][c4]) = v;
    }
    float acc[2][2][4];
    #pragma unroll
    for (int mt=0; mt<2; ++mt) for (int j=0;j<2;++j) for (int q=0;q<4;++q) acc[mt][j][q]=0.f;

    for (int kc = 0; kc < 128; kc += 32) {
        #pragma unroll
        for (int i = 0; i < 4; ++i) {
            int idx = tid + i*128;
            int krow = idx >> 4;
            int c4 = (idx & 15) * 4;
            int kk = kc + krow;
            const float* src = uW + ((size_t)(2*n + (kk>=64))*C + Cin + (kk&63))*64 + c4;
            float4 v = *reinterpret_cast<const float4*>(src);
            float4 w; w.x=to_tf32(v.x); w.y=to_tf32(v.y); w.z=to_tf32(v.z); w.w=to_tf32(v.w);
            *reinterpret_cast<float4*>(&Bs[krow][c4]) = w;
        }
        __syncthreads();
        #pragma unroll
        for (int k8 = 0; k8 < 32; k8 += 8) {
            int kg = kc + k8;
            int ar = lane>>2, ac = kg + (lane&3);
            uint32_t a[2][4];
            #pragma unroll
            for (int mt = 0; mt < 2; ++mt) {
                int rr = ar + mt*16;
                a[mt][0] = cvu(As[rr][ac]);
                a[mt][1] = cvu(As[rr+8][ac]);
                a[mt][2] = cvu(As[rr][ac+4]);
                a[mt][3] = cvu(As[rr+8][ac+4]);
            }
            #pragma unroll
            for (int j = 0; j < 2; ++j) {
                int col = warp*16 + j*8 + (lane>>2);
                uint32_t b0 = __float_as_uint(Bs[k8 + (lane&3)][col]);
                uint32_t b1 = __float_as_uint(Bs[k8 + (lane&3) + 4][col]);
                mma_tf32(acc[0][j], a[0], b0, b1);
                mma_tf32(acc[1][j], a[1], b0, b1);
            }
        }
        __syncthreads();
    }
    #pragma unroll
    for (int mt = 0; mt < 2; ++mt) {
        #pragma unroll
        for (int j = 0; j < 2; ++j) {
            int col = warp*16 + j*8 + (lane&3)*2;
            #pragma unroll
            for (int half = 0; half < 2; ++half) {
                int b = mt*16 + (lane>>2) + half*8;
                float v0 = acc[mt][j][half*2], v1 = acc[mt][j][half*2+1];
                size_t base = (size_t)b*NN + n;
                float2 cuv = *reinterpret_cast<const float2*>(&cu_t[base*64 + col]);
                float hc0 = tanhfast(v0 + cuv.x), hc1 = tanhfast(v1 + cuv.y);
                size_t idx = base*64 + col;
                float2 rr = *reinterpret_cast<const float2*>(&g_r[idx]);
                float2 st = *reinterpret_cast<const float2*>(&g_state[idx]);
                float h0 = rr.x*st.x + (1.f-rr.x)*hc0;
                float h1 = rr.y*st.y + (1.f-rr.y)*hc1;
                *reinterpret_cast<float2*>(&g_state[idx]) = make_float2(h0, h1);
                *reinterpret_cast<float2*>(&hs[(((size_t)b*TT + t)*NN + n)*64 + col]) = make_float2(h0, h1);
            }
        }
    }
}

// Layer-0 precompute (Cin=2) — cheap SIMT.
__global__ void __launch_bounds__(192) k_precomp(
        const float* __restrict__ xt, const float* __restrict__ mxt,
        const float* __restrict__ gW, const float* __restrict__ uW,
        const float* __restrict__ gb, const float* __restrict__ ub,
        float* __restrict__ cg, float* __restrict__ cu, int Cin) {
    const int C = Cin + HH;
    __shared__ float xs[64][2];
    __shared__ float ms[64][2];
    int n = blockIdx.x;
    int r0 = blockIdx.y * 64;
    int tid = threadIdx.x;
    for (int idx = tid; idx < 64*Cin; idx += 192) {
        int r = idx / Cin, c = idx - r*Cin;
        int z = r0 + r;
        xs[r][c] = xt[((size_t)z*NN + n)*Cin + c];
        int g = z*Cin + c;
        ms[r][c] = mxt[((size_t)(g>>6)*NN + n)*64 + (g&63)];
    }
    __syncthreads();
    float a[64];
    #pragma unroll
    for (int i = 0; i < 64; ++i) a[i] = 0.f;
    if (tid < 128) {
        int o = tid;
        const float* W0 = gW + (size_t)(n*2)*C*128 + o;
        const float* W1 = gW + (size_t)(n*2+1)*C*128 + o;
        for (int c = 0; c < Cin; ++c) {
            float w0 = W0[c*128], w1 = W1[c*128];
            #pragma unroll
            for (int r = 0; r < 64; ++r) a[r] += xs[r][c]*w0 + ms[r][c]*w1;
        }
        float bias = gb[n*128 + o];
        for (int r = 0; r < 64; ++r) {
            int z = r0 + r; int b = z / 12, t = z - b*12;
            cg[(((size_t)t*BB + b)*NN + n)*128 + o] = a[r] + bias;
        }
    } else {
        int o = tid - 128;
        const float* W0 = uW + (size_t)(n*2)*C*64 + o;
        const float* W1 = uW + (size_t)(n*2+1)*C*64 + o;
        for (int c = 0; c < Cin; ++c) {
            float w0 = W0[c*64], w1 = W1[c*64];
            #pragma unroll
            for (int r = 0; r < 64; ++r) a[r] += xs[r][c]*w0 + ms[r][c]*w1;
        }
        float bias = ub[n*64 + o];
        for (int r = 0; r < 64; ++r) {
            int z = r0 + r; int b = z / 12, t = z - b*12;
            cu[(((size_t)t*BB + b)*NN + n)*64 + o] = a[r] + bias;
        }
    }
}

// Layer-1 precompute via MMA: per node, M=384(z) x K=128([xt|mxt]) x N=192([gate|upd]).
// grid (512, 3 m-chunks of 128), block 256 (8 warps: 4 over M, 2 over N).
__global__ void __launch_bounds__(256) k_precomp_mma(
        const float* __restrict__ xt, const float* __restrict__ mxt,
        const float* __restrict__ gW, const float* __restrict__ uW,
        const float* __restrict__ gb, const float* __restrict__ ub,
        float* __restrict__ cg, float* __restrict__ cu) {
    const int C = 128;
    __shared__ float As[128][36];
    __shared__ float Bs[32][200];
    int n = blockIdx.x;
    int m0 = blockIdx.y * 128;
    int tid = threadIdx.x;
    int warp = tid >> 5, lane = tid & 31;
    int wm = warp >> 1, wn = warp & 1;
    float acc[2][12][4];
    #pragma unroll
    for (int mt=0;mt<2;++mt) for (int j=0;j<12;++j) for (int q=0;q<4;++q) acc[mt][j][q]=0.f;

    for (int kc = 0; kc < 128; kc += 32) {
        // A: 128 rows x 32 k = 1024 float4 / 256 = 4 each
        #pragma unroll
        for (int i = 0; i < 4; ++i) {
            int idx = tid + i*256;
            int row = idx >> 3;
            int c4 = (idx & 7) * 4;
            int z = m0 + row;
            int k = kc + c4;
            float4 v = (k < 64)
                ? *reinterpret_cast<const float4*>(&xt[((size_t)z*NN + n)*64 + k])
                : *reinterpret_cast<const float4*>(&mxt[((size_t)z*NN + n)*64 + k - 64]);
            float4 w; w.x=to_tf32(v.x); w.y=to_tf32(v.y); w.z=to_tf32(v.z); w.w=to_tf32(v.w);
            *reinterpret_cast<float4*>(&As[row][c4]) = w;
        }
        // B: 32 k x 192 n = 1536 float4 / 256 = 6 each
        #pragma unroll
        for (int i = 0; i < 6; ++i) {
            int idx = tid + i*256;
            int krow = idx / 48;
            int c4 = (idx % 48) * 4;
            int kk = kc + krow;
            const float* src = (c4 < 128)
                ? gW + ((size_t)(2*n + (kk>=64))*C + (kk&63))*128 + c4
                : uW + ((size_t)(2*n + (kk>=64))*C + (kk&63))*64 + (c4 - 128);
            float4 v = *reinterpret_cast<const float4*>(src);
            float4 w; w.x=to_tf32(v.x); w.y=to_tf32(v.y); w.z=to_tf32(v.z); w.w=to_tf32(v.w);
            *reinterpret_cast<float4*>(&Bs[krow][c4]) = w;
        }
        __syncthreads();
        #pragma unroll
        for (int k8 = 0; k8 < 32; k8 += 8) {
            uint32_t a[2][4];
            int ac = k8 + (lane&3);
            #pragma unroll
            for (int mt = 0; mt < 2; ++mt) {
                int rr = wm*32 + mt*16 + (lane>>2);
                a[mt][0] = __float_as_uint(As[rr][ac]);
                a[mt][1] = __float_as_uint(As[rr+8][ac]);
                a[mt][2] = __float_as_uint(As[rr][ac+4]);
                a[mt][3] = __float_as_uint(As[rr+8][ac+4]);
            }
            #pragma unroll
            for (int j = 0; j < 12; ++j) {
                int col = wn*96 + j*8 + (lane>>2);
                uint32_t b0 = __float_as_uint(Bs[k8 + (lane&3)][col]);
                uint32_t b1 = __float_as_uint(Bs[k8 + (lane&3) + 4][col]);
                mma_tf32(acc[0][j], a[0], b0, b1);
                mma_tf32(acc[1][j], a[1], b0, b1);
            }
        }
        __syncthreads();
    }
    #pragma unroll
    for (int mt = 0; mt < 2; ++mt) {
        #pragma unroll
        for (int j = 0; j < 12; ++j) {
            int col = wn*96 + j*8 + (lane&3)*2;
            #pragma unroll
            for (int half = 0; half < 2; ++half) {
                int z = m0 + wm*32 + mt*16 + (lane>>2) + half*8;
                int b = z / 12, t = z - b*12;
                float v0 = acc[mt][j][half*2], v1 = acc[mt][j][half*2+1];
                if (col < 128) {
                    float2 bb = *reinterpret_cast<const float2*>(&gb[n*128 + col]);
                    *reinterpret_cast<float2*>(&cg[(((size_t)t*BB + b)*NN + n)*128 + col]) =
                        make_float2(v0 + bb.x, v1 + bb.y);
                } else {
                    int o = col - 128;
                    float2 bb = *reinterpret_cast<const float2*>(&ub[n*64 + o]);
                    *reinterpret_cast<float2*>(&cu[(((size_t)t*BB + b)*NN + n)*64 + o]) =
                        make_float2(v0 + bb.x, v1 + bb.y);
                }
            }
        }
    }
}

// hlin = uW_flat @ hypW + hypb ; fs = group-sum of 4
__global__ void k_hyp(const float* __restrict__ hypW, const float* __restrict__ hypb) {
    __shared__ float part[192];
    __shared__ float hlin[48];
    int n = blockIdx.x;
    int tid = threadIdx.x;
    int j = tid % 48, sl = tid / 48;
    const float* u = g_uW + (size_t)n * 16384;
    float a = 0.f;
    int i0 = sl * 4096;
    for (int i = i0; i < i0 + 4096; ++i) a += u[i] * hypW[i*48 + j];
    part[tid] = a;
    __syncthreads();
    if (tid < 48) hlin[tid] = part[tid] + part[48+tid] + part[96+tid] + part[144+tid] + hypb[tid];
    __syncthreads();
    if (tid < 12) {
        g_fs[n*TT + tid] = hlin[tid*4] + hlin[tid*4+1] + hlin[tid*4+2] + hlin[tid*4+3];
    }
}

// copy last hidden state into compact [b][n][64]
__global__ void k_copy_last() {
    int idx = blockIdx.x*blockDim.x + threadIdx.x;
    if (idx >= BB*NN*HH) return;
    int c = idx & 63;
    int bn = idx >> 6;
    int n = bn & 511, b = bn >> 9;
    g_hv[idx] = g_hs1[(((size_t)b*TT + (TT-1))*NN + n)*64 + c];
}

// Y[rows,64] = act(X[rows,64]@W[64,64] + bias), tf32 MMA, 128-row tiles, 256 thr.
__global__ void __launch_bounds__(256) k_gemm64_mma(
        const float* __restrict__ X, const float* __restrict__ W,
        const float* __restrict__ bias, float* __restrict__ Y, int relu) {
    __shared__ float Xs[128][36];
    __shared__ float Ws[32][72];
    int r0 = blockIdx.x * 128;
    int tid = threadIdx.x;
    int warp = tid >> 5, lane = tid & 31;
    float acc[8][4];
    #pragma unroll
    for (int j=0;j<8;++j) for (int q=0;q<4;++q) acc[j][q]=0.f;
    for (int kc = 0; kc < 64; kc += 32) {
        #pragma unroll
        for (int i = 0; i < 4; ++i) {
            int idx = tid + i*256;
            int row = idx >> 3;
            int c4 = (idx & 7) * 4;
            float4 v = *reinterpret_cast<const float4*>(&X[(size_t)(r0+row)*64 + kc + c4]);
            float4 w; w.x=to_tf32(v.x); w.y=to_tf32(v.y); w.z=to_tf32(v.z); w.w=to_tf32(v.w);
            *reinterpret_cast<float4*>(&Xs[row][c4]) = w;
        }
        #pragma unroll
        for (int i = 0; i < 2; ++i) {
            int idx = tid + i*256;
            int krow = idx >> 4;
            int c4 = (idx & 15) * 4;
            float4 v = *reinterpret_cast<const float4*>(&W[(size_t)(kc+krow)*64 + c4]);
            float4 w; w.x=to_tf32(v.x); w.y=to_tf32(v.y); w.z=to_tf32(v.z); w.w=to_tf32(v.w);
            *reinterpret_cast<float4*>(&Ws[krow][c4]) = w;
        }
        __syncthreads();
        #pragma unroll
        for (int k8 = 0; k8 < 32; k8 += 8) {
            uint32_t a[4];
            int ar = warp*16 + (lane>>2);
            int ac = k8 + (lane&3);
            a[0] = __float_as_uint(Xs[ar][ac]);
            a[1] = __float_as_uint(Xs[ar+8][ac]);
            a[2] = __float_as_uint(Xs[ar][ac+4]);
            a[3] = __float_as_uint(Xs[ar+8][ac+4]);
            #pragma unroll
            for (int j = 0; j < 8; ++j) {
                uint32_t b0 = __float_as_uint(Ws[k8 + (lane&3)][j*8 + (lane>>2)]);
                uint32_t b1 = __float_as_uint(Ws[k8 + (lane&3) + 4][j*8 + (lane>>2)]);
                mma_tf32(acc[j], a, b0, b1);
            }
        }
        __syncthreads();
    }
    int row = r0 + warp*16 + (lane>>2);
    #pragma unroll
    for (int j = 0; j < 8; ++j) {
        int col = j*8 + (lane&3)*2;
        float b0 = bias ? bias[col] : 0.f, b1 = bias ? bias[col+1] : 0.f;
        float v0 = acc[j][0] + b0, v1 = acc[j][1] + b1;
        float v2 = acc[j][2] + b0, v3 = acc[j][3] + b1;
        if (relu) { v0=fmaxf(v0,0.f); v1=fmaxf(v1,0.f); v2=fmaxf(v2,0.f); v3=fmaxf(v3,0.f); }
        *reinterpret_cast<float2*>(&Y[(size_t)row*64 + col]) = make_float2(v0, v1);
        *reinterpret_cast<float2*>(&Y[(size_t)(row+8)*64 + col]) = make_float2(v2, v3);
    }
}

// attention per (b,n): T=12, heads=2, d=32; v built from vb*fs + bv.
__global__ void k_attn(const float* __restrict__ bv) {
    __shared__ float qs[12][64], ks[12][64], vs[12][64];
    __shared__ float sc[2][12][12];
    int bn = blockIdx.x;
    int b = bn >> 9, n = bn & 511;
    int tid = threadIdx.x;
    for (int idx = tid; idx < 12*64; idx += 128) {
        int t = idx >> 6, c = idx & 63;
        size_t g = (((size_t)b*TT + t)*NN + n)*HH + c;
        qs[t][c] = g_q[g];
        ks[t][c] = g_k[g];
        vs[t][c] = g_fs[n*TT + t] * g_v[((size_t)b*NN + n)*64 + c] + bv[c];
    }
    __syncthreads();
    for (int idx = tid; idx < 288; idx += 128) {
        int h = idx / 144, rem = idx - h*144;
        int t = rem / 12, s = rem - t*12;
        float d = 0.f;
        #pragma unroll
        for (int k = 0; k < 32; ++k) d += qs[t][h*32 + k] * ks[s][h*32 + k];
        sc[h][t][s] = d * 0.17677669529663687f;
    }
    __syncthreads();
    if (tid < 24) {
        int h = tid / 12, t = tid - h*12;
        float mx = -1e30f;
        #pragma unroll
        for (int s = 0; s < 12; ++s) mx = fmaxf(mx, sc[h][t][s]);
        float sum = 0.f;
        #pragma unroll
        for (int s = 0; s < 12; ++s) { float e = __expf(sc[h][t][s] - mx); sc[h][t][s] = e; sum += e; }
        float inv = 1.f / sum;
        #pragma unroll
        for (int s = 0; s < 12; ++s) sc[h][t][s] *= inv;
    }
    __syncthreads();
    for (int idx = tid; idx < 768; idx += 128) {
        int h = idx / 384, rem = idx - h*384;
        int t = rem >> 5, d = rem & 31;
        float a = 0.f;
        #pragma unroll
        for (int s = 0; s < 12; ++s) a += sc[h][t][s] * vs[s][h*32 + d];
        g_o[(((size_t)b*TT + t)*NN + n)*HH + h*32 + d] = a;
    }
}

// warp-per-row LN(A+Bv): 8 rows / block of 256.
__global__ void __launch_bounds__(256) k_lnres_w(
        const float* __restrict__ A, const float* __restrict__ Bv,
        const float* __restrict__ g, const float* __restrict__ be,
        float* __restrict__ Y) {
    int lane = threadIdx.x & 31;
    size_t row = (size_t)blockIdx.x * 8 + (threadIdx.x >> 5);
    int c = lane * 2;
    float2 a = *reinterpret_cast<const float2*>(&A[row*64 + c]);
    float2 b2 = *reinterpret_cast<const float2*>(&Bv[row*64 + c]);
    float x0 = a.x + b2.x, x1 = a.y + b2.y;
    float s = x0 + x1, sq = x0*x0 + x1*x1;
    #pragma unroll
    for (int o = 16; o > 0; o >>= 1) {
        s  += __shfl_xor_sync(0xffffffffu, s, o);
        sq += __shfl_xor_sync(0xffffffffu, sq, o);
    }
    float mu = s * (1.f/64.f);
    float var = sq * (1.f/64.f) - mu*mu;
    float rstd = rsqrtf(var + 1e-5f);
    float y0 = (x0 - mu) * rstd * g[c] + be[c];
    float y1 = (x1 - mu) * rstd * g[c+1] + be[c+1];
    *reinterpret_cast<float2*>(&Y[row*64 + c]) = make_float2(y0, y1);
}

// warp-per-row fc: y[row] = dot(X[row], w) + b
__global__ void __launch_bounds__(256) k_fc_w(
        const float* __restrict__ X, const float* __restrict__ w,
        const float* __restrict__ bp, float* __restrict__ Y) {
    int lane = threadIdx.x & 31;
    size_t row = (size_t)blockIdx.x * 8 + (threadIdx.x >> 5);
    int c = lane * 2;
    float2 x = *reinterpret_cast<const float2*>(&X[row*64 + c]);
    float s = x.x * w[c] + x.y * w[c+1];
    #pragma unroll
    for (int o = 16; o > 0; o >>= 1) s += __shfl_xor_sync(0xffffffffu, s, o);
    if (lane == 0) Y[row] = s + bp[0];
}

// ---------------- host ----------------

extern "C" void kernel_launch(void* const* d_in, const int* in_sizes, int n_in,
                              void* d_out, int out_size) {
    const float* src  = (const float*)d_in[0];
    const float* emb  = (const float*)d_in[2];
    const float* gwp0 = (const float*)d_in[3];
    const float* gbp0 = (const float*)d_in[4];
    const float* uwp0 = (const float*)d_in[5];
    const float* ubp0 = (const float*)d_in[6];
    const float* gwp1 = (const float*)d_in[7];
    const float* gbp1 = (const float*)d_in[8];
    const float* uwp1 = (const float*)d_in[9];
    const float* ubp1 = (const float*)d_in[10];
    const float* hypW = (const float*)d_in[11];
    const float* hypb = (const float*)d_in[12];

    const float *Wq,*Wk,*Wv,*ffW1,*ffW2,*bq,*bk,*bv,*ffb1,*ffb2,*ln1g,*ln1b,*ln2g,*ln2b,*fcW,*fcb;
    if (n_in > 14 && in_sizes[14] == 64) {
        Wq  = (const float*)d_in[13]; bq  = (const float*)d_in[14];
        Wk  = (const float*)d_in[15]; bk  = (const float*)d_in[16];
        Wv  = (const float*)d_in[17]; bv  = (const float*)d_in[18];
        ln1g= (const float*)d_in[19]; ln1b= (const float*)d_in[20];
        ffW1= (const float*)d_in[21]; ffb1= (const float*)d_in[22];
        ffW2= (const float*)d_in[23]; ffb2= (const float*)d_in[24];
        ln2g= (const float*)d_in[25]; ln2b= (const float*)d_in[26];
        fcW = (const float*)d_in[27]; fcb = (const float*)d_in[28];
    } else {
        Wq  = (const float*)d_in[13]; Wk  = (const float*)d_in[14];
        Wv  = (const float*)d_in[15]; ffW1= (const float*)d_in[16];
        ffW2= (const float*)d_in[17]; bq  = (const float*)d_in[18];
        bk  = (const float*)d_in[19]; bv  = (const float*)d_in[20];
        ffb1= (const float*)d_in[21]; ffb2= (const float*)d_in[22];
        ln1g= (const float*)d_in[23]; ln1b= (const float*)d_in[24];
        ln2g= (const float*)d_in[25]; ln2b= (const float*)d_in[26];
        fcW = (const float*)d_in[27]; fcb = (const float*)d_in[28];
    }

    float *p_gW,*p_gb,*p_uW,*p_ub,*p_state,*p_mixs,*p_zs,*p_mixzs,*p_cg,*p_cu,*p_mxt,*p_xt0t;
    float *p_hs0,*p_hs1,*p_hv,*p_q,*p_k,*p_v,*p_o,*p_val,*p_ff1,*p_ffo,*p_out2;
    cudaGetSymbolAddress((void**)&p_gW, g_gW);
    cudaGetSymbolAddress((void**)&p_gb, g_gb);
    cudaGetSymbolAddress((void**)&p_uW, g_uW);
    cudaGetSymbolAddress((void**)&p_ub, g_ub);
    cudaGetSymbolAddress((void**)&p_state, g_state);
    cudaGetSymbolAddress((void**)&p_mixs, g_mixs);
    cudaGetSymbolAddress((void**)&p_zs, g_zs);
    cudaGetSymbolAddress((void**)&p_mixzs, g_mixzs);
    cudaGetSymbolAddress((void**)&p_cg, g_cg);
    cudaGetSymbolAddress((void**)&p_cu, g_cu);
    cudaGetSymbolAddress((void**)&p_mxt, g_mxt);
    cudaGetSymbolAddress((void**)&p_xt0t, g_xt0t);
    cudaGetSymbolAddress((void**)&p_hs0, g_hs0);
    cudaGetSymbolAddress((void**)&p_hs1, g_hs1);
    cudaGetSymbolAddress((void**)&p_hv, g_hv);
    cudaGetSymbolAddress((void**)&p_q, g_q);
    cudaGetSymbolAddress((void**)&p_k, g_k);
    cudaGetSymbolAddress((void**)&p_v, g_v);
    cudaGetSymbolAddress((void**)&p_o, g_o);
    cudaGetSymbolAddress((void**)&p_val, g_val);
    cudaGetSymbolAddress((void**)&p_ff1, g_ff1);
    cudaGetSymbolAddress((void**)&p_ffo, g_ffo);
    cudaGetSymbolAddress((void**)&p_out2, g_out2);

    k_adj<<<NN, 256>>>(emb);

    for (int layer = 0; layer < 2; ++layer) {
        int Cin = (layer == 0) ? 2 : 64;
        int C = Cin + HH;
        float* hs_out;
        if (layer == 0) {
            int s;
            s = 2*C*128/4; k_matpool4<<<(NN*s+255)/256, 256>>>(emb, gwp0, p_gW, s);
            s = 128/4;     k_matpool4<<<(NN*s+255)/256, 256>>>(emb, gbp0, p_gb, s);
            s = 2*C*64/4;  k_matpool4<<<(NN*s+255)/256, 256>>>(emb, uwp0, p_uW, s);
            s = 64/4;      k_matpool4<<<(NN*s+255)/256, 256>>>(emb, ubp0, p_ub, s);
            k_transp0<<<(ZT*NN*2 + 255)/256, 256>>>(src, p_xt0t);
            k_mix64<<<dim3(8, (ZT*2)/64), 128>>>(p_xt0t, p_mxt);
            k_precomp<<<dim3(NN, 6), 192>>>(src, p_mxt, p_gW, p_uW, p_gb, p_ub, p_cg, p_cu, Cin);
            hs_out = p_hs0;
        } else {
            int s;
            s = 2*C*128/4; k_matpool4<<<(NN*s+255)/256, 256>>>(emb, gwp1, p_gW, s);
            s = 128/4;     k_matpool4<<<(NN*s+255)/256, 256>>>(emb, gbp1, p_gb, s);
            s = 2*C*64/4;  k_matpool4<<<(NN*s+255)/256, 256>>>(emb, uwp1, p_uW, s);
            s = 64/4;      k_matpool4<<<(NN*s+255)/256, 256>>>(emb, ubp1, p_ub, s);
            k_mix64<<<dim3(8, ZT), 128>>>(p_hs0, p_mxt);
            k_precomp_mma<<<dim3(NN, 3), 256>>>(p_hs0, p_mxt, p_gW, p_uW, p_gb, p_ub, p_cg, p_cu);
            hs_out = p_hs1;
        }
        k_zero<<<1024, 256>>>(p_state, BB*NN*HH);
        for (int t = 0; t < TT; ++t) {
            const float* cg_t = p_cg + (size_t)t*BB*NN*128;
            const float* cu_t = p_cu + (size_t)t*BB*NN*64;
            k_mix64<<<dim3(8, BB), 128>>>(p_state, p_mixs);
            k_gate_mma<<<NN, 128>>>(p_state, p_mixs, p_gW, cg_t, C, Cin);
            k_mix64<<<dim3(8, BB), 128>>>(p_zs, p_mixzs);
            k_upd_mma<<<NN, 128>>>(p_zs, p_mixzs, p_uW, cu_t, C, Cin, hs_out, t);
        }
    }

    // hypernetwork + compact last state
    k_hyp<<<NN, 192>>>(hypW, hypb);
    k_copy_last<<<(BB*NN*HH + 255)/256, 256>>>();

    // projections
    k_gemm64_mma<<<BTN/128, 256>>>(p_hs1, Wq, bq, p_q, 0);
    k_gemm64_mma<<<BTN/128, 256>>>(p_hs1, Wk, bk, p_k, 0);
    k_gemm64_mma<<<BB*NN/128, 256>>>(p_hv, Wv, nullptr, p_v, 0);

    k_attn<<<BB*NN, 128>>>(bv);

    k_lnres_w<<<BTN/8, 256>>>(p_o, p_hs1, ln1g, ln1b, p_val);
    k_gemm64_mma<<<BTN/128, 256>>>(p_val, ffW1, ffb1, p_ff1, 1);
    k_gemm64_mma<<<BTN/128, 256>>>(p_ff1, ffW2, ffb2, p_ffo, 0);
    k_lnres_w<<<BTN/8, 256>>>(p_ffo, p_val, ln2g, ln2b, p_out2);
    k_fc_w<<<BTN/8, 256>>>(p_out2, fcW, fcb, (float*)d_out);
}

// round 4
// speedup vs baseline: 3.0253x; 1.1034x over previous
#include <cuda_runtime.h>
#include <math.h>
#include <stdint.h>

#define BB 32
#define TT 12
#define NN 512
#define HH 64
#define EE 16
#define BTN (BB*TT*NN)
#define BTNH (BTN*HH)
#define ZT (BB*TT)          // 384
#define GRID_P 256          // persistent grid (<= 296 co-resident guaranteed)

// ---------------- scratch (device globals) ----------------
__device__ float g_adj[NN*NN];
__device__ float g_gW[NN*2*128*128];
__device__ float g_gb[NN*128];
__device__ float g_uW[NN*2*128*64];
__device__ float g_ub[NN*64];
__device__ float g_state[BB*NN*HH];
__device__ float g_mixs[BB*NN*HH];
__device__ float g_zs[BB*NN*HH];
__device__ float g_mixzs[BB*NN*HH];
__device__ float g_r[BB*NN*HH];
__device__ float g_cg[TT*BB*NN*128];
__device__ float g_cu[TT*BB*NN*64];
__device__ float g_mxt[ZT*NN*64];
__device__ float g_xt0t[TT*NN*64];
__device__ float g_hs0[BTNH];
__device__ float g_hs1[BTNH];
__device__ float g_fs[NN*TT];
__device__ float g_hv[BB*NN*HH];
__device__ float g_q[BTNH];
__device__ float g_k[BTNH];
__device__ float g_v[BB*NN*HH];
__device__ float g_o[BTNH];
__device__ float g_val[BTNH];
__device__ float g_ff1[BTNH];
__device__ float g_ffo[BTNH];
__device__ float g_out2[BTNH];
__device__ unsigned g_bar;

// ---------------- helpers ----------------

__device__ __forceinline__ float to_tf32(float x) {
    uint32_t u;
    asm("cvt.rna.tf32.f32 %0, %1;" : "=r"(u) : "f"(x));
    return __uint_as_float(u);
}
__device__ __forceinline__ uint32_t cvu(float x) {
    uint32_t u;
    asm("cvt.rna.tf32.f32 %0, %1;" : "=r"(u) : "f"(x));
    return u;
}

__device__ __forceinline__ void mma_tf32(float* c, const uint32_t* a, uint32_t b0, uint32_t b1) {
    asm volatile("mma.sync.aligned.m16n8k8.row.col.f32.tf32.tf32.f32 "
        "{%0,%1,%2,%3}, {%4,%5,%6,%7}, {%8,%9}, {%0,%1,%2,%3};"
        : "+f"(c[0]), "+f"(c[1]), "+f"(c[2]), "+f"(c[3])
        : "r"(a[0]), "r"(a[1]), "r"(a[2]), "r"(a[3]), "r"(b0), "r"(b1));
}

__device__ __forceinline__ float sigm(float v) { return 1.f / (1.f + __expf(-v)); }
__device__ __forceinline__ float tanhfast(float v) { return 1.f - 2.f / (__expf(2.f*v) + 1.f); }

// software grid barrier (all GRID_P blocks co-resident by construction)
__device__ __forceinline__ void gbar(unsigned n) {
    __syncthreads();
    if (threadIdx.x == 0) {
        __threadfence();
        atomicAdd(&g_bar, 1u);
        unsigned target = n * GRID_P;
        volatile unsigned* p = &g_bar;
        while (*p < target) __nanosleep(64);
        __threadfence();
    }
    __syncthreads();
}

// ---------------- small kernels ----------------

__global__ void k_reset_bar() { g_bar = 0u; }

__global__ void k_adj(const float* __restrict__ emb) {
    __shared__ float semb[NN*EE];
    __shared__ float row[NN];
    __shared__ float red[256];
    int n = blockIdx.x;
    for (int i = threadIdx.x; i < NN*EE; i += blockDim.x) semb[i] = emb[i];
    __syncthreads();
    float lmax = -1e30f;
    for (int m = threadIdx.x; m < NN; m += blockDim.x) {
        float s = 0.f;
        #pragma unroll
        for (int e = 0; e < EE; ++e) s += semb[n*EE+e] * semb[m*EE+e];
        s = fmaxf(s, 0.f);
        row[m] = s;
        lmax = fmaxf(lmax, s);
    }
    red[threadIdx.x] = lmax; __syncthreads();
    for (int s = 128; s > 0; s >>= 1) {
        if (threadIdx.x < s) red[threadIdx.x] = fmaxf(red[threadIdx.x], red[threadIdx.x+s]);
        __syncthreads();
    }
    float mx = red[0];
    __syncthreads();
    float lsum = 0.f;
    for (int m = threadIdx.x; m < NN; m += blockDim.x) {
        float v = expf(row[m] - mx);
        row[m] = v; lsum += v;
    }
    red[threadIdx.x] = lsum; __syncthreads();
    for (int s = 128; s > 0; s >>= 1) {
        if (threadIdx.x < s) red[threadIdx.x] += red[threadIdx.x+s];
        __syncthreads();
    }
    float inv = 1.f / red[0];
    for (int m = threadIdx.x; m < NN; m += blockDim.x) g_adj[n*NN + m] = row[m] * inv;
}

__global__ void k_matpool4(const float* __restrict__ emb, const float* __restrict__ pool,
                           float* __restrict__ out, int S4) {
    int idx = blockIdx.x*blockDim.x + threadIdx.x;
    if (idx >= NN * S4) return;
    int n = idx / S4, i = idx - n*S4;
    float4 a = make_float4(0.f,0.f,0.f,0.f);
    const float* e = emb + n*EE;
    const float4* p4 = (const float4*)pool;
    #pragma unroll
    for (int k = 0; k < EE; ++k) {
        float w = e[k];
        float4 p = p4[(size_t)k*S4 + i];
        a.x += w*p.x; a.y += w*p.y; a.z += w*p.z; a.w += w*p.w;
    }
    ((float4*)out)[idx] = a;
}

__global__ void k_transp0(const float* __restrict__ src, float* __restrict__ xt0) {
    int idx = blockIdx.x*blockDim.x + threadIdx.x;
    if (idx >= ZT*NN*2) return;
    int c = idx & 1, m = (idx >> 1) & 511, z = idx >> 10;
    int g = z*2 + c;
    xt0[((size_t)(g>>6)*NN + m)*64 + (g&63)] = src[idx];
}

// standalone batched mix (precompute): Y[z][n][c] = sum_m adj[n][m] X[z][m][c]
__global__ void __launch_bounds__(128) k_mix64(const float* __restrict__ X, float* __restrict__ Y) {
    __shared__ float As[64][36];
    __shared__ float Xs[32][72];
    int z = blockIdx.y;
    int r0 = blockIdx.x * 64;
    int tid = threadIdx.x;
    int warp = tid >> 5, lane = tid & 31;
    const float* Xb = X + (size_t)z * (NN*64);
    float* Yb = Y + (size_t)z * (NN*64);
    float acc[8][4];
    #pragma unroll
    for (int j = 0; j < 8; ++j)
        #pragma unroll
        for (int q = 0; q < 4; ++q) acc[j][q] = 0.f;

    for (int kc = 0; kc < NN; kc += 32) {
        #pragma unroll
        for (int i = 0; i < 4; ++i) {
            int idx = tid + i*128;
            int row = idx >> 3;
            int c4 = (idx & 7) * 4;
            float4 v = *reinterpret_cast<const float4*>(&g_adj[(size_t)(r0+row)*NN + kc + c4]);
            float4 w; w.x=to_tf32(v.x); w.y=to_tf32(v.y); w.z=to_tf32(v.z); w.w=to_tf32(v.w);
            *reinterpret_cast<float4*>(&As[row][c4]) = w;
        }
        #pragma unroll
        for (int i = 0; i < 4; ++i) {
            int idx = tid + i*128;
            int row = idx >> 4;
            int c4 = (idx & 15) * 4;
            float4 v = *reinterpret_cast<const float4*>(&Xb[(size_t)(kc+row)*64 + c4]);
            float4 w; w.x=to_tf32(v.x); w.y=to_tf32(v.y); w.z=to_tf32(v.z); w.w=to_tf32(v.w);
            *reinterpret_cast<float4*>(&Xs[row][c4]) = w;
        }
        __syncthreads();
        #pragma unroll
        for (int k8 = 0; k8 < 32; k8 += 8) {
            uint32_t a[4];
            int ar = warp*16 + (lane>>2);
            int ac = k8 + (lane&3);
            a[0] = __float_as_uint(As[ar][ac]);
            a[1] = __float_as_uint(As[ar+8][ac]);
            a[2] = __float_as_uint(As[ar][ac+4]);
            a[3] = __float_as_uint(As[ar+8][ac+4]);
            #pragma unroll
            for (int j = 0; j < 8; ++j) {
                uint32_t b0 = __float_as_uint(Xs[k8 + (lane&3)][j*8 + (lane>>2)]);
                uint32_t b1 = __float_as_uint(Xs[k8 + (lane&3) + 4][j*8 + (lane>>2)]);
                mma_tf32(acc[j], a, b0, b1);
            }
        }
        __syncthreads();
    }
    int row = r0 + warp*16 + (lane>>2);
    #pragma unroll
    for (int j = 0; j < 8; ++j) {
        int col = j*8 + (lane&3)*2;
        *reinterpret_cast<float2*>(&Yb[(size_t)row*64 + col]) = make_float2(acc[j][0], acc[j][1]);
        *reinterpret_cast<float2*>(&Yb[(size_t)(row+8)*64 + col]) = make_float2(acc[j][2], acc[j][3]);
    }
}

// ---------------- persistent recurrence kernel ----------------

// shared scratch: max phase usage = gate (32*132 + 32*136 = 8576 floats)
#define SM_FLOATS 8704

__device__ __forceinline__ void phase_mix(const float* __restrict__ X, float* __restrict__ Y,
                                          float* sm, int tid, int warp, int lane) {
    float (*As)[36] = (float(*)[36])sm;            // 64 x 36
    float (*Xs)[72] = (float(*)[72])(sm + 2304);   // 32 x 72
    int tile = blockIdx.x;          // 256 tiles = 8 rowtiles x 32 z
    int z  = tile >> 3;
    int r0 = (tile & 7) * 64;
    const float* Xb = X + (size_t)z * (NN*64);
    float* Yb = Y + (size_t)z * (NN*64);
    int wm = warp >> 1, wn = warp & 1;
    float acc[4][4];
    #pragma unroll
    for (int j=0;j<4;++j) for (int q=0;q<4;++q) acc[j][q]=0.f;

    for (int kc = 0; kc < NN; kc += 32) {
        #pragma unroll
        for (int i = 0; i < 2; ++i) {
            int idx = tid + i*256;
            int row = idx >> 3;
            int c4 = (idx & 7) * 4;
            float4 v = *reinterpret_cast<const float4*>(&g_adj[(size_t)(r0+row)*NN + kc + c4]);
            float4 w; w.x=to_tf32(v.x); w.y=to_tf32(v.y); w.z=to_tf32(v.z); w.w=to_tf32(v.w);
            *reinterpret_cast<float4*>(&As[row][c4]) = w;
        }
        #pragma unroll
        for (int i = 0; i < 2; ++i) {
            int idx = tid + i*256;
            int row = idx >> 4;
            int c4 = (idx & 15) * 4;
            float4 v = *reinterpret_cast<const float4*>(&Xb[(size_t)(kc+row)*64 + c4]);
            float4 w; w.x=to_tf32(v.x); w.y=to_tf32(v.y); w.z=to_tf32(v.z); w.w=to_tf32(v.w);
            *reinterpret_cast<float4*>(&Xs[row][c4]) = w;
        }
        __syncthreads();
        #pragma unroll
        for (int k8 = 0; k8 < 32; k8 += 8) {
            uint32_t a[4];
            int ar = wm*16 + (lane>>2);
            int ac = k8 + (lane&3);
            a[0] = __float_as_uint(As[ar][ac]);
            a[1] = __float_as_uint(As[ar+8][ac]);
            a[2] = __float_as_uint(As[ar][ac+4]);
            a[3] = __float_as_uint(As[ar+8][ac+4]);
            #pragma unroll
            for (int j = 0; j < 4; ++j) {
                int col = wn*32 + j*8 + (lane>>2);
                uint32_t b0 = __float_as_uint(Xs[k8 + (lane&3)][col]);
                uint32_t b1 = __float_as_uint(Xs[k8 + (lane&3) + 4][col]);
                mma_tf32(acc[j], a, b0, b1);
            }
        }
        __syncthreads();
    }
    int row = r0 + wm*16 + (lane>>2);
    #pragma unroll
    for (int j = 0; j < 4; ++j) {
        int col = wn*32 + j*8 + (lane&3)*2;
        *reinterpret_cast<float2*>(&Yb[(size_t)row*64 + col]) = make_float2(acc[j][0], acc[j][1]);
        *reinterpret_cast<float2*>(&Yb[(size_t)(row+8)*64 + col]) = make_float2(acc[j][2], acc[j][3]);
    }
}

__device__ __forceinline__ void phase_gate(const float* __restrict__ gW, const float* __restrict__ cg_t,
                                           int C, int Cin, float* sm, int tid, int warp, int lane) {
    float (*As)[132] = (float(*)[132])sm;           // 32 x 132
    float (*Bs)[136] = (float(*)[136])(sm + 4224);  // 32 x 136
    int wm = warp >> 2, wn = warp & 3;
    for (int n = blockIdx.x; n < NN; n += GRID_P) {
        __syncthreads();
        #pragma unroll
        for (int i = 0; i < 4; ++i) {
            int idx = tid + i*256;
            int row = idx >> 5;
            int c4 = (idx & 31) * 4;
            float4 v = (c4 < 64)
                ? *reinterpret_cast<const float4*>(&g_state[((size_t)row*NN + n)*64 + c4])
                : *reinterpret_cast<const float4*>(&g_mixs[((size_t)row*NN + n)*64 + c4 - 64]);
            *reinterpret_cast<float4*>(&As[row][c4]) = v;
        }
        float acc[4][4];
        #pragma unroll
        for (int j=0;j<4;++j) for (int q=0;q<4;++q) acc[j][q]=0.f;
        for (int kc = 0; kc < 128; kc += 32) {
            #pragma unroll
            for (int i = 0; i < 4; ++i) {
                int idx = tid + i*256;
                int krow = idx >> 5;
                int c4 = (idx & 31) * 4;
                int kk = kc + krow;
                const float* src = gW + ((size_t)(2*n + (kk>=64))*C + Cin + (kk&63))*128 + c4;
                float4 v = *reinterpret_cast<const float4*>(src);
                float4 w; w.x=to_tf32(v.x); w.y=to_tf32(v.y); w.z=to_tf32(v.z); w.w=to_tf32(v.w);
                *reinterpret_cast<float4*>(&Bs[krow][c4]) = w;
            }
            __syncthreads();
            #pragma unroll
            for (int k8 = 0; k8 < 32; k8 += 8) {
                int ar = wm*16 + (lane>>2);
                int ac = kc + k8 + (lane&3);
                uint32_t a[4];
                a[0] = cvu(As[ar][ac]);
                a[1] = cvu(As[ar+8][ac]);
                a[2] = cvu(As[ar][ac+4]);
                a[3] = cvu(As[ar+8][ac+4]);
                #pragma unroll
                for (int j = 0; j < 4; ++j) {
                    int col = wn*32 + j*8 + (lane>>2);
                    uint32_t b0 = __float_as_uint(Bs[k8 + (lane&3)][col]);
                    uint32_t b1 = __float_as_uint(Bs[k8 + (lane&3) + 4][col]);
                    mma_tf32(acc[j], a, b0, b1);
                }
            }
            __syncthreads();
        }
        #pragma unroll
        for (int j = 0; j < 4; ++j) {
            int col = wn*32 + j*8 + (lane&3)*2;
            #pragma unroll
            for (int half = 0; half < 2; ++half) {
                int b = wm*16 + (lane>>2) + half*8;
                float v0 = acc[j][half*2], v1 = acc[j][half*2+1];
                size_t base = (size_t)b*NN + n;
                float2 cgv = *reinterpret_cast<const float2*>(&cg_t[base*128 + col]);
                v0 += cgv.x; v1 += cgv.y;
                if (col < 64) {
                    *reinterpret_cast<float2*>(&g_zs[base*64 + col]) =
                        make_float2(sigm(v0) * As[b][col], sigm(v1) * As[b][col+1]);
                } else {
                    *reinterpret_cast<float2*>(&g_r[base*64 + col - 64]) =
                        make_float2(sigm(v0), sigm(v1));
                }
            }
        }
    }
}

__device__ __forceinline__ void phase_upd(const float* __restrict__ uW, const float* __restrict__ cu_t,
                                          int C, int Cin, float* __restrict__ hs, int t,
                                          float* sm, int tid, int warp, int lane) {
    float (*As)[132] = (float(*)[132])sm;
    float (*Bs)[72]  = (float(*)[72])(sm + 4224);
    int wm = warp >> 2, wn = warp & 3;
    for (int n = blockIdx.x; n < NN; n += GRID_P) {
        __syncthreads();
        #pragma unroll
        for (int i = 0; i < 4; ++i) {
            int idx = tid + i*256;
            int row = idx >> 5;
            int c4 = (idx & 31) * 4;
            float4 v = (c4 < 64)
                ? *reinterpret_cast<const float4*>(&g_zs[((size_t)row*NN + n)*64 + c4])
                : *reinterpret_cast<const float4*>(&g_mixzs[((size_t)row*NN + n)*64 + c4 - 64]);
            *reinterpret_cast<float4*>(&As[row][c4]) = v;
        }
        float acc[2][4];
        #pragma unroll
        for (int j=0;j<2;++j) for (int q=0;q<4;++q) acc[j][q]=0.f;
        for (int kc = 0; kc < 128; kc += 32) {
            #pragma unroll
            for (int i = 0; i < 2; ++i) {
                int idx = tid + i*256;
                int krow = idx >> 4;
                int c4 = (idx & 15) * 4;
                int kk = kc + krow;
                const float* src = uW + ((size_t)(2*n + (kk>=64))*C + Cin + (kk&63))*64 + c4;
                float4 v = *reinterpret_cast<const float4*>(src);
                float4 w; w.x=to_tf32(v.x); w.y=to_tf32(v.y); w.z=to_tf32(v.z); w.w=to_tf32(v.w);
                *reinterpret_cast<float4*>(&Bs[krow][c4]) = w;
            }
            __syncthreads();
            #pragma unroll
            for (int k8 = 0; k8 < 32; k8 += 8) {
                int ar = wm*16 + (lane>>2);
                int ac = kc + k8 + (lane&3);
                uint32_t a[4];
                a[0] = cvu(As[ar][ac]);
                a[1] = cvu(As[ar+8][ac]);
                a[2] = cvu(As[ar][ac+4]);
                a[3] = cvu(As[ar+8][ac+4]);
                #pragma unroll
                for (int j = 0; j < 2; ++j) {
                    int col = wn*16 + j*8 + (lane>>2);
                    uint32_t b0 = __float_as_uint(Bs[k8 + (lane&3)][col]);
                    uint32_t b1 = __float_as_uint(Bs[k8 + (lane&3) + 4][col]);
                    mma_tf32(acc[j], a, b0, b1);
                }
            }
            __syncthreads();
        }
        #pragma unroll
        for (int j = 0; j < 2; ++j) {
            int col = wn*16 + j*8 + (lane&3)*2;
            #pragma unroll
            for (int half = 0; half < 2; ++half) {
                int b = wm*16 + (lane>>2) + half*8;
                float v0 = acc[j][half*2], v1 = acc[j][half*2+1];
                size_t base = (size_t)b*NN + n;
                float2 cuv = *reinterpret_cast<const float2*>(&cu_t[base*64 + col]);
                float hc0 = tanhfast(v0 + cuv.x), hc1 = tanhfast(v1 + cuv.y);
                size_t idx = base*64 + col;
                float2 rr = *reinterpret_cast<const float2*>(&g_r[idx]);
                float2 st = *reinterpret_cast<const float2*>(&g_state[idx]);
                float h0 = rr.x*st.x + (1.f-rr.x)*hc0;
                float h1 = rr.y*st.y + (1.f-rr.y)*hc1;
                *reinterpret_cast<float2*>(&g_state[idx]) = make_float2(h0, h1);
                *reinterpret_cast<float2*>(&hs[(((size_t)b*TT + t)*NN + n)*64 + col]) = make_float2(h0, h1);
            }
        }
    }
}

__global__ void __launch_bounds__(256, 2) k_recur(
        const float* __restrict__ gW, const float* __restrict__ uW,
        const float* __restrict__ cg, const float* __restrict__ cu,
        float* __restrict__ hs, int C, int Cin) {
    __shared__ float sm[SM_FLOATS];
    int tid = threadIdx.x;
    int warp = tid >> 5, lane = tid & 31;
    unsigned nbar = 0;

    // t = 0: state=0 => r = sigm(cg_r), h = (1-r)*tanh(cu)
    for (int idx = blockIdx.x*256 + tid; idx < BB*NN*64; idx += GRID_P*256) {
        int c = idx & 63;
        int n = (idx >> 6) & 511;
        int b = idx >> 15;
        size_t base = (size_t)b*NN + n;
        float r = sigm(cg[base*128 + 64 + c]);
        float hc = tanhfast(cu[base*64 + c]);
        float h = (1.f - r) * hc;
        g_state[base*64 + c] = h;
        hs[(((size_t)b*TT)*NN + n)*64 + c] = h;
    }
    gbar(++nbar);

    for (int t = 1; t < TT; ++t) {
        const float* cg_t = cg + (size_t)t*BB*NN*128;
        const float* cu_t = cu + (size_t)t*BB*NN*64;
        phase_mix(g_state, g_mixs, sm, tid, warp, lane);
        gbar(++nbar);
        phase_gate(gW, cg_t, C, Cin, sm, tid, warp, lane);
        gbar(++nbar);
        phase_mix(g_zs, g_mixzs, sm, tid, warp, lane);
        gbar(++nbar);
        phase_upd(uW, cu_t, C, Cin, hs, t, sm, tid, warp, lane);
        gbar(++nbar);
    }
}

// ---------------- precompute kernels (unchanged from round 3) ----------------

__global__ void __launch_bounds__(192) k_precomp(
        const float* __restrict__ xt, const float* __restrict__ mxt,
        const float* __restrict__ gW, const float* __restrict__ uW,
        const float* __restrict__ gb, const float* __restrict__ ub,
        float* __restrict__ cg, float* __restrict__ cu, int Cin) {
    const int C = Cin + HH;
    __shared__ float xs[64][2];
    __shared__ float ms[64][2];
    int n = blockIdx.x;
    int r0 = blockIdx.y * 64;
    int tid = threadIdx.x;
    for (int idx = tid; idx < 64*Cin; idx += 192) {
        int r = idx / Cin, c = idx - r*Cin;
        int z = r0 + r;
        xs[r][c] = xt[((size_t)z*NN + n)*Cin + c];
        int g = z*Cin + c;
        ms[r][c] = mxt[((size_t)(g>>6)*NN + n)*64 + (g&63)];
    }
    __syncthreads();
    float a[64];
    #pragma unroll
    for (int i = 0; i < 64; ++i) a[i] = 0.f;
    if (tid < 128) {
        int o = tid;
        const float* W0 = gW + (size_t)(n*2)*C*128 + o;
        const float* W1 = gW + (size_t)(n*2+1)*C*128 + o;
        for (int c = 0; c < Cin; ++c) {
            float w0 = W0[c*128], w1 = W1[c*128];
            #pragma unroll
            for (int r = 0; r < 64; ++r) a[r] += xs[r][c]*w0 + ms[r][c]*w1;
        }
        float bias = gb[n*128 + o];
        for (int r = 0; r < 64; ++r) {
            int z = r0 + r; int b = z / 12, t = z - b*12;
            cg[(((size_t)t*BB + b)*NN + n)*128 + o] = a[r] + bias;
        }
    } else {
        int o = tid - 128;
        const float* W0 = uW + (size_t)(n*2)*C*64 + o;
        const float* W1 = uW + (size_t)(n*2+1)*C*64 + o;
        for (int c = 0; c < Cin; ++c) {
            float w0 = W0[c*64], w1 = W1[c*64];
            #pragma unroll
            for (int r = 0; r < 64; ++r) a[r] += xs[r][c]*w0 + ms[r][c]*w1;
        }
        float bias = ub[n*64 + o];
        for (int r = 0; r < 64; ++r) {
            int z = r0 + r; int b = z / 12, t = z - b*12;
            cu[(((size_t)t*BB + b)*NN + n)*64 + o] = a[r] + bias;
        }
    }
}

__global__ void __launch_bounds__(256) k_precomp_mma(
        const float* __restrict__ xt, const float* __restrict__ mxt,
        const float* __restrict__ gW, const float* __restrict__ uW,
        const float* __restrict__ gb, const float* __restrict__ ub,
        float* __restrict__ cg, float* __restrict__ cu) {
    const int C = 128;
    __shared__ float As[128][36];
    __shared__ float Bs[32][200];
    int n = blockIdx.x;
    int m0 = blockIdx.y * 128;
    int tid = threadIdx.x;
    int warp = tid >> 5, lane = tid & 31;
    int wm = warp >> 1, wn = warp & 1;
    float acc[2][12][4];
    #pragma unroll
    for (int mt=0;mt<2;++mt) for (int j=0;j<12;++j) for (int q=0;q<4;++q) acc[mt][j][q]=0.f;

    for (int kc = 0; kc < 128; kc += 32) {
        #pragma unroll
        for (int i = 0; i < 4; ++i) {
            int idx = tid + i*256;
            int row = idx >> 3;
            int c4 = (idx & 7) * 4;
            int z = m0 + row;
            int k = kc + c4;
            float4 v = (k < 64)
                ? *reinterpret_cast<const float4*>(&xt[((size_t)z*NN + n)*64 + k])
                : *reinterpret_cast<const float4*>(&mxt[((size_t)z*NN + n)*64 + k - 64]);
            float4 w; w.x=to_tf32(v.x); w.y=to_tf32(v.y); w.z=to_tf32(v.z); w.w=to_tf32(v.w);
            *reinterpret_cast<float4*>(&As[row][c4]) = w;
        }
        #pragma unroll
        for (int i = 0; i < 6; ++i) {
            int idx = tid + i*256;
            int krow = idx / 48;
            int c4 = (idx % 48) * 4;
            int kk = kc + krow;
            const float* src = (c4 < 128)
                ? gW + ((size_t)(2*n + (kk>=64))*C + (kk&63))*128 + c4
                : uW + ((size_t)(2*n + (kk>=64))*C + (kk&63))*64 + (c4 - 128);
            float4 v = *reinterpret_cast<const float4*>(src);
            float4 w; w.x=to_tf32(v.x); w.y=to_tf32(v.y); w.z=to_tf32(v.z); w.w=to_tf32(v.w);
            *reinterpret_cast<float4*>(&Bs[krow][c4]) = w;
        }
        __syncthreads();
        #pragma unroll
        for (int k8 = 0; k8 < 32; k8 += 8) {
            uint32_t a[2][4];
            int ac = k8 + (lane&3);
            #pragma unroll
            for (int mt = 0; mt < 2; ++mt) {
                int rr = wm*32 + mt*16 + (lane>>2);
                a[mt][0] = __float_as_uint(As[rr][ac]);
                a[mt][1] = __float_as_uint(As[rr+8][ac]);
                a[mt][2] = __float_as_uint(As[rr][ac+4]);
                a[mt][3] = __float_as_uint(As[rr+8][ac+4]);
            }
            #pragma unroll
            for (int j = 0; j < 12; ++j) {
                int col = wn*96 + j*8 + (lane>>2);
                uint32_t b0 = __float_as_uint(Bs[k8 + (lane&3)][col]);
                uint32_t b1 = __float_as_uint(Bs[k8 + (lane&3) + 4][col]);
                mma_tf32(acc[0][j], a[0], b0, b1);
                mma_tf32(acc[1][j], a[1], b0, b1);
            }
        }
        __syncthreads();
    }
    #pragma unroll
    for (int mt = 0; mt < 2; ++mt) {
        #pragma unroll
        for (int j = 0; j < 12; ++j) {
            int col = wn*96 + j*8 + (lane&3)*2;
            #pragma unroll
            for (int half = 0; half < 2; ++half) {
                int z = m0 + wm*32 + mt*16 + (lane>>2) + half*8;
                int b = z / 12, t = z - b*12;
                float v0 = acc[mt][j][half*2], v1 = acc[mt][j][half*2+1];
                if (col < 128) {
                    float2 bb = *reinterpret_cast<const float2*>(&gb[n*128 + col]);
                    *reinterpret_cast<float2*>(&cg[(((size_t)t*BB + b)*NN + n)*128 + col]) =
                        make_float2(v0 + bb.x, v1 + bb.y);
                } else {
                    int o = col - 128;
                    float2 bb = *reinterpret_cast<const float2*>(&ub[n*64 + o]);
                    *reinterpret_cast<float2*>(&cu[(((size_t)t*BB + b)*NN + n)*64 + o]) =
                        make_float2(v0 + bb.x, v1 + bb.y);
                }
            }
        }
    }
}

__global__ void k_hyp(const float* __restrict__ hypW, const float* __restrict__ hypb) {
    __shared__ float part[192];
    __shared__ float hlin[48];
    int n = blockIdx.x;
    int tid = threadIdx.x;
    int j = tid % 48, sl = tid / 48;
    const float* u = g_uW + (size_t)n * 16384;
    float a = 0.f;
    int i0 = sl * 4096;
    for (int i = i0; i < i0 + 4096; ++i) a += u[i] * hypW[i*48 + j];
    part[tid] = a;
    __syncthreads();
    if (tid < 48) hlin[tid] = part[tid] + part[48+tid] + part[96+tid] + part[144+tid] + hypb[tid];
    __syncthreads();
    if (tid < 12) {
        g_fs[n*TT + tid] = hlin[tid*4] + hlin[tid*4+1] + hlin[tid*4+2] + hlin[tid*4+3];
    }
}

__global__ void k_copy_last() {
    int idx = blockIdx.x*blockDim.x + threadIdx.x;
    if (idx >= BB*NN*HH) return;
    int c = idx & 63;
    int bn = idx >> 6;
    int n = bn & 511, b = bn >> 9;
    g_hv[idx] = g_hs1[(((size_t)b*TT + (TT-1))*NN + n)*64 + c];
}

__global__ void __launch_bounds__(256) k_gemm64_mma(
        const float* __restrict__ X, const float* __restrict__ W,
        const float* __restrict__ bias, float* __restrict__ Y, int relu) {
    __shared__ float Xs[128][36];
    __shared__ float Ws[32][72];
    int r0 = blockIdx.x * 128;
    int tid = threadIdx.x;
    int warp = tid >> 5, lane = tid & 31;
    float acc[8][4];
    #pragma unroll
    for (int j=0;j<8;++j) for (int q=0;q<4;++q) acc[j][q]=0.f;
    for (int kc = 0; kc < 64; kc += 32) {
        #pragma unroll
        for (int i = 0; i < 4; ++i) {
            int idx = tid + i*256;
            int row = idx >> 3;
            int c4 = (idx & 7) * 4;
            float4 v = *reinterpret_cast<const float4*>(&X[(size_t)(r0+row)*64 + kc + c4]);
            float4 w; w.x=to_tf32(v.x); w.y=to_tf32(v.y); w.z=to_tf32(v.z); w.w=to_tf32(v.w);
            *reinterpret_cast<float4*>(&Xs[row][c4]) = w;
        }
        #pragma unroll
        for (int i = 0; i < 2; ++i) {
            int idx = tid + i*256;
            int krow = idx >> 4;
            int c4 = (idx & 15) * 4;
            float4 v = *reinterpret_cast<const float4*>(&W[(size_t)(kc+krow)*64 + c4]);
            float4 w; w.x=to_tf32(v.x); w.y=to_tf32(v.y); w.z=to_tf32(v.z); w.w=to_tf32(v.w);
            *reinterpret_cast<float4*>(&Ws[krow][c4]) = w;
        }
        __syncthreads();
        #pragma unroll
        for (int k8 = 0; k8 < 32; k8 += 8) {
            uint32_t a[4];
            int ar = warp*16 + (lane>>2);
            int ac = k8 + (lane&3);
            a[0] = __float_as_uint(Xs[ar][ac]);
            a[1] = __float_as_uint(Xs[ar+8][ac]);
            a[2] = __float_as_uint(Xs[ar][ac+4]);
            a[3] = __float_as_uint(Xs[ar+8][ac+4]);
            #pragma unroll
            for (int j = 0; j < 8; ++j) {
                uint32_t b0 = __float_as_uint(Ws[k8 + (lane&3)][j*8 + (lane>>2)]);
                uint32_t b1 = __float_as_uint(Ws[k8 + (lane&3) + 4][j*8 + (lane>>2)]);
                mma_tf32(acc[j], a, b0, b1);
            }
        }
        __syncthreads();
    }
    int row = r0 + warp*16 + (lane>>2);
    #pragma unroll
    for (int j = 0; j < 8; ++j) {
        int col = j*8 + (lane&3)*2;
        float b0 = bias ? bias[col] : 0.f, b1 = bias ? bias[col+1] : 0.f;
        float v0 = acc[j][0] + b0, v1 = acc[j][1] + b1;
        float v2 = acc[j][2] + b0, v3 = acc[j][3] + b1;
        if (relu) { v0=fmaxf(v0,0.f); v1=fmaxf(v1,0.f); v2=fmaxf(v2,0.f); v3=fmaxf(v3,0.f); }
        *reinterpret_cast<float2*>(&Y[(size_t)row*64 + col]) = make_float2(v0, v1);
        *reinterpret_cast<float2*>(&Y[(size_t)(row+8)*64 + col]) = make_float2(v2, v3);
    }
}

__global__ void k_attn(const float* __restrict__ bv) {
    __shared__ float qs[12][64], ks[12][64], vs[12][64];
    __shared__ float sc[2][12][12];
    int bn = blockIdx.x;
    int b = bn >> 9, n = bn & 511;
    int tid = threadIdx.x;
    for (int idx = tid; idx < 12*64; idx += 128) {
        int t = idx >> 6, c = idx & 63;
        size_t g = (((size_t)b*TT + t)*NN + n)*HH + c;
        qs[t][c] = g_q[g];
        ks[t][c] = g_k[g];
        vs[t][c] = g_fs[n*TT + t] * g_v[((size_t)b*NN + n)*64 + c] + bv[c];
    }
    __syncthreads();
    for (int idx = tid; idx < 288; idx += 128) {
        int h = idx / 144, rem = idx - h*144;
        int t = rem / 12, s = rem - t*12;
        float d = 0.f;
        #pragma unroll
        for (int k = 0; k < 32; ++k) d += qs[t][h*32 + k] * ks[s][h*32 + k];
        sc[h][t][s] = d * 0.17677669529663687f;
    }
    __syncthreads();
    if (tid < 24) {
        int h = tid / 12, t = tid - h*12;
        float mx = -1e30f;
        #pragma unroll
        for (int s = 0; s < 12; ++s) mx = fmaxf(mx, sc[h][t][s]);
        float sum = 0.f;
        #pragma unroll
        for (int s = 0; s < 12; ++s) { float e = __expf(sc[h][t][s] - mx); sc[h][t][s] = e; sum += e; }
        float inv = 1.f / sum;
        #pragma unroll
        for (int s = 0; s < 12; ++s) sc[h][t][s] *= inv;
    }
    __syncthreads();
    for (int idx = tid; idx < 768; idx += 128) {
        int h = idx / 384, rem = idx - h*384;
        int t = rem >> 5, d = rem & 31;
        float a = 0.f;
        #pragma unroll
        for (int s = 0; s < 12; ++s) a += sc[h][t][s] * vs[s][h*32 + d];
        g_o[(((size_t)b*TT + t)*NN + n)*HH + h*32 + d] = a;
    }
}

__global__ void __launch_bounds__(256) k_lnres_w(
        const float* __restrict__ A, const float* __restrict__ Bv,
        const float* __restrict__ g, const float* __restrict__ be,
        float* __restrict__ Y) {
    int lane = threadIdx.x & 31;
    size_t row = (size_t)blockIdx.x * 8 + (threadIdx.x >> 5);
    int c = lane * 2;
    float2 a = *reinterpret_cast<const float2*>(&A[row*64 + c]);
    float2 b2 = *reinterpret_cast<const float2*>(&Bv[row*64 + c]);
    float x0 = a.x + b2.x, x1 = a.y + b2.y;
    float s = x0 + x1, sq = x0*x0 + x1*x1;
    #pragma unroll
    for (int o = 16; o > 0; o >>= 1) {
        s  += __shfl_xor_sync(0xffffffffu, s, o);
        sq += __shfl_xor_sync(0xffffffffu, sq, o);
    }
    float mu = s * (1.f/64.f);
    float var = sq * (1.f/64.f) - mu*mu;
    float rstd = rsqrtf(var + 1e-5f);
    float y0 = (x0 - mu) * rstd * g[c] + be[c];
    float y1 = (x1 - mu) * rstd * g[c+1] + be[c+1];
    *reinterpret_cast<float2*>(&Y[row*64 + c]) = make_float2(y0, y1);
}

__global__ void __launch_bounds__(256) k_fc_w(
        const float* __restrict__ X, const float* __restrict__ w,
        const float* __restrict__ bp, float* __restrict__ Y) {
    int lane = threadIdx.x & 31;
    size_t row = (size_t)blockIdx.x * 8 + (threadIdx.x >> 5);
    int c = lane * 2;
    float2 x = *reinterpret_cast<const float2*>(&X[row*64 + c]);
    float s = x.x * w[c] + x.y * w[c+1];
    #pragma unroll
    for (int o = 16; o > 0; o >>= 1) s += __shfl_xor_sync(0xffffffffu, s, o);
    if (lane == 0) Y[row] = s + bp[0];
}

// ---------------- host ----------------

extern "C" void kernel_launch(void* const* d_in, const int* in_sizes, int n_in,
                              void* d_out, int out_size) {
    const float* src  = (const float*)d_in[0];
    const float* emb  = (const float*)d_in[2];
    const float* gwp0 = (const float*)d_in[3];
    const float* gbp0 = (const float*)d_in[4];
    const float* uwp0 = (const float*)d_in[5];
    const float* ubp0 = (const float*)d_in[6];
    const float* gwp1 = (const float*)d_in[7];
    const float* gbp1 = (const float*)d_in[8];
    const float* uwp1 = (const float*)d_in[9];
    const float* ubp1 = (const float*)d_in[10];
    const float* hypW = (const float*)d_in[11];
    const float* hypb = (const float*)d_in[12];

    const float *Wq,*Wk,*Wv,*ffW1,*ffW2,*bq,*bk,*bv,*ffb1,*ffb2,*ln1g,*ln1b,*ln2g,*ln2b,*fcW,*fcb;
    if (n_in > 14 && in_sizes[14] == 64) {
        Wq  = (const float*)d_in[13]; bq  = (const float*)d_in[14];
        Wk  = (const float*)d_in[15]; bk  = (const float*)d_in[16];
        Wv  = (const float*)d_in[17]; bv  = (const float*)d_in[18];
        ln1g= (const float*)d_in[19]; ln1b= (const float*)d_in[20];
        ffW1= (const float*)d_in[21]; ffb1= (const float*)d_in[22];
        ffW2= (const float*)d_in[23]; ffb2= (const float*)d_in[24];
        ln2g= (const float*)d_in[25]; ln2b= (const float*)d_in[26];
        fcW = (const float*)d_in[27]; fcb = (const float*)d_in[28];
    } else {
        Wq  = (const float*)d_in[13]; Wk  = (const float*)d_in[14];
        Wv  = (const float*)d_in[15]; ffW1= (const float*)d_in[16];
        ffW2= (const float*)d_in[17]; bq  = (const float*)d_in[18];
        bk  = (const float*)d_in[19]; bv  = (const float*)d_in[20];
        ffb1= (const float*)d_in[21]; ffb2= (const float*)d_in[22];
        ln1g= (const float*)d_in[23]; ln1b= (const float*)d_in[24];
        ln2g= (const float*)d_in[25]; ln2b= (const float*)d_in[26];
        fcW = (const float*)d_in[27]; fcb = (const float*)d_in[28];
    }

    float *p_gW,*p_gb,*p_uW,*p_ub,*p_cg,*p_cu,*p_mxt,*p_xt0t;
    float *p_hs0,*p_hs1,*p_hv,*p_q,*p_k,*p_v,*p_o,*p_val,*p_ff1,*p_ffo,*p_out2;
    cudaGetSymbolAddress((void**)&p_gW, g_gW);
    cudaGetSymbolAddress((void**)&p_gb, g_gb);
    cudaGetSymbolAddress((void**)&p_uW, g_uW);
    cudaGetSymbolAddress((void**)&p_ub, g_ub);
    cudaGetSymbolAddress((void**)&p_cg, g_cg);
    cudaGetSymbolAddress((void**)&p_cu, g_cu);
    cudaGetSymbolAddress((void**)&p_mxt, g_mxt);
    cudaGetSymbolAddress((void**)&p_xt0t, g_xt0t);
    cudaGetSymbolAddress((void**)&p_hs0, g_hs0);
    cudaGetSymbolAddress((void**)&p_hs1, g_hs1);
    cudaGetSymbolAddress((void**)&p_hv, g_hv);
    cudaGetSymbolAddress((void**)&p_q, g_q);
    cudaGetSymbolAddress((void**)&p_k, g_k);
    cudaGetSymbolAddress((void**)&p_v, g_v);
    cudaGetSymbolAddress((void**)&p_o, g_o);
    cudaGetSymbolAddress((void**)&p_val, g_val);
    cudaGetSymbolAddress((void**)&p_ff1, g_ff1);
    cudaGetSymbolAddress((void**)&p_ffo, g_ffo);
    cudaGetSymbolAddress((void**)&p_out2, g_out2);

    k_adj<<<NN, 256>>>(emb);

    for (int layer = 0; layer < 2; ++layer) {
        int Cin = (layer == 0) ? 2 : 64;
        int C = Cin + HH;
        float* hs_out;
        if (layer == 0) {
            int s;
            s = 2*C*128/4; k_matpool4<<<(NN*s+255)/256, 256>>>(emb, gwp0, p_gW, s);
            s = 128/4;     k_matpool4<<<(NN*s+255)/256, 256>>>(emb, gbp0, p_gb, s);
            s = 2*C*64/4;  k_matpool4<<<(NN*s+255)/256, 256>>>(emb, uwp0, p_uW, s);
            s = 64/4;      k_matpool4<<<(NN*s+255)/256, 256>>>(emb, ubp0, p_ub, s);
            k_transp0<<<(ZT*NN*2 + 255)/256, 256>>>(src, p_xt0t);
            k_mix64<<<dim3(8, (ZT*2)/64), 128>>>(p_xt0t, p_mxt);
            k_precomp<<<dim3(NN, 6), 192>>>(src, p_mxt, p_gW, p_uW, p_gb, p_ub, p_cg, p_cu, Cin);
            hs_out = p_hs0;
        } else {
            int s;
            s = 2*C*128/4; k_matpool4<<<(NN*s+255)/256, 256>>>(emb, gwp1, p_gW, s);
            s = 128/4;     k_matpool4<<<(NN*s+255)/256, 256>>>(emb, gbp1, p_gb, s);
            s = 2*C*64/4;  k_matpool4<<<(NN*s+255)/256, 256>>>(emb, uwp1, p_uW, s);
            s = 64/4;      k_matpool4<<<(NN*s+255)/256, 256>>>(emb, ubp1, p_ub, s);
            k_mix64<<<dim3(8, ZT), 128>>>(p_hs0, p_mxt);
            k_precomp_mma<<<dim3(NN, 3), 256>>>(p_hs0, p_mxt, p_gW, p_uW, p_gb, p_ub, p_cg, p_cu);
            hs_out = p_hs1;
        }
        k_reset_bar<<<1, 1>>>();
        k_recur<<<GRID_P, 256>>>(p_gW, p_uW, p_cg, p_cu, hs_out, C, Cin);
    }

    k_hyp<<<NN, 192>>>(hypW, hypb);
    k_copy_last<<<(BB*NN*HH + 255)/256, 256>>>();

    k_gemm64_mma<<<BTN/128, 256>>>(p_hs1, Wq, bq, p_q, 0);
    k_gemm64_mma<<<BTN/128, 256>>>(p_hs1, Wk, bk, p_k, 0);
    k_gemm64_mma<<<BB*NN/128, 256>>>(p_hv, Wv, nullptr, p_v, 0);

    k_attn<<<BB*NN, 128>>>(bv);

    k_lnres_w<<<BTN/8, 256>>>(p_o, p_hs1, ln1g, ln1b, p_val);
    k_gemm64_mma<<<BTN/128, 256>>>(p_val, ffW1, ffb1, p_ff1, 1);
    k_gemm64_mma<<<BTN/128, 256>>>(p_ff1, ffW2, ffb2, p_ffo, 0);
    k_lnres_w<<<BTN/8, 256>>>(p_ffo, p_val, ln2g, ln2b, p_out2);
    k_fc_w<<<BTN/8, 256>>>(p_out2, fcW, fcb, (float*)d_out);
}

// round 5
// speedup vs baseline: 3.0317x; 1.0021x over previous
#include <cuda_runtime.h>
#include <math.h>
#include <stdint.h>

#define BB 32
#define TT 12
#define NN 512
#define HH 64
#define EE 16
#define BTN (BB*TT*NN)
#define BTNH (BTN*HH)
#define ZT (BB*TT)          // 384
#define GRID_P 256          // persistent grid (<= 296 co-resident guaranteed)

// ---------------- scratch (device globals) ----------------
__device__ float g_adj[NN*NN];
__device__ float g_gW[NN*2*128*128];
__device__ float g_gb[NN*128];
__device__ float g_uW[NN*2*128*64];
__device__ float g_ub[NN*64];
__device__ float g_state[BB*NN*HH];
__device__ float g_mixs[BB*NN*HH];
__device__ float g_zs[BB*NN*HH];
__device__ float g_mixzs[BB*NN*HH];
__device__ float g_r[BB*NN*HH];
__device__ float g_cg[TT*BB*NN*128];
__device__ float g_cu[TT*BB*NN*64];
__device__ float g_mxt[ZT*NN*64];
__device__ float g_xt0t[TT*NN*64];
__device__ float g_hs0[BTNH];
__device__ float g_hs1[BTNH];
__device__ float g_fs[NN*TT];
__device__ float g_hv[BB*NN*HH];
__device__ float g_q[BTNH];
__device__ float g_k[BTNH];
__device__ float g_v[BB*NN*HH];
__device__ float g_o[BTNH];
__device__ float g_val[BTNH];
__device__ float g_ff1[BTNH];
__device__ float g_ffo[BTNH];
__device__ float g_out2[BTNH];
__device__ unsigned g_bar;

// ---------------- helpers ----------------

__device__ __forceinline__ float to_tf32(float x) {
    uint32_t u;
    asm("cvt.rna.tf32.f32 %0, %1;" : "=r"(u) : "f"(x));
    return __uint_as_float(u);
}
__device__ __forceinline__ uint32_t cvu(float x) {
    uint32_t u;
    asm("cvt.rna.tf32.f32 %0, %1;" : "=r"(u) : "f"(x));
    return u;
}

__device__ __forceinline__ void mma_tf32(float* c, const uint32_t* a, uint32_t b0, uint32_t b1) {
    asm volatile("mma.sync.aligned.m16n8k8.row.col.f32.tf32.tf32.f32 "
        "{%0,%1,%2,%3}, {%4,%5,%6,%7}, {%8,%9}, {%0,%1,%2,%3};"
        : "+f"(c[0]), "+f"(c[1]), "+f"(c[2]), "+f"(c[3])
        : "r"(a[0]), "r"(a[1]), "r"(a[2]), "r"(a[3]), "r"(b0), "r"(b1));
}

__device__ __forceinline__ float sigm(float v) { return 1.f / (1.f + __expf(-v)); }
__device__ __forceinline__ float tanhfast(float v) { return 1.f - 2.f / (__expf(2.f*v) + 1.f); }

// software grid barrier (all GRID_P blocks co-resident by construction)
__device__ __forceinline__ void gbar(unsigned n) {
    __syncthreads();
    if (threadIdx.x == 0) {
        __threadfence();
        atomicAdd(&g_bar, 1u);
        unsigned target = n * GRID_P;
        volatile unsigned* p = &g_bar;
        while (*p < target) __nanosleep(64);
        __threadfence();
    }
    __syncthreads();
}

// ---------------- small kernels ----------------

__global__ void k_reset_bar() { g_bar = 0u; }

__global__ void k_adj(const float* __restrict__ emb) {
    __shared__ float semb[NN*EE];
    __shared__ float row[NN];
    __shared__ float red[256];
    int n = blockIdx.x;
    for (int i = threadIdx.x; i < NN*EE; i += blockDim.x) semb[i] = emb[i];
    __syncthreads();
    float lmax = -1e30f;
    for (int m = threadIdx.x; m < NN; m += blockDim.x) {
        float s = 0.f;
        #pragma unroll
        for (int e = 0; e < EE; ++e) s += semb[n*EE+e] * semb[m*EE+e];
        s = fmaxf(s, 0.f);
        row[m] = s;
        lmax = fmaxf(lmax, s);
    }
    red[threadIdx.x] = lmax; __syncthreads();
    for (int s = 128; s > 0; s >>= 1) {
        if (threadIdx.x < s) red[threadIdx.x] = fmaxf(red[threadIdx.x], red[threadIdx.x+s]);
        __syncthreads();
    }
    float mx = red[0];
    __syncthreads();
    float lsum = 0.f;
    for (int m = threadIdx.x; m < NN; m += blockDim.x) {
        float v = expf(row[m] - mx);
        row[m] = v; lsum += v;
    }
    red[threadIdx.x] = lsum; __syncthreads();
    for (int s = 128; s > 0; s >>= 1) {
        if (threadIdx.x < s) red[threadIdx.x] += red[threadIdx.x+s];
        __syncthreads();
    }
    float inv = 1.f / red[0];
    for (int m = threadIdx.x; m < NN; m += blockDim.x) g_adj[n*NN + m] = row[m] * inv;
}

__global__ void k_matpool4(const float* __restrict__ emb, const float* __restrict__ pool,
                           float* __restrict__ out, int S4) {
    int idx = blockIdx.x*blockDim.x + threadIdx.x;
    if (idx >= NN * S4) return;
    int n = idx / S4, i = idx - n*S4;
    float4 a = make_float4(0.f,0.f,0.f,0.f);
    const float* e = emb + n*EE;
    const float4* p4 = (const float4*)pool;
    #pragma unroll
    for (int k = 0; k < EE; ++k) {
        float w = e[k];
        float4 p = p4[(size_t)k*S4 + i];
        a.x += w*p.x; a.y += w*p.y; a.z += w*p.z; a.w += w*p.w;
    }
    ((float4*)out)[idx] = a;
}

__global__ void k_transp0(const float* __restrict__ src, float* __restrict__ xt0) {
    int idx = blockIdx.x*blockDim.x + threadIdx.x;
    if (idx >= ZT*NN*2) return;
    int c = idx & 1, m = (idx >> 1) & 511, z = idx >> 10;
    int g = z*2 + c;
    xt0[((size_t)(g>>6)*NN + m)*64 + (g&63)] = src[idx];
}

// standalone batched mix (precompute): Y[z][n][c] = sum_m adj[n][m] X[z][m][c]
__global__ void __launch_bounds__(128) k_mix64(const float* __restrict__ X, float* __restrict__ Y) {
    __shared__ float As[64][36];
    __shared__ float Xs[32][72];
    int z = blockIdx.y;
    int r0 = blockIdx.x * 64;
    int tid = threadIdx.x;
    int warp = tid >> 5, lane = tid & 31;
    const float* Xb = X + (size_t)z * (NN*64);
    float* Yb = Y + (size_t)z * (NN*64);
    float acc[8][4];
    #pragma unroll
    for (int j = 0; j < 8; ++j)
        #pragma unroll
        for (int q = 0; q < 4; ++q) acc[j][q] = 0.f;

    for (int kc = 0; kc < NN; kc += 32) {
        #pragma unroll
        for (int i = 0; i < 4; ++i) {
            int idx = tid + i*128;
            int row = idx >> 3;
            int c4 = (idx & 7) * 4;
            float4 v = *reinterpret_cast<const float4*>(&g_adj[(size_t)(r0+row)*NN + kc + c4]);
            float4 w; w.x=to_tf32(v.x); w.y=to_tf32(v.y); w.z=to_tf32(v.z); w.w=to_tf32(v.w);
            *reinterpret_cast<float4*>(&As[row][c4]) = w;
        }
        #pragma unroll
        for (int i = 0; i < 4; ++i) {
            int idx = tid + i*128;
            int row = idx >> 4;
            int c4 = (idx & 15) * 4;
            float4 v = *reinterpret_cast<const float4*>(&Xb[(size_t)(kc+row)*64 + c4]);
            float4 w; w.x=to_tf32(v.x); w.y=to_tf32(v.y); w.z=to_tf32(v.z); w.w=to_tf32(v.w);
            *reinterpret_cast<float4*>(&Xs[row][c4]) = w;
        }
        __syncthreads();
        #pragma unroll
        for (int k8 = 0; k8 < 32; k8 += 8) {
            uint32_t a[4];
            int ar = warp*16 + (lane>>2);
            int ac = k8 + (lane&3);
            a[0] = __float_as_uint(As[ar][ac]);
            a[1] = __float_as_uint(As[ar+8][ac]);
            a[2] = __float_as_uint(As[ar][ac+4]);
            a[3] = __float_as_uint(As[ar+8][ac+4]);
            #pragma unroll
            for (int j = 0; j < 8; ++j) {
                uint32_t b0 = __float_as_uint(Xs[k8 + (lane&3)][j*8 + (lane>>2)]);
                uint32_t b1 = __float_as_uint(Xs[k8 + (lane&3) + 4][j*8 + (lane>>2)]);
                mma_tf32(acc[j], a, b0, b1);
            }
        }
        __syncthreads();
    }
    int row = r0 + warp*16 + (lane>>2);
    #pragma unroll
    for (int j = 0; j < 8; ++j) {
        int col = j*8 + (lane&3)*2;
        *reinterpret_cast<float2*>(&Yb[(size_t)row*64 + col]) = make_float2(acc[j][0], acc[j][1]);
        *reinterpret_cast<float2*>(&Yb[(size_t)(row+8)*64 + col]) = make_float2(acc[j][2], acc[j][3]);
    }
}

// ---------------- persistent recurrence kernel ----------------

// shared scratch: max phase usage = gate (32*132 + 32*136 = 8576 floats)
#define SM_FLOATS 8704

__device__ __forceinline__ void phase_mix(const float* __restrict__ X, float* __restrict__ Y,
                                          float* sm, int tid, int warp, int lane) {
    float (*As)[36] = (float(*)[36])sm;            // 64 x 36
    float (*Xs)[72] = (float(*)[72])(sm + 2304);   // 32 x 72
    int tile = blockIdx.x;          // 256 tiles = 8 rowtiles x 32 z
    int z  = tile >> 3;
    int r0 = (tile & 7) * 64;
    const float* Xb = X + (size_t)z * (NN*64);
    float* Yb = Y + (size_t)z * (NN*64);
    int wm = warp >> 1, wn = warp & 1;
    float acc[4][4];
    #pragma unroll
    for (int j=0;j<4;++j) for (int q=0;q<4;++q) acc[j][q]=0.f;

    for (int kc = 0; kc < NN; kc += 32) {
        #pragma unroll
        for (int i = 0; i < 2; ++i) {
            int idx = tid + i*256;
            int row = idx >> 3;
            int c4 = (idx & 7) * 4;
            float4 v = *reinterpret_cast<const float4*>(&g_adj[(size_t)(r0+row)*NN + kc + c4]);
            float4 w; w.x=to_tf32(v.x); w.y=to_tf32(v.y); w.z=to_tf32(v.z); w.w=to_tf32(v.w);
            *reinterpret_cast<float4*>(&As[row][c4]) = w;
        }
        #pragma unroll
        for (int i = 0; i < 2; ++i) {
            int idx = tid + i*256;
            int row = idx >> 4;
            int c4 = (idx & 15) * 4;
            float4 v = *reinterpret_cast<const float4*>(&Xb[(size_t)(kc+row)*64 + c4]);
            float4 w; w.x=to_tf32(v.x); w.y=to_tf32(v.y); w.z=to_tf32(v.z); w.w=to_tf32(v.w);
            *reinterpret_cast<float4*>(&Xs[row][c4]) = w;
        }
        __syncthreads();
        #pragma unroll
        for (int k8 = 0; k8 < 32; k8 += 8) {
            uint32_t a[4];
            int ar = wm*16 + (lane>>2);
            int ac = k8 + (lane&3);
            a[0] = __float_as_uint(As[ar][ac]);
            a[1] = __float_as_uint(As[ar+8][ac]);
            a[2] = __float_as_uint(As[ar][ac+4]);
            a[3] = __float_as_uint(As[ar+8][ac+4]);
            #pragma unroll
            for (int j = 0; j < 4; ++j) {
                int col = wn*32 + j*8 + (lane>>2);
                uint32_t b0 = __float_as_uint(Xs[k8 + (lane&3)][col]);
                uint32_t b1 = __float_as_uint(Xs[k8 + (lane&3) + 4][col]);
                mma_tf32(acc[j], a, b0, b1);
            }
        }
        __syncthreads();
    }
    int row = r0 + wm*16 + (lane>>2);
    #pragma unroll
    for (int j = 0; j < 4; ++j) {
        int col = wn*32 + j*8 + (lane&3)*2;
        *reinterpret_cast<float2*>(&Yb[(size_t)row*64 + col]) = make_float2(acc[j][0], acc[j][1]);
        *reinterpret_cast<float2*>(&Yb[(size_t)(row+8)*64 + col]) = make_float2(acc[j][2], acc[j][3]);
    }
}

__device__ __forceinline__ void phase_gate(const float* __restrict__ gW, const float* __restrict__ cg_t,
                                           int C, int Cin, float* sm, int tid, int warp, int lane) {
    float (*As)[132] = (float(*)[132])sm;           // 32 x 132
    float (*Bs)[136] = (float(*)[136])(sm + 4224);  // 32 x 136
    int wm = warp >> 2, wn = warp & 3;
    for (int n = blockIdx.x; n < NN; n += GRID_P) {
        __syncthreads();
        #pragma unroll
        for (int i = 0; i < 4; ++i) {
            int idx = tid + i*256;
            int row = idx >> 5;
            int c4 = (idx & 31) * 4;
            float4 v = (c4 < 64)
                ? *reinterpret_cast<const float4*>(&g_state[((size_t)row*NN + n)*64 + c4])
                : *reinterpret_cast<const float4*>(&g_mixs[((size_t)row*NN + n)*64 + c4 - 64]);
            *reinterpret_cast<float4*>(&As[row][c4]) = v;
        }
        float acc[4][4];
        #pragma unroll
        for (int j=0;j<4;++j) for (int q=0;q<4;++q) acc[j][q]=0.f;
        for (int kc = 0; kc < 128; kc += 32) {
            #pragma unroll
            for (int i = 0; i < 4; ++i) {
                int idx = tid + i*256;
                int krow = idx >> 5;
                int c4 = (idx & 31) * 4;
                int kk = kc + krow;
                const float* src = gW + ((size_t)(2*n + (kk>=64))*C + Cin + (kk&63))*128 + c4;
                float4 v = *reinterpret_cast<const float4*>(src);
                float4 w; w.x=to_tf32(v.x); w.y=to_tf32(v.y); w.z=to_tf32(v.z); w.w=to_tf32(v.w);
                *reinterpret_cast<float4*>(&Bs[krow][c4]) = w;
            }
            __syncthreads();
            #pragma unroll
            for (int k8 = 0; k8 < 32; k8 += 8) {
                int ar = wm*16 + (lane>>2);
                int ac = kc + k8 + (lane&3);
                uint32_t a[4];
                a[0] = cvu(As[ar][ac]);
                a[1] = cvu(As[ar+8][ac]);
                a[2] = cvu(As[ar][ac+4]);
                a[3] = cvu(As[ar+8][ac+4]);
                #pragma unroll
                for (int j = 0; j < 4; ++j) {
                    int col = wn*32 + j*8 + (lane>>2);
                    uint32_t b0 = __float_as_uint(Bs[k8 + (lane&3)][col]);
                    uint32_t b1 = __float_as_uint(Bs[k8 + (lane&3) + 4][col]);
                    mma_tf32(acc[j], a, b0, b1);
                }
            }
            __syncthreads();
        }
        #pragma unroll
        for (int j = 0; j < 4; ++j) {
            int col = wn*32 + j*8 + (lane&3)*2;
            #pragma unroll
            for (int half = 0; half < 2; ++half) {
                int b = wm*16 + (lane>>2) + half*8;
                float v0 = acc[j][half*2], v1 = acc[j][half*2+1];
                size_t base = (size_t)b*NN + n;
                float2 cgv = *reinterpret_cast<const float2*>(&cg_t[base*128 + col]);
                v0 += cgv.x; v1 += cgv.y;
                if (col < 64) {
                    *reinterpret_cast<float2*>(&g_zs[base*64 + col]) =
                        make_float2(sigm(v0) * As[b][col], sigm(v1) * As[b][col+1]);
                } else {
                    *reinterpret_cast<float2*>(&g_r[base*64 + col - 64]) =
                        make_float2(sigm(v0), sigm(v1));
                }
            }
        }
    }
}

__device__ __forceinline__ void phase_upd(const float* __restrict__ uW, const float* __restrict__ cu_t,
                                          int C, int Cin, float* __restrict__ hs, int t,
                                          float* sm, int tid, int warp, int lane) {
    float (*As)[132] = (float(*)[132])sm;
    float (*Bs)[72]  = (float(*)[72])(sm + 4224);
    int wm = warp >> 2, wn = warp & 3;
    for (int n = blockIdx.x; n < NN; n += GRID_P) {
        __syncthreads();
        #pragma unroll
        for (int i = 0; i < 4; ++i) {
            int idx = tid + i*256;
            int row = idx >> 5;
            int c4 = (idx & 31) * 4;
            float4 v = (c4 < 64)
                ? *reinterpret_cast<const float4*>(&g_zs[((size_t)row*NN + n)*64 + c4])
                : *reinterpret_cast<const float4*>(&g_mixzs[((size_t)row*NN + n)*64 + c4 - 64]);
            *reinterpret_cast<float4*>(&As[row][c4]) = v;
        }
        float acc[2][4];
        #pragma unroll
        for (int j=0;j<2;++j) for (int q=0;q<4;++q) acc[j][q]=0.f;
        for (int kc = 0; kc < 128; kc += 32) {
            #pragma unroll
            for (int i = 0; i < 2; ++i) {
                int idx = tid + i*256;
                int krow = idx >> 4;
                int c4 = (idx & 15) * 4;
                int kk = kc + krow;
                const float* src = uW + ((size_t)(2*n + (kk>=64))*C + Cin + (kk&63))*64 + c4;
                float4 v = *reinterpret_cast<const float4*>(src);
                float4 w; w.x=to_tf32(v.x); w.y=to_tf32(v.y); w.z=to_tf32(v.z); w.w=to_tf32(v.w);
                *reinterpret_cast<float4*>(&Bs[krow][c4]) = w;
            }
            __syncthreads();
            #pragma unroll
            for (int k8 = 0; k8 < 32; k8 += 8) {
                int ar = wm*16 + (lane>>2);
                int ac = kc + k8 + (lane&3);
                uint32_t a[4];
                a[0] = cvu(As[ar][ac]);
                a[1] = cvu(As[ar+8][ac]);
                a[2] = cvu(As[ar][ac+4]);
                a[3] = cvu(As[ar+8][ac+4]);
                #pragma unroll
                for (int j = 0; j < 2; ++j) {
                    int col = wn*16 + j*8 + (lane>>2);
                    uint32_t b0 = __float_as_uint(Bs[k8 + (lane&3)][col]);
                    uint32_t b1 = __float_as_uint(Bs[k8 + (lane&3) + 4][col]);
                    mma_tf32(acc[j], a, b0, b1);
                }
            }
            __syncthreads();
        }
        #pragma unroll
        for (int j = 0; j < 2; ++j) {
            int col = wn*16 + j*8 + (lane&3)*2;
            #pragma unroll
            for (int half = 0; half < 2; ++half) {
                int b = wm*16 + (lane>>2) + half*8;
                float v0 = acc[j][half*2], v1 = acc[j][half*2+1];
                size_t base = (size_t)b*NN + n;
                float2 cuv = *reinterpret_cast<const float2*>(&cu_t[base*64 + col]);
                float hc0 = tanhfast(v0 + cuv.x), hc1 = tanhfast(v1 + cuv.y);
                size_t idx = base*64 + col;
                float2 rr = *reinterpret_cast<const float2*>(&g_r[idx]);
                float2 st = *reinterpret_cast<const float2*>(&g_state[idx]);
                float h0 = rr.x*st.x + (1.f-rr.x)*hc0;
                float h1 = rr.y*st.y + (1.f-rr.y)*hc1;
                *reinterpret_cast<float2*>(&g_state[idx]) = make_float2(h0, h1);
                *reinterpret_cast<float2*>(&hs[(((size_t)b*TT + t)*NN + n)*64 + col]) = make_float2(h0, h1);
            }
        }
    }
}

__global__ void __launch_bounds__(256, 2) k_recur(
        const float* __restrict__ gW, const float* __restrict__ uW,
        const float* __restrict__ cg, const float* __restrict__ cu,
        float* __restrict__ hs, int C, int Cin) {
    __shared__ float sm[SM_FLOATS];
    int tid = threadIdx.x;
    int warp = tid >> 5, lane = tid & 31;
    unsigned nbar = 0;

    // t = 0: state=0 => r = sigm(cg_r), h = (1-r)*tanh(cu)
    for (int idx = blockIdx.x*256 + tid; idx < BB*NN*64; idx += GRID_P*256) {
        int c = idx & 63;
        int n = (idx >> 6) & 511;
        int b = idx >> 15;
        size_t base = (size_t)b*NN + n;
        float r = sigm(cg[base*128 + 64 + c]);
        float hc = tanhfast(cu[base*64 + c]);
        float h = (1.f - r) * hc;
        g_state[base*64 + c] = h;
        hs[(((size_t)b*TT)*NN + n)*64 + c] = h;
    }
    gbar(++nbar);

    for (int t = 1; t < TT; ++t) {
        const float* cg_t = cg + (size_t)t*BB*NN*128;
        const float* cu_t = cu + (size_t)t*BB*NN*64;
        phase_mix(g_state, g_mixs, sm, tid, warp, lane);
        gbar(++nbar);
        phase_gate(gW, cg_t, C, Cin, sm, tid, warp, lane);
        gbar(++nbar);
        phase_mix(g_zs, g_mixzs, sm, tid, warp, lane);
        gbar(++nbar);
        phase_upd(uW, cu_t, C, Cin, hs, t, sm, tid, warp, lane);
        gbar(++nbar);
    }
}

// ---------------- precompute kernels (unchanged from round 3) ----------------

__global__ void __launch_bounds__(192) k_precomp(
        const float* __restrict__ xt, const float* __restrict__ mxt,
        const float* __restrict__ gW, const float* __restrict__ uW,
        const float* __restrict__ gb, const float* __restrict__ ub,
        float* __restrict__ cg, float* __restrict__ cu, int Cin) {
    const int C = Cin + HH;
    __shared__ float xs[64][2];
    __shared__ float ms[64][2];
    int n = blockIdx.x;
    int r0 = blockIdx.y * 64;
    int tid = threadIdx.x;
    for (int idx = tid; idx < 64*Cin; idx += 192) {
        int r = idx / Cin, c = idx - r*Cin;
        int z = r0 + r;
        xs[r][c] = xt[((size_t)z*NN + n)*Cin + c];
        int g = z*Cin + c;
        ms[r][c] = mxt[((size_t)(g>>6)*NN + n)*64 + (g&63)];
    }
    __syncthreads();
    float a[64];
    #pragma unroll
    for (int i = 0; i < 64; ++i) a[i] = 0.f;
    if (tid < 128) {
        int o = tid;
        const float* W0 = gW + (size_t)(n*2)*C*128 + o;
        const float* W1 = gW + (size_t)(n*2+1)*C*128 + o;
        for (int c = 0; c < Cin; ++c) {
            float w0 = W0[c*128], w1 = W1[c*128];
            #pragma unroll
            for (int r = 0; r < 64; ++r) a[r] += xs[r][c]*w0 + ms[r][c]*w1;
        }
        float bias = gb[n*128 + o];
        for (int r = 0; r < 64; ++r) {
            int z = r0 + r; int b = z / 12, t = z - b*12;
            cg[(((size_t)t*BB + b)*NN + n)*128 + o] = a[r] + bias;
        }
    } else {
        int o = tid - 128;
        const float* W0 = uW + (size_t)(n*2)*C*64 + o;
        const float* W1 = uW + (size_t)(n*2+1)*C*64 + o;
        for (int c = 0; c < Cin; ++c) {
            float w0 = W0[c*64], w1 = W1[c*64];
            #pragma unroll
            for (int r = 0; r < 64; ++r) a[r] += xs[r][c]*w0 + ms[r][c]*w1;
        }
        float bias = ub[n*64 + o];
        for (int r = 0; r < 64; ++r) {
            int z = r0 + r; int b = z / 12, t = z - b*12;
            cu[(((size_t)t*BB + b)*NN + n)*64 + o] = a[r] + bias;
        }
    }
}

__global__ void __launch_bounds__(256) k_precomp_mma(
        const float* __restrict__ xt, const float* __restrict__ mxt,
        const float* __restrict__ gW, const float* __restrict__ uW,
        const float* __restrict__ gb, const float* __restrict__ ub,
        float* __restrict__ cg, float* __restrict__ cu) {
    const int C = 128;
    __shared__ float As[128][36];
    __shared__ float Bs[32][200];
    int n = blockIdx.x;
    int m0 = blockIdx.y * 128;
    int tid = threadIdx.x;
    int warp = tid >> 5, lane = tid & 31;
    int wm = warp >> 1, wn = warp & 1;
    float acc[2][12][4];
    #pragma unroll
    for (int mt=0;mt<2;++mt) for (int j=0;j<12;++j) for (int q=0;q<4;++q) acc[mt][j][q]=0.f;

    for (int kc = 0; kc < 128; kc += 32) {
        #pragma unroll
        for (int i = 0; i < 4; ++i) {
            int idx = tid + i*256;
            int row = idx >> 3;
            int c4 = (idx & 7) * 4;
            int z = m0 + row;
            int k = kc + c4;
            float4 v = (k < 64)
                ? *reinterpret_cast<const float4*>(&xt[((size_t)z*NN + n)*64 + k])
                : *reinterpret_cast<const float4*>(&mxt[((size_t)z*NN + n)*64 + k - 64]);
            float4 w; w.x=to_tf32(v.x); w.y=to_tf32(v.y); w.z=to_tf32(v.z); w.w=to_tf32(v.w);
            *reinterpret_cast<float4*>(&As[row][c4]) = w;
        }
        #pragma unroll
        for (int i = 0; i < 6; ++i) {
            int idx = tid + i*256;
            int krow = idx / 48;
            int c4 = (idx % 48) * 4;
            int kk = kc + krow;
            const float* src = (c4 < 128)
                ? gW + ((size_t)(2*n + (kk>=64))*C + (kk&63))*128 + c4
                : uW + ((size_t)(2*n + (kk>=64))*C + (kk&63))*64 + (c4 - 128);
            float4 v = *reinterpret_cast<const float4*>(src);
            float4 w; w.x=to_tf32(v.x); w.y=to_tf32(v.y); w.z=to_tf32(v.z); w.w=to_tf32(v.w);
            *reinterpret_cast<float4*>(&Bs[krow][c4]) = w;
        }
        __syncthreads();
        #pragma unroll
        for (int k8 = 0; k8 < 32; k8 += 8) {
            uint32_t a[2][4];
            int ac = k8 + (lane&3);
            #pragma unroll
            for (int mt = 0; mt < 2; ++mt) {
                int rr = wm*32 + mt*16 + (lane>>2);
                a[mt][0] = __float_as_uint(As[rr][ac]);
                a[mt][1] = __float_as_uint(As[rr+8][ac]);
                a[mt][2] = __float_as_uint(As[rr][ac+4]);
                a[mt][3] = __float_as_uint(As[rr+8][ac+4]);
            }
            #pragma unroll
            for (int j = 0; j < 12; ++j) {
                int col = wn*96 + j*8 + (lane>>2);
                uint32_t b0 = __float_as_uint(Bs[k8 + (lane&3)][col]);
                uint32_t b1 = __float_as_uint(Bs[k8 + (lane&3) + 4][col]);
                mma_tf32(acc[0][j], a[0], b0, b1);
                mma_tf32(acc[1][j], a[1], b0, b1);
            }
        }
        __syncthreads();
    }
    #pragma unroll
    for (int mt = 0; mt < 2; ++mt) {
        #pragma unroll
        for (int j = 0; j < 12; ++j) {
            int col = wn*96 + j*8 + (lane&3)*2;
            #pragma unroll
            for (int half = 0; half < 2; ++half) {
                int z = m0 + wm*32 + mt*16 + (lane>>2) + half*8;
                int b = z / 12, t = z - b*12;
                float v0 = acc[mt][j][half*2], v1 = acc[mt][j][half*2+1];
                if (col < 128) {
                    float2 bb = *reinterpret_cast<const float2*>(&gb[n*128 + col]);
                    *reinterpret_cast<float2*>(&cg[(((size_t)t*BB + b)*NN + n)*128 + col]) =
                        make_float2(v0 + bb.x, v1 + bb.y);
                } else {
                    int o = col - 128;
                    float2 bb = *reinterpret_cast<const float2*>(&ub[n*64 + o]);
                    *reinterpret_cast<float2*>(&cu[(((size_t)t*BB + b)*NN + n)*64 + o]) =
                        make_float2(v0 + bb.x, v1 + bb.y);
                }
            }
        }
    }
}

__global__ void k_hyp(const float* __restrict__ hypW, const float* __restrict__ hypb) {
    __shared__ float part[192];
    __shared__ float hlin[48];
    int n = blockIdx.x;
    int tid = threadIdx.x;
    int j = tid % 48, sl = tid / 48;
    const float* u = g_uW + (size_t)n * 16384;
    float a = 0.f;
    int i0 = sl * 4096;
    for (int i = i0; i < i0 + 4096; ++i) a += u[i] * hypW[i*48 + j];
    part[tid] = a;
    __syncthreads();
    if (tid < 48) hlin[tid] = part[tid] + part[48+tid] + part[96+tid] + part[144+tid] + hypb[tid];
    __syncthreads();
    if (tid < 12) {
        g_fs[n*TT + tid] = hlin[tid*4] + hlin[tid*4+1] + hlin[tid*4+2] + hlin[tid*4+3];
    }
}

__global__ void k_copy_last() {
    int idx = blockIdx.x*blockDim.x + threadIdx.x;
    if (idx >= BB*NN*HH) return;
    int c = idx & 63;
    int bn = idx >> 6;
    int n = bn & 511, b = bn >> 9;
    g_hv[idx] = g_hs1[(((size_t)b*TT + (TT-1))*NN + n)*64 + c];
}

__global__ void __launch_bounds__(256) k_gemm64_mma(
        const float* __restrict__ X, const float* __restrict__ W,
        const float* __restrict__ bias, float* __restrict__ Y, int relu) {
    __shared__ float Xs[128][36];
    __shared__ float Ws[32][72];
    int r0 = blockIdx.x * 128;
    int tid = threadIdx.x;
    int warp = tid >> 5, lane = tid & 31;
    float acc[8][4];
    #pragma unroll
    for (int j=0;j<8;++j) for (int q=0;q<4;++q) acc[j][q]=0.f;
    for (int kc = 0; kc < 64; kc += 32) {
        #pragma unroll
        for (int i = 0; i < 4; ++i) {
            int idx = tid + i*256;
            int row = idx >> 3;
            int c4 = (idx & 7) * 4;
            float4 v = *reinterpret_cast<const float4*>(&X[(size_t)(r0+row)*64 + kc + c4]);
            float4 w; w.x=to_tf32(v.x); w.y=to_tf32(v.y); w.z=to_tf32(v.z); w.w=to_tf32(v.w);
            *reinterpret_cast<float4*>(&Xs[row][c4]) = w;
        }
        #pragma unroll
        for (int i = 0; i < 2; ++i) {
            int idx = tid + i*256;
            int krow = idx >> 4;
            int c4 = (idx & 15) * 4;
            float4 v = *reinterpret_cast<const float4*>(&W[(size_t)(kc+krow)*64 + c4]);
            float4 w; w.x=to_tf32(v.x); w.y=to_tf32(v.y); w.z=to_tf32(v.z); w.w=to_tf32(v.w);
            *reinterpret_cast<float4*>(&Ws[krow][c4]) = w;
        }
        __syncthreads();
        #pragma unroll
        for (int k8 = 0; k8 < 32; k8 += 8) {
            uint32_t a[4];
            int ar = warp*16 + (lane>>2);
            int ac = k8 + (lane&3);
            a[0] = __float_as_uint(Xs[ar][ac]);
            a[1] = __float_as_uint(Xs[ar+8][ac]);
            a[2] = __float_as_uint(Xs[ar][ac+4]);
            a[3] = __float_as_uint(Xs[ar+8][ac+4]);
            #pragma unroll
            for (int j = 0; j < 8; ++j) {
                uint32_t b0 = __float_as_uint(Ws[k8 + (lane&3)][j*8 + (lane>>2)]);
                uint32_t b1 = __float_as_uint(Ws[k8 + (lane&3) + 4][j*8 + (lane>>2)]);
                mma_tf32(acc[j], a, b0, b1);
            }
        }
        __syncthreads();
    }
    int row = r0 + warp*16 + (lane>>2);
    #pragma unroll
    for (int j = 0; j < 8; ++j) {
        int col = j*8 + (lane&3)*2;
        float b0 = bias ? bias[col] : 0.f, b1 = bias ? bias[col+1] : 0.f;
        float v0 = acc[j][0] + b0, v1 = acc[j][1] + b1;
        float v2 = acc[j][2] + b0, v3 = acc[j][3] + b1;
        if (relu) { v0=fmaxf(v0,0.f); v1=fmaxf(v1,0.f); v2=fmaxf(v2,0.f); v3=fmaxf(v3,0.f); }
        *reinterpret_cast<float2*>(&Y[(size_t)row*64 + col]) = make_float2(v0, v1);
        *reinterpret_cast<float2*>(&Y[(size_t)(row+8)*64 + col]) = make_float2(v2, v3);
    }
}

__global__ void k_attn(const float* __restrict__ bv) {
    __shared__ float qs[12][64], ks[12][64], vs[12][64];
    __shared__ float sc[2][12][12];
    int bn = blockIdx.x;
    int b = bn >> 9, n = bn & 511;
    int tid = threadIdx.x;
    for (int idx = tid; idx < 12*64; idx += 128) {
        int t = idx >> 6, c = idx & 63;
        size_t g = (((size_t)b*TT + t)*NN + n)*HH + c;
        qs[t][c] = g_q[g];
        ks[t][c] = g_k[g];
        vs[t][c] = g_fs[n*TT + t] * g_v[((size_t)b*NN + n)*64 + c] + bv[c];
    }
    __syncthreads();
    for (int idx = tid; idx < 288; idx += 128) {
        int h = idx / 144, rem = idx - h*144;
        int t = rem / 12, s = rem - t*12;
        float d = 0.f;
        #pragma unroll
        for (int k = 0; k < 32; ++k) d += qs[t][h*32 + k] * ks[s][h*32 + k];
        sc[h][t][s] = d * 0.17677669529663687f;
    }
    __syncthreads();
    if (tid < 24) {
        int h = tid / 12, t = tid - h*12;
        float mx = -1e30f;
        #pragma unroll
        for (int s = 0; s < 12; ++s) mx = fmaxf(mx, sc[h][t][s]);
        float sum = 0.f;
        #pragma unroll
        for (int s = 0; s < 12; ++s) { float e = __expf(sc[h][t][s] - mx); sc[h][t][s] = e; sum += e; }
        float inv = 1.f / sum;
        #pragma unroll
        for (int s = 0; s < 12; ++s) sc[h][t][s] *= inv;
    }
    __syncthreads();
    for (int idx = tid; idx < 768; idx += 128) {
        int h = idx / 384, rem = idx - h*384;
        int t = rem >> 5, d = rem & 31;
        float a = 0.f;
        #pragma unroll
        for (int s = 0; s < 12; ++s) a += sc[h][t][s] * vs[s][h*32 + d];
        g_o[(((size_t)b*TT + t)*NN + n)*HH + h*32 + d] = a;
    }
}

__global__ void __launch_bounds__(256) k_lnres_w(
        const float* __restrict__ A, const float* __restrict__ Bv,
        const float* __restrict__ g, const float* __restrict__ be,
        float* __restrict__ Y) {
    int lane = threadIdx.x & 31;
    size_t row = (size_t)blockIdx.x * 8 + (threadIdx.x >> 5);
    int c = lane * 2;
    float2 a = *reinterpret_cast<const float2*>(&A[row*64 + c]);
    float2 b2 = *reinterpret_cast<const float2*>(&Bv[row*64 + c]);
    float x0 = a.x + b2.x, x1 = a.y + b2.y;
    float s = x0 + x1, sq = x0*x0 + x1*x1;
    #pragma unroll
    for (int o = 16; o > 0; o >>= 1) {
        s  += __shfl_xor_sync(0xffffffffu, s, o);
        sq += __shfl_xor_sync(0xffffffffu, sq, o);
    }
    float mu = s * (1.f/64.f);
    float var = sq * (1.f/64.f) - mu*mu;
    float rstd = rsqrtf(var + 1e-5f);
    float y0 = (x0 - mu) * rstd * g[c] + be[c];
    float y1 = (x1 - mu) * rstd * g[c+1] + be[c+1];
    *reinterpret_cast<float2*>(&Y[row*64 + c]) = make_float2(y0, y1);
}

__global__ void __launch_bounds__(256) k_fc_w(
        const float* __restrict__ X, const float* __restrict__ w,
        const float* __restrict__ bp, float* __restrict__ Y) {
    int lane = threadIdx.x & 31;
    size_t row = (size_t)blockIdx.x * 8 + (threadIdx.x >> 5);
    int c = lane * 2;
    float2 x = *reinterpret_cast<const float2*>(&X[row*64 + c]);
    float s = x.x * w[c] + x.y * w[c+1];
    #pragma unroll
    for (int o = 16; o > 0; o >>= 1) s += __shfl_xor_sync(0xffffffffu, s, o);
    if (lane == 0) Y[row] = s + bp[0];
}

// ---------------- host ----------------

extern "C" void kernel_launch(void* const* d_in, const int* in_sizes, int n_in,
                              void* d_out, int out_size) {
    const float* src  = (const float*)d_in[0];
    const float* emb  = (const float*)d_in[2];
    const float* gwp0 = (const float*)d_in[3];
    const float* gbp0 = (const float*)d_in[4];
    const float* uwp0 = (const float*)d_in[5];
    const float* ubp0 = (const float*)d_in[6];
    const float* gwp1 = (const float*)d_in[7];
    const float* gbp1 = (const float*)d_in[8];
    const float* uwp1 = (const float*)d_in[9];
    const float* ubp1 = (const float*)d_in[10];
    const float* hypW = (const float*)d_in[11];
    const float* hypb = (const float*)d_in[12];

    const float *Wq,*Wk,*Wv,*ffW1,*ffW2,*bq,*bk,*bv,*ffb1,*ffb2,*ln1g,*ln1b,*ln2g,*ln2b,*fcW,*fcb;
    if (n_in > 14 && in_sizes[14] == 64) {
        Wq  = (const float*)d_in[13]; bq  = (const float*)d_in[14];
        Wk  = (const float*)d_in[15]; bk  = (const float*)d_in[16];
        Wv  = (const float*)d_in[17]; bv  = (const float*)d_in[18];
        ln1g= (const float*)d_in[19]; ln1b= (const float*)d_in[20];
        ffW1= (const float*)d_in[21]; ffb1= (const float*)d_in[22];
        ffW2= (const float*)d_in[23]; ffb2= (const float*)d_in[24];
        ln2g= (const float*)d_in[25]; ln2b= (const float*)d_in[26];
        fcW = (const float*)d_in[27]; fcb = (const float*)d_in[28];
    } else {
        Wq  = (const float*)d_in[13]; Wk  = (const float*)d_in[14];
        Wv  = (const float*)d_in[15]; ffW1= (const float*)d_in[16];
        ffW2= (const float*)d_in[17]; bq  = (const float*)d_in[18];
        bk  = (const float*)d_in[19]; bv  = (const float*)d_in[20];
        ffb1= (const float*)d_in[21]; ffb2= (const float*)d_in[22];
        ln1g= (const float*)d_in[23]; ln1b= (const float*)d_in[24];
        ln2g= (const float*)d_in[25]; ln2b= (const float*)d_in[26];
        fcW = (const float*)d_in[27]; fcb = (const float*)d_in[28];
    }

    float *p_gW,*p_gb,*p_uW,*p_ub,*p_cg,*p_cu,*p_mxt,*p_xt0t;
    float *p_hs0,*p_hs1,*p_hv,*p_q,*p_k,*p_v,*p_o,*p_val,*p_ff1,*p_ffo,*p_out2;
    cudaGetSymbolAddress((void**)&p_gW, g_gW);
    cudaGetSymbolAddress((void**)&p_gb, g_gb);
    cudaGetSymbolAddress((void**)&p_uW, g_uW);
    cudaGetSymbolAddress((void**)&p_ub, g_ub);
    cudaGetSymbolAddress((void**)&p_cg, g_cg);
    cudaGetSymbolAddress((void**)&p_cu, g_cu);
    cudaGetSymbolAddress((void**)&p_mxt, g_mxt);
    cudaGetSymbolAddress((void**)&p_xt0t, g_xt0t);
    cudaGetSymbolAddress((void**)&p_hs0, g_hs0);
    cudaGetSymbolAddress((void**)&p_hs1, g_hs1);
    cudaGetSymbolAddress((void**)&p_hv, g_hv);
    cudaGetSymbolAddress((void**)&p_q, g_q);
    cudaGetSymbolAddress((void**)&p_k, g_k);
    cudaGetSymbolAddress((void**)&p_v, g_v);
    cudaGetSymbolAddress((void**)&p_o, g_o);
    cudaGetSymbolAddress((void**)&p_val, g_val);
    cudaGetSymbolAddress((void**)&p_ff1, g_ff1);
    cudaGetSymbolAddress((void**)&p_ffo, g_ffo);
    cudaGetSymbolAddress((void**)&p_out2, g_out2);

    k_adj<<<NN, 256>>>(emb);

    for (int layer = 0; layer < 2; ++layer) {
        int Cin = (layer == 0) ? 2 : 64;
        int C = Cin + HH;
        float* hs_out;
        if (layer == 0) {
            int s;
            s = 2*C*128/4; k_matpool4<<<(NN*s+255)/256, 256>>>(emb, gwp0, p_gW, s);
            s = 128/4;     k_matpool4<<<(NN*s+255)/256, 256>>>(emb, gbp0, p_gb, s);
            s = 2*C*64/4;  k_matpool4<<<(NN*s+255)/256, 256>>>(emb, uwp0, p_uW, s);
            s = 64/4;      k_matpool4<<<(NN*s+255)/256, 256>>>(emb, ubp0, p_ub, s);
            k_transp0<<<(ZT*NN*2 + 255)/256, 256>>>(src, p_xt0t);
            k_mix64<<<dim3(8, (ZT*2)/64), 128>>>(p_xt0t, p_mxt);
            k_precomp<<<dim3(NN, 6), 192>>>(src, p_mxt, p_gW, p_uW, p_gb, p_ub, p_cg, p_cu, Cin);
            hs_out = p_hs0;
        } else {
            int s;
            s = 2*C*128/4; k_matpool4<<<(NN*s+255)/256, 256>>>(emb, gwp1, p_gW, s);
            s = 128/4;     k_matpool4<<<(NN*s+255)/256, 256>>>(emb, gbp1, p_gb, s);
            s = 2*C*64/4;  k_matpool4<<<(NN*s+255)/256, 256>>>(emb, uwp1, p_uW, s);
            s = 64/4;      k_matpool4<<<(NN*s+255)/256, 256>>>(emb, ubp1, p_ub, s);
            k_mix64<<<dim3(8, ZT), 128>>>(p_hs0, p_mxt);
            k_precomp_mma<<<dim3(NN, 3), 256>>>(p_hs0, p_mxt, p_gW, p_uW, p_gb, p_ub, p_cg, p_cu);
            hs_out = p_hs1;
        }
        k_reset_bar<<<1, 1>>>();
        k_recur<<<GRID_P, 256>>>(p_gW, p_uW, p_cg, p_cu, hs_out, C, Cin);
    }

    k_hyp<<<NN, 192>>>(hypW, hypb);
    k_copy_last<<<(BB*NN*HH + 255)/256, 256>>>();

    k_gemm64_mma<<<BTN/128, 256>>>(p_hs1, Wq, bq, p_q, 0);
    k_gemm64_mma<<<BTN/128, 256>>>(p_hs1, Wk, bk, p_k, 0);
    k_gemm64_mma<<<BB*NN/128, 256>>>(p_hv, Wv, nullptr, p_v, 0);

    k_attn<<<BB*NN, 128>>>(bv);

    k_lnres_w<<<BTN/8, 256>>>(p_o, p_hs1, ln1g, ln1b, p_val);
    k_gemm64_mma<<<BTN/128, 256>>>(p_val, ffW1, ffb1, p_ff1, 1);
    k_gemm64_mma<<<BTN/128, 256>>>(p_ff1, ffW2, ffb2, p_ffo, 0);
    k_lnres_w<<<BTN/8, 256>>>(p_ffo, p_val, ln2g, ln2b, p_out2);
    k_fc_w<<<BTN/8, 256>>>(p_out2, fcW, fcb, (float*)d_out);
}

// round 6
// speedup vs baseline: 3.2622x; 1.0760x over previous
#include <cuda_runtime.h>
#include <math.h>
#include <stdint.h>

#define BB 32
#define TT 12
#define NN 512
#define HH 64
#define EE 16
#define BTN (BB*TT*NN)
#define BTNH (BTN*HH)
#define ZT (BB*TT)
#define GRID_P 256
#define RECUR_SMEM 51712   // bytes = 12928 floats (gate phase max)

__device__ float g_adj[NN*NN];
__device__ float g_gW[NN*2*128*128];
__device__ float g_gb[NN*128];
__device__ float g_uW[NN*2*128*64];
__device__ float g_ub[NN*64];
__device__ float g_state[BB*NN*HH];
__device__ float g_mixs[BB*NN*HH];
__device__ float g_zs[BB*NN*HH];
__device__ float g_mixzs[BB*NN*HH];
__device__ float g_r[BB*NN*HH];
__device__ float g_cg[TT*BB*NN*128];
__device__ float g_cu[TT*BB*NN*64];
__device__ float g_mxt[ZT*NN*64];
__device__ float g_xt0t[TT*NN*64];
__device__ float g_hs0[BTNH];
__device__ float g_hs1[BTNH];
__device__ float g_fs[NN*TT];
__device__ float g_hlin[NN*48];
__device__ float g_hv[BB*NN*HH];
__device__ float g_q[BTNH];
__device__ float g_k[BTNH];
__device__ float g_v[BB*NN*HH];
__device__ float g_o[BTNH];
__device__ float g_val[BTNH];
__device__ float g_ff1[BTNH];
__device__ float g_ffo[BTNH];
__device__ float g_out2[BTNH];
__device__ unsigned g_bar;

__device__ __forceinline__ float to_tf32(float x) {
    uint32_t u; asm("cvt.rna.tf32.f32 %0, %1;" : "=r"(u) : "f"(x));
    return __uint_as_float(u);
}
__device__ __forceinline__ uint32_t cvu(float x) {
    uint32_t u; asm("cvt.rna.tf32.f32 %0, %1;" : "=r"(u) : "f"(x));
    return u;
}
__device__ __forceinline__ float4 tf32x4(float4 v) {
    float4 w; w.x=to_tf32(v.x); w.y=to_tf32(v.y); w.z=to_tf32(v.z); w.w=to_tf32(v.w);
    return w;
}
__device__ __forceinline__ void mma_tf32(float* c, const uint32_t* a, uint32_t b0, uint32_t b1) {
    asm volatile("mma.sync.aligned.m16n8k8.row.col.f32.tf32.tf32.f32 "
        "{%0,%1,%2,%3}, {%4,%5,%6,%7}, {%8,%9}, {%0,%1,%2,%3};"
        : "+f"(c[0]), "+f"(c[1]), "+f"(c[2]), "+f"(c[3])
        : "r"(a[0]), "r"(a[1]), "r"(a[2]), "r"(a[3]), "r"(b0), "r"(b1));
}
__device__ __forceinline__ float sigm(float v) { return 1.f / (1.f + __expf(-v)); }
__device__ __forceinline__ float tanhfast(float v) { return 1.f - 2.f / (__expf(2.f*v) + 1.f); }

__device__ __forceinline__ void gbar(unsigned n) {
    __syncthreads();
    if (threadIdx.x == 0) {
        __threadfence();
        atomicAdd(&g_bar, 1u);
        unsigned target = n * GRID_P;
        volatile unsigned* p = &g_bar;
        while (*p < target) __nanosleep(64);
        __threadfence();
    }
    __syncthreads();
}

// ---------------- adjacency (also resets barrier, zeroes hyp partials) ----------------
__global__ void k_adj(const float* __restrict__ emb) {
    __shared__ float semb[NN*EE];
    __shared__ float row[NN];
    __shared__ float red[256];
    if (blockIdx.x == 0 && threadIdx.x == 0) g_bar = 0u;
    for (int i = blockIdx.x*256 + threadIdx.x; i < NN*48; i += NN*256) g_hlin[i] = 0.f;
    int n = blockIdx.x;
    for (int i = threadIdx.x; i < NN*EE; i += 256) semb[i] = emb[i];
    __syncthreads();
    float lmax = -1e30f;
    for (int m = threadIdx.x; m < NN; m += 256) {
        float s = 0.f;
        #pragma unroll
        for (int e = 0; e < EE; ++e) s += semb[n*EE+e] * semb[m*EE+e];
        s = fmaxf(s, 0.f);
        row[m] = s;
        lmax = fmaxf(lmax, s);
    }
    red[threadIdx.x] = lmax; __syncthreads();
    for (int s = 128; s > 0; s >>= 1) {
        if (threadIdx.x < s) red[threadIdx.x] = fmaxf(red[threadIdx.x], red[threadIdx.x+s]);
        __syncthreads();
    }
    float mx = red[0];
    __syncthreads();
    float lsum = 0.f;
    for (int m = threadIdx.x; m < NN; m += 256) {
        float v = expf(row[m] - mx);
        row[m] = v; lsum += v;
    }
    red[threadIdx.x] = lsum; __syncthreads();
    for (int s = 128; s > 0; s >>= 1) {
        if (threadIdx.x < s) red[threadIdx.x] += red[threadIdx.x+s];
        __syncthreads();
    }
    float inv = 1.f / red[0];
    for (int m = threadIdx.x; m < NN; m += 256) g_adj[n*NN + m] = row[m] * inv;
}

__global__ void k_matpool4(const float* __restrict__ emb, const float* __restrict__ pool,
                           float* __restrict__ out, int S4) {
    int idx = blockIdx.x*blockDim.x + threadIdx.x;
    if (idx >= NN * S4) return;
    int n = idx / S4, i = idx - n*S4;
    float4 a = make_float4(0.f,0.f,0.f,0.f);
    const float* e = emb + n*EE;
    const float4* p4 = (const float4*)pool;
    #pragma unroll
    for (int k = 0; k < EE; ++k) {
        float w = e[k];
        float4 p = p4[(size_t)k*S4 + i];
        a.x += w*p.x; a.y += w*p.y; a.z += w*p.z; a.w += w*p.w;
    }
    ((float4*)out)[idx] = a;
}

__global__ void k_transp0(const float* __restrict__ src, float* __restrict__ xt0) {
    int idx = blockIdx.x*blockDim.x + threadIdx.x;
    if (idx >= ZT*NN*2) return;
    int c = idx & 1, m = (idx >> 1) & 511, z = idx >> 10;
    int g = z*2 + c;
    xt0[((size_t)(g>>6)*NN + m)*64 + (g&63)] = src[idx];
}

// ---------------- double-buffered mix tile ----------------
// sm: A0@0(2304) A1@2304 X0@4608(2304) X1@6912  (needs 9216 floats)
__device__ __forceinline__ void mix_tile(const float* __restrict__ X, float* __restrict__ Y,
                                         float* sm, int tid, int z, int r0) {
    int warp = tid >> 5, lane = tid & 31;
    int wm = warp >> 1, wn = warp & 1;
    const float* Xb = X + (size_t)z * (NN*64);
    float* Yb = Y + (size_t)z * (NN*64);
    float acc[4][4];
    #pragma unroll
    for (int j=0;j<4;++j){acc[j][0]=0.f;acc[j][1]=0.f;acc[j][2]=0.f;acc[j][3]=0.f;}
    float4 ar0, ar1, xr0, xr1;
    int i0 = tid, i1 = tid + 256;
    ar0 = *(const float4*)&g_adj[(size_t)(r0 + (i0>>3))*NN + (i0&7)*4];
    ar1 = *(const float4*)&g_adj[(size_t)(r0 + (i1>>3))*NN + (i1&7)*4];
    xr0 = *(const float4*)&Xb[(size_t)(i0>>4)*64 + (i0&15)*4];
    xr1 = *(const float4*)&Xb[(size_t)(i1>>4)*64 + (i1&15)*4];
    {
        float* As = sm; float* Xs = sm + 4608;
        *(float4*)&As[(i0>>3)*36 + (i0&7)*4] = tf32x4(ar0);
        *(float4*)&As[(i1>>3)*36 + (i1&7)*4] = tf32x4(ar1);
        *(float4*)&Xs[(i0>>4)*72 + (i0&15)*4] = tf32x4(xr0);
        *(float4*)&Xs[(i1>>4)*72 + (i1&15)*4] = tf32x4(xr1);
    }
    for (int c = 0; c < 16; ++c) {
        __syncthreads();
        if (c < 15) {
            int kc = (c+1)*32;
            ar0 = *(const float4*)&g_adj[(size_t)(r0 + (i0>>3))*NN + kc + (i0&7)*4];
            ar1 = *(const float4*)&g_adj[(size_t)(r0 + (i1>>3))*NN + kc + (i1&7)*4];
            xr0 = *(const float4*)&Xb[(size_t)(kc + (i0>>4))*64 + (i0&15)*4];
            xr1 = *(const float4*)&Xb[(size_t)(kc + (i1>>4))*64 + (i1&15)*4];
        }
        float* As = sm + (c&1)*2304;
        float* Xs = sm + 4608 + (c&1)*2304;
        #pragma unroll
        for (int k8 = 0; k8 < 32; k8 += 8) {
            uint32_t a[4];
            int arow = wm*16 + (lane>>2);
            int ac = k8 + (lane&3);
            a[0] = __float_as_uint(As[arow*36 + ac]);
            a[1] = __float_as_uint(As[(arow+8)*36 + ac]);
            a[2] = __float_as_uint(As[arow*36 + ac + 4]);
            a[3] = __float_as_uint(As[(arow+8)*36 + ac + 4]);
            #pragma unroll
            for (int j = 0; j < 4; ++j) {
                int col = wn*32 + j*8 + (lane>>2);
                uint32_t b0 = __float_as_uint(Xs[(k8+(lane&3))*72 + col]);
                uint32_t b1 = __float_as_uint(Xs[(k8+(lane&3)+4)*72 + col]);
                mma_tf32(acc[j], a, b0, b1);
            }
        }
        if (c < 15) {
            float* Asn = sm + ((c+1)&1)*2304;
            float* Xsn = sm + 4608 + ((c+1)&1)*2304;
            *(float4*)&Asn[(i0>>3)*36 + (i0&7)*4] = tf32x4(ar0);
            *(float4*)&Asn[(i1>>3)*36 + (i1&7)*4] = tf32x4(ar1);
            *(float4*)&Xsn[(i0>>4)*72 + (i0&15)*4] = tf32x4(xr0);
            *(float4*)&Xsn[(i1>>4)*72 + (i1&15)*4] = tf32x4(xr1);
        }
    }
    int row = r0 + wm*16 + (lane>>2);
    #pragma unroll
    for (int j = 0; j < 4; ++j) {
        int col = wn*32 + j*8 + (lane&3)*2;
        *(float2*)&Yb[(size_t)row*64 + col] = make_float2(acc[j][0], acc[j][1]);
        *(float2*)&Yb[(size_t)(row+8)*64 + col] = make_float2(acc[j][2], acc[j][3]);
    }
}

// standalone mix for precompute
__global__ void __launch_bounds__(256) k_mix64(const float* __restrict__ X, float* __restrict__ Y) {
    __shared__ float sm[9216];
    mix_tile(X, Y, sm, threadIdx.x, blockIdx.y, blockIdx.x*64);
}

// ---------------- persistent recurrence phases ----------------
// gate sm: As@0 (32x132=4224), Bs0@4224 (32x136=4352), Bs1@8576
__device__ __forceinline__ void phase_gate(const float* __restrict__ gW, const float* __restrict__ cg_t,
                                           int C, int Cin, float* sm, int tid) {
    int warp = tid >> 5, lane = tid & 31;
    int wm = warp >> 2, wn = warp & 3;
    float (*As)[132] = (float(*)[132])sm;
    for (int n = blockIdx.x; n < NN; n += GRID_P) {
        __syncthreads();
        #pragma unroll
        for (int i = 0; i < 4; ++i) {
            int idx = tid + i*256;
            int row = idx >> 5;
            int c4 = (idx & 31) * 4;
            float4 v = (c4 < 64)
                ? *(const float4*)&g_state[((size_t)row*NN + n)*64 + c4]
                : *(const float4*)&g_mixs[((size_t)row*NN + n)*64 + c4 - 64];
            *(float4*)&As[row][c4] = v;
        }
        {
            float* Bs = sm + 4224;
            #pragma unroll
            for (int i = 0; i < 4; ++i) {
                int idx = tid + i*256;
                int kk = idx >> 5;
                int c4 = (idx & 31) * 4;
                float4 v = *(const float4*)&gW[((size_t)(2*n + (kk>=64))*C + Cin + (kk&63))*128 + c4];
                *(float4*)&Bs[kk*136 + c4] = tf32x4(v);
            }
        }
        float acc[4][4];
        #pragma unroll
        for (int j=0;j<4;++j){acc[j][0]=0.f;acc[j][1]=0.f;acc[j][2]=0.f;acc[j][3]=0.f;}
        float4 bv[4];
        for (int c = 0; c < 4; ++c) {
            __syncthreads();
            if (c < 3) {
                int kc = (c+1)*32;
                #pragma unroll
                for (int i = 0; i < 4; ++i) {
                    int idx = tid + i*256;
                    int kk = kc + (idx >> 5);
                    int c4 = (idx & 31) * 4;
                    bv[i] = *(const float4*)&gW[((size_t)(2*n + (kk>=64))*C + Cin + (kk&63))*128 + c4];
                }
            }
            float* Bs = sm + 4224 + (c&1)*4352;
            #pragma unroll
            for (int k8 = 0; k8 < 32; k8 += 8) {
                int arow = wm*16 + (lane>>2);
                int ac = c*32 + k8 + (lane&3);
                uint32_t a[4];
                a[0] = cvu(As[arow][ac]);
                a[1] = cvu(As[arow+8][ac]);
                a[2] = cvu(As[arow][ac+4]);
                a[3] = cvu(As[arow+8][ac+4]);
                #pragma unroll
                for (int j = 0; j < 4; ++j) {
                    int col = wn*32 + j*8 + (lane>>2);
                    uint32_t b0 = __float_as_uint(Bs[(k8+(lane&3))*136 + col]);
                    uint32_t b1 = __float_as_uint(Bs[(k8+(lane&3)+4)*136 + col]);
                    mma_tf32(acc[j], a, b0, b1);
                }
            }
            if (c < 3) {
                float* Bsn = sm + 4224 + ((c+1)&1)*4352;
                #pragma unroll
                for (int i = 0; i < 4; ++i) {
                    int idx = tid + i*256;
                    int c4 = (idx & 31) * 4;
                    *(float4*)&Bsn[(idx>>5)*136 + c4] = tf32x4(bv[i]);
                }
            }
        }
        #pragma unroll
        for (int j = 0; j < 4; ++j) {
            int col = wn*32 + j*8 + (lane&3)*2;
            #pragma unroll
            for (int half = 0; half < 2; ++half) {
                int b = wm*16 + (lane>>2) + half*8;
                float v0 = acc[j][half*2], v1 = acc[j][half*2+1];
                size_t base = (size_t)b*NN + n;
                float2 cgv = *(const float2*)&cg_t[base*128 + col];
                v0 += cgv.x; v1 += cgv.y;
                if (col < 64) {
                    *(float2*)&g_zs[base*64 + col] =
                        make_float2(sigm(v0) * As[b][col], sigm(v1) * As[b][col+1]);
                } else {
                    *(float2*)&g_r[base*64 + col - 64] = make_float2(sigm(v0), sigm(v1));
                }
            }
        }
    }
}

// upd sm: As@0 (4224), Bs0@4224 (32x72=2304), Bs1@6528
__device__ __forceinline__ void phase_upd(const float* __restrict__ uW, const float* __restrict__ cu_t,
                                          int C, int Cin, float* __restrict__ hs, int t,
                                          float* sm, int tid) {
    int warp = tid >> 5, lane = tid & 31;
    int wm = warp >> 2, wn = warp & 3;
    float (*As)[132] = (float(*)[132])sm;
    for (int n = blockIdx.x; n < NN; n += GRID_P) {
        __syncthreads();
        #pragma unroll
        for (int i = 0; i < 4; ++i) {
            int idx = tid + i*256;
            int row = idx >> 5;
            int c4 = (idx & 31) * 4;
            float4 v = (c4 < 64)
                ? *(const float4*)&g_zs[((size_t)row*NN + n)*64 + c4]
                : *(const float4*)&g_mixzs[((size_t)row*NN + n)*64 + c4 - 64];
            *(float4*)&As[row][c4] = v;
        }
        {
            float* Bs = sm + 4224;
            #pragma unroll
            for (int i = 0; i < 2; ++i) {
                int idx = tid + i*256;
                int kk = idx >> 4;
                int c4 = (idx & 15) * 4;
                float4 v = *(const float4*)&uW[((size_t)(2*n + (kk>=64))*C + Cin + (kk&63))*64 + c4];
                *(float4*)&Bs[kk*72 + c4] = tf32x4(v);
            }
        }
        float acc[2][4];
        #pragma unroll
        for (int j=0;j<2;++j){acc[j][0]=0.f;acc[j][1]=0.f;acc[j][2]=0.f;acc[j][3]=0.f;}
        float4 bv[2];
        for (int c = 0; c < 4; ++c) {
            __syncthreads();
            if (c < 3) {
                int kc = (c+1)*32;
                #pragma unroll
                for (int i = 0; i < 2; ++i) {
                    int idx = tid + i*256;
                    int kk = kc + (idx >> 4);
                    int c4 = (idx & 15) * 4;
                    bv[i] = *(const float4*)&uW[((size_t)(2*n + (kk>=64))*C + Cin + (kk&63))*64 + c4];
                }
            }
            float* Bs = sm + 4224 + (c&1)*2304;
            #pragma unroll
            for (int k8 = 0; k8 < 32; k8 += 8) {
                int arow = wm*16 + (lane>>2);
                int ac = c*32 + k8 + (lane&3);
                uint32_t a[4];
                a[0] = cvu(As[arow][ac]);
                a[1] = cvu(As[arow+8][ac]);
                a[2] = cvu(As[arow][ac+4]);
                a[3] = cvu(As[arow+8][ac+4]);
                #pragma unroll
                for (int j = 0; j < 2; ++j) {
                    int col = wn*16 + j*8 + (lane>>2);
                    uint32_t b0 = __float_as_uint(Bs[(k8+(lane&3))*72 + col]);
                    uint32_t b1 = __float_as_uint(Bs[(k8+(lane&3)+4)*72 + col]);
                    mma_tf32(acc[j], a, b0, b1);
                }
            }
            if (c < 3) {
                float* Bsn = sm + 4224 + ((c+1)&1)*2304;
                #pragma unroll
                for (int i = 0; i < 2; ++i) {
                    int idx = tid + i*256;
                    int c4 = (idx & 15) * 4;
                    *(float4*)&Bsn[(idx>>4)*72 + c4] = tf32x4(bv[i]);
                }
            }
        }
        #pragma unroll
        for (int j = 0; j < 2; ++j) {
            int col = wn*16 + j*8 + (lane&3)*2;
            #pragma unroll
            for (int half = 0; half < 2; ++half) {
                int b = wm*16 + (lane>>2) + half*8;
                float v0 = acc[j][half*2], v1 = acc[j][half*2+1];
                size_t base = (size_t)b*NN + n;
                float2 cuv = *(const float2*)&cu_t[base*64 + col];
                float hc0 = tanhfast(v0 + cuv.x), hc1 = tanhfast(v1 + cuv.y);
                size_t idx = base*64 + col;
                float2 rr = *(const float2*)&g_r[idx];
                float2 st = *(const float2*)&g_state[idx];
                float h0 = rr.x*st.x + (1.f-rr.x)*hc0;
                float h1 = rr.y*st.y + (1.f-rr.y)*hc1;
                *(float2*)&g_state[idx] = make_float2(h0, h1);
                *(float2*)&hs[(((size_t)b*TT + t)*NN + n)*64 + col] = make_float2(h0, h1);
            }
        }
    }
}

__global__ void __launch_bounds__(256, 2) k_recur(
        const float* __restrict__ gW, const float* __restrict__ uW,
        const float* __restrict__ cg, const float* __restrict__ cu,
        float* __restrict__ hs, int C, int Cin, unsigned nbar) {
    extern __shared__ float sm[];
    int tid = threadIdx.x;
    // t = 0: state=0 => r = sigm(cg_r), h = (1-r)*tanh(cu)
    for (int idx = blockIdx.x*256 + tid; idx < BB*NN*64; idx += GRID_P*256) {
        int c = idx & 63;
        int n = (idx >> 6) & 511;
        int b = idx >> 15;
        size_t base = (size_t)b*NN + n;
        float r = sigm(cg[base*128 + 64 + c]);
        float hc = tanhfast(cu[base*64 + c]);
        float h = (1.f - r) * hc;
        g_state[base*64 + c] = h;
        hs[(((size_t)b*TT)*NN + n)*64 + c] = h;
    }
    gbar(++nbar);
    int z = blockIdx.x >> 3;
    int r0 = (blockIdx.x & 7) * 64;
    for (int t = 1; t < TT; ++t) {
        const float* cg_t = cg + (size_t)t*BB*NN*128;
        const float* cu_t = cu + (size_t)t*BB*NN*64;
        mix_tile(g_state, g_mixs, sm, tid, z, r0);
        gbar(++nbar);
        phase_gate(gW, cg_t, C, Cin, sm, tid);
        gbar(++nbar);
        mix_tile(g_zs, g_mixzs, sm, tid, z, r0);
        gbar(++nbar);
        phase_upd(uW, cu_t, C, Cin, hs, t, sm, tid);
        gbar(++nbar);
    }
}

// ---------------- precompute ----------------
__global__ void __launch_bounds__(192) k_precomp(
        const float* __restrict__ xt, const float* __restrict__ mxt,
        const float* __restrict__ gW, const float* __restrict__ uW,
        const float* __restrict__ gb, const float* __restrict__ ub,
        float* __restrict__ cg, float* __restrict__ cu, int Cin) {
    const int C = Cin + HH;
    __shared__ float xs[64][2];
    __shared__ float ms[64][2];
    int n = blockIdx.x;
    int r0 = blockIdx.y * 64;
    int tid = threadIdx.x;
    for (int idx = tid; idx < 64*Cin; idx += 192) {
        int r = idx / Cin, c = idx - r*Cin;
        int z = r0 + r;
        xs[r][c] = xt[((size_t)z*NN + n)*Cin + c];
        int g = z*Cin + c;
        ms[r][c] = mxt[((size_t)(g>>6)*NN + n)*64 + (g&63)];
    }
    __syncthreads();
    float a[64];
    #pragma unroll
    for (int i = 0; i < 64; ++i) a[i] = 0.f;
    if (tid < 128) {
        int o = tid;
        const float* W0 = gW + (size_t)(n*2)*C*128 + o;
        const float* W1 = gW + (size_t)(n*2+1)*C*128 + o;
        for (int c = 0; c < Cin; ++c) {
            float w0 = W0[c*128], w1 = W1[c*128];
            #pragma unroll
            for (int r = 0; r < 64; ++r) a[r] += xs[r][c]*w0 + ms[r][c]*w1;
        }
        float bias = gb[n*128 + o];
        for (int r = 0; r < 64; ++r) {
            int z = r0 + r; int b = z / 12, t = z - b*12;
            cg[(((size_t)t*BB + b)*NN + n)*128 + o] = a[r] + bias;
        }
    } else {
        int o = tid - 128;
        const float* W0 = uW + (size_t)(n*2)*C*64 + o;
        const float* W1 = uW + (size_t)(n*2+1)*C*64 + o;
        for (int c = 0; c < Cin; ++c) {
            float w0 = W0[c*64], w1 = W1[c*64];
            #pragma unroll
            for (int r = 0; r < 64; ++r) a[r] += xs[r][c]*w0 + ms[r][c]*w1;
        }
        float bias = ub[n*64 + o];
        for (int r = 0; r < 64; ++r) {
            int z = r0 + r; int b = z / 12, t = z - b*12;
            cu[(((size_t)t*BB + b)*NN + n)*64 + o] = a[r] + bias;
        }
    }
}

__global__ void __launch_bounds__(256) k_precomp_mma(
        const float* __restrict__ xt, const float* __restrict__ mxt,
        const float* __restrict__ gW, const float* __restrict__ uW,
        const float* __restrict__ gb, const float* __restrict__ ub,
        float* __restrict__ cg, float* __restrict__ cu) {
    const int C = 128;
    __shared__ float As[128][36];
    __shared__ float Bs[32][200];
    int n = blockIdx.x;
    int m0 = blockIdx.y * 128;
    int tid = threadIdx.x;
    int warp = tid >> 5, lane = tid & 31;
    int wm = warp >> 1, wn = warp & 1;
    float acc[2][12][4];
    #pragma unroll
    for (int mt=0;mt<2;++mt) for (int j=0;j<12;++j) for (int q=0;q<4;++q) acc[mt][j][q]=0.f;
    for (int kc = 0; kc < 128; kc += 32) {
        #pragma unroll
        for (int i = 0; i < 4; ++i) {
            int idx = tid + i*256;
            int row = idx >> 3;
            int c4 = (idx & 7) * 4;
            int z = m0 + row;
            int k = kc + c4;
            float4 v = (k < 64)
                ? *(const float4*)&xt[((size_t)z*NN + n)*64 + k]
                : *(const float4*)&mxt[((size_t)z*NN + n)*64 + k - 64];
            *(float4*)&As[row][c4] = tf32x4(v);
        }
        #pragma unroll
        for (int i = 0; i < 6; ++i) {
            int idx = tid + i*256;
            int krow = idx / 48;
            int c4 = (idx % 48) * 4;
            int kk = kc + krow;
            const float* src = (c4 < 128)
                ? gW + ((size_t)(2*n + (kk>=64))*C + (kk&63))*128 + c4
                : uW + ((size_t)(2*n + (kk>=64))*C + (kk&63))*64 + (c4 - 128);
            *(float4*)&Bs[krow][c4] = tf32x4(*(const float4*)src);
        }
        __syncthreads();
        #pragma unroll
        for (int k8 = 0; k8 < 32; k8 += 8) {
            uint32_t a[2][4];
            int ac = k8 + (lane&3);
            #pragma unroll
            for (int mt = 0; mt < 2; ++mt) {
                int rr = wm*32 + mt*16 + (lane>>2);
                a[mt][0] = __float_as_uint(As[rr][ac]);
                a[mt][1] = __float_as_uint(As[rr+8][ac]);
                a[mt][2] = __float_as_uint(As[rr][ac+4]);
                a[mt][3] = __float_as_uint(As[rr+8][ac+4]);
            }
            #pragma unroll
            for (int j = 0; j < 12; ++j) {
                int col = wn*96 + j*8 + (lane>>2);
                uint32_t b0 = __float_as_uint(Bs[k8 + (lane&3)][col]);
                uint32_t b1 = __float_as_uint(Bs[k8 + (lane&3) + 4][col]);
                mma_tf32(acc[0][j], a[0], b0, b1);
                mma_tf32(acc[1][j], a[1], b0, b1);
            }
        }
        __syncthreads();
    }
    #pragma unroll
    for (int mt = 0; mt < 2; ++mt) {
        #pragma unroll
        for (int j = 0; j < 12; ++j) {
            int col = wn*96 + j*8 + (lane&3)*2;
            #pragma unroll
            for (int half = 0; half < 2; ++half) {
                int z = m0 + wm*32 + mt*16 + (lane>>2) + half*8;
                int b = z / 12, t = z - b*12;
                float v0 = acc[mt][j][half*2], v1 = acc[mt][j][half*2+1];
                if (col < 128) {
                    float2 bb = *(const float2*)&gb[n*128 + col];
                    *(float2*)&cg[(((size_t)t*BB + b)*NN + n)*128 + col] =
                        make_float2(v0 + bb.x, v1 + bb.y);
                } else {
                    int o = col - 128;
                    float2 bb = *(const float2*)&ub[n*64 + o];
                    *(float2*)&cu[(((size_t)t*BB + b)*NN + n)*64 + o] =
                        make_float2(v0 + bb.x, v1 + bb.y);
                }
            }
        }
    }
}

// ---------------- hypernetwork: split-K MMA GEMM ----------------
__global__ void __launch_bounds__(256) k_hyp_mma(const float* __restrict__ hypW) {
    __shared__ float As[128][36];
    __shared__ float Bs[32][56];
    int m0 = blockIdx.x * 128;
    int k0 = blockIdx.y * 1024;
    int tid = threadIdx.x, warp = tid >> 5, lane = tid & 31;
    int wm = warp >> 1, wn = warp & 1;
    float acc[2][3][4];
    #pragma unroll
    for (int mt=0;mt<2;++mt) for (int j=0;j<3;++j) for (int q=0;q<4;++q) acc[mt][j][q]=0.f;
    for (int kc = k0; kc < k0 + 1024; kc += 32) {
        #pragma unroll
        for (int i = 0; i < 4; ++i) {
            int idx = tid + i*256;
            int row = idx >> 3;
            int c4 = (idx & 7) * 4;
            *(float4*)&As[row][c4] = tf32x4(*(const float4*)&g_uW[(size_t)(m0+row)*16384 + kc + c4]);
        }
        if (tid < 128) {
            int krow = tid / 4, c4a = (tid % 4) * 4;
            #pragma unroll
            for (int seg = 0; seg < 3; ++seg) {
                int c4 = c4a + seg*16;
                if (c4 < 48)
                    *(float4*)&Bs[krow][c4] = tf32x4(*(const float4*)&hypW[(size_t)(kc+krow)*48 + c4]);
            }
        }
        __syncthreads();
        #pragma unroll
        for (int k8 = 0; k8 < 32; k8 += 8) {
            uint32_t a[2][4];
            int ac = k8 + (lane&3);
            #pragma unroll
            for (int mt = 0; mt < 2; ++mt) {
                int rr = wm*32 + mt*16 + (lane>>2);
                a[mt][0] = __float_as_uint(As[rr][ac]);
                a[mt][1] = __float_as_uint(As[rr+8][ac]);
                a[mt][2] = __float_as_uint(As[rr][ac+4]);
                a[mt][3] = __float_as_uint(As[rr+8][ac+4]);
            }
            #pragma unroll
            for (int j = 0; j < 3; ++j) {
                int col = wn*24 + j*8 + (lane>>2);
                uint32_t b0 = __float_as_uint(Bs[k8 + (lane&3)][col]);
                uint32_t b1 = __float_as_uint(Bs[k8 + (lane&3) + 4][col]);
                mma_tf32(acc[0][j], a[0], b0, b1);
                mma_tf32(acc[1][j], a[1], b0, b1);
            }
        }
        __syncthreads();
    }
    #pragma unroll
    for (int mt = 0; mt < 2; ++mt)
    #pragma unroll
    for (int j = 0; j < 3; ++j) {
        int col = wn*24 + j*8 + (lane&3)*2;
        int row = m0 + wm*32 + mt*16 + (lane>>2);
        atomicAdd(&g_hlin[row*48 + col],   acc[mt][j][0]);
        atomicAdd(&g_hlin[row*48 + col+1], acc[mt][j][1]);
        atomicAdd(&g_hlin[(row+8)*48 + col],   acc[mt][j][2]);
        atomicAdd(&g_hlin[(row+8)*48 + col+1], acc[mt][j][3]);
    }
}

__global__ void k_hyp_fin(const float* __restrict__ hypb) {
    int idx = blockIdx.x*blockDim.x + threadIdx.x;
    if (idx >= NN*TT) return;
    int t = idx % TT, n = idx / TT;
    float s = 0.f;
    #pragma unroll
    for (int f = 0; f < 4; ++f) s += g_hlin[n*48 + t*4 + f] + hypb[t*4 + f];
    g_fs[n*TT + t] = s;
}

__global__ void k_copy_last() {
    int idx = blockIdx.x*blockDim.x + threadIdx.x;
    if (idx >= BB*NN*HH) return;
    int c = idx & 63;
    int bn = idx >> 6;
    int n = bn & 511, b = bn >> 9;
    g_hv[idx] = g_hs1[(((size_t)b*TT + (TT-1))*NN + n)*64 + c];
}

__global__ void __launch_bounds__(256) k_gemm64_mma(
        const float* __restrict__ X, const float* __restrict__ W,
        const float* __restrict__ bias, float* __restrict__ Y, int relu) {
    __shared__ float Xs[128][36];
    __shared__ float Ws[32][72];
    int r0 = blockIdx.x * 128;
    int tid = threadIdx.x;
    int warp = tid >> 5, lane = tid & 31;
    float acc[8][4];
    #pragma unroll
    for (int j=0;j<8;++j) for (int q=0;q<4;++q) acc[j][q]=0.f;
    for (int kc = 0; kc < 64; kc += 32) {
        #pragma unroll
        for (int i = 0; i < 4; ++i) {
            int idx = tid + i*256;
            int row = idx >> 3;
            int c4 = (idx & 7) * 4;
            *(float4*)&Xs[row][c4] = tf32x4(*(const float4*)&X[(size_t)(r0+row)*64 + kc + c4]);
        }
        #pragma unroll
        for (int i = 0; i < 2; ++i) {
            int idx = tid + i*256;
            int krow = idx >> 4;
            int c4 = (idx & 15) * 4;
            *(float4*)&Ws[krow][c4] = tf32x4(*(const float4*)&W[(size_t)(kc+krow)*64 + c4]);
        }
        __syncthreads();
        #pragma unroll
        for (int k8 = 0; k8 < 32; k8 += 8) {
            uint32_t a[4];
            int ar = warp*16 + (lane>>2);
            int ac = k8 + (lane&3);
            a[0] = __float_as_uint(Xs[ar][ac]);
            a[1] = __float_as_uint(Xs[ar+8][ac]);
            a[2] = __float_as_uint(Xs[ar][ac+4]);
            a[3] = __float_as_uint(Xs[ar+8][ac+4]);
            #pragma unroll
            for (int j = 0; j < 8; ++j) {
                uint32_t b0 = __float_as_uint(Ws[k8 + (lane&3)][j*8 + (lane>>2)]);
                uint32_t b1 = __float_as_uint(Ws[k8 + (lane&3) + 4][j*8 + (lane>>2)]);
                mma_tf32(acc[j], a, b0, b1);
            }
        }
        __syncthreads();
    }
    int row = r0 + warp*16 + (lane>>2);
    #pragma unroll
    for (int j = 0; j < 8; ++j) {
        int col = j*8 + (lane&3)*2;
        float b0 = bias ? bias[col] : 0.f, b1 = bias ? bias[col+1] : 0.f;
        float v0 = acc[j][0] + b0, v1 = acc[j][1] + b1;
        float v2 = acc[j][2] + b0, v3 = acc[j][3] + b1;
        if (relu) { v0=fmaxf(v0,0.f); v1=fmaxf(v1,0.f); v2=fmaxf(v2,0.f); v3=fmaxf(v3,0.f); }
        *(float2*)&Y[(size_t)row*64 + col] = make_float2(v0, v1);
        *(float2*)&Y[(size_t)(row+8)*64 + col] = make_float2(v2, v3);
    }
}

__global__ void k_attn(const float* __restrict__ bv) {
    __shared__ float qs[12][64], ks[12][64], vs[12][64];
    __shared__ float sc[2][12][12];
    int bn = blockIdx.x;
    int b = bn >> 9, n = bn & 511;
    int tid = threadIdx.x;
    for (int idx = tid; idx < 12*64; idx += 128) {
        int t = idx >> 6, c = idx & 63;
        size_t g = (((size_t)b*TT + t)*NN + n)*HH + c;
        qs[t][c] = g_q[g];
        ks[t][c] = g_k[g];
        vs[t][c] = g_fs[n*TT + t] * g_v[((size_t)b*NN + n)*64 + c] + bv[c];
    }
    __syncthreads();
    for (int idx = tid; idx < 288; idx += 128) {
        int h = idx / 144, rem = idx - h*144;
        int t = rem / 12, s = rem - t*12;
        float d = 0.f;
        #pragma unroll
        for (int k = 0; k < 32; ++k) d += qs[t][h*32 + k] * ks[s][h*32 + k];
        sc[h][t][s] = d * 0.17677669529663687f;
    }
    __syncthreads();
    if (tid < 24) {
        int h = tid / 12, t = tid - h*12;
        float mx = -1e30f;
        #pragma unroll
        for (int s = 0; s < 12; ++s) mx = fmaxf(mx, sc[h][t][s]);
        float sum = 0.f;
        #pragma unroll
        for (int s = 0; s < 12; ++s) { float e = __expf(sc[h][t][s] - mx); sc[h][t][s] = e; sum += e; }
        float inv = 1.f / sum;
        #pragma unroll
        for (int s = 0; s < 12; ++s) sc[h][t][s] *= inv;
    }
    __syncthreads();
    for (int idx = tid; idx < 768; idx += 128) {
        int h = idx / 384, rem = idx - h*384;
        int t = rem >> 5, d = rem & 31;
        float a = 0.f;
        #pragma unroll
        for (int s = 0; s < 12; ++s) a += sc[h][t][s] * vs[s][h*32 + d];
        g_o[(((size_t)b*TT + t)*NN + n)*HH + h*32 + d] = a;
    }
}

__global__ void __launch_bounds__(256) k_lnres_w(
        const float* __restrict__ A, const float* __restrict__ Bv,
        const float* __restrict__ g, const float* __restrict__ be,
        float* __restrict__ Y) {
    int lane = threadIdx.x & 31;
    size_t row = (size_t)blockIdx.x * 8 + (threadIdx.x >> 5);
    int c = lane * 2;
    float2 a = *(const float2*)&A[row*64 + c];
    float2 b2 = *(const float2*)&Bv[row*64 + c];
    float x0 = a.x + b2.x, x1 = a.y + b2.y;
    float s = x0 + x1, sq = x0*x0 + x1*x1;
    #pragma unroll
    for (int o = 16; o > 0; o >>= 1) {
        s  += __shfl_xor_sync(0xffffffffu, s, o);
        sq += __shfl_xor_sync(0xffffffffu, sq, o);
    }
    float mu = s * (1.f/64.f);
    float var = sq * (1.f/64.f) - mu*mu;
    float rstd = rsqrtf(var + 1e-5f);
    float y0 = (x0 - mu) * rstd * g[c] + be[c];
    float y1 = (x1 - mu) * rstd * g[c+1] + be[c+1];
    *(float2*)&Y[row*64 + c] = make_float2(y0, y1);
}

__global__ void __launch_bounds__(256) k_fc_w(
        const float* __restrict__ X, const float* __restrict__ w,
        const float* __restrict__ bp, float* __restrict__ Y) {
    int lane = threadIdx.x & 31;
    size_t row = (size_t)blockIdx.x * 8 + (threadIdx.x >> 5);
    int c = lane * 2;
    float2 x = *(const float2*)&X[row*64 + c];
    float s = x.x * w[c] + x.y * w[c+1];
    #pragma unroll
    for (int o = 16; o > 0; o >>= 1) s += __shfl_xor_sync(0xffffffffu, s, o);
    if (lane == 0) Y[row] = s + bp[0];
}

// ---------------- host ----------------
extern "C" void kernel_launch(void* const* d_in, const int* in_sizes, int n_in,
                              void* d_out, int out_size) {
    const float* src  = (const float*)d_in[0];
    const float* emb  = (const float*)d_in[2];
    const float* gwp0 = (const float*)d_in[3];
    const float* gbp0 = (const float*)d_in[4];
    const float* uwp0 = (const float*)d_in[5];
    const float* ubp0 = (const float*)d_in[6];
    const float* gwp1 = (const float*)d_in[7];
    const float* gbp1 = (const float*)d_in[8];
    const float* uwp1 = (const float*)d_in[9];
    const float* ubp1 = (const float*)d_in[10];
    const float* hypW = (const float*)d_in[11];
    const float* hypb = (const float*)d_in[12];

    const float *Wq,*Wk,*Wv,*ffW1,*ffW2,*bq,*bk,*bv,*ffb1,*ffb2,*ln1g,*ln1b,*ln2g,*ln2b,*fcW,*fcb;
    if (n_in > 14 && in_sizes[14] == 64) {
        Wq  = (const float*)d_in[13]; bq  = (const float*)d_in[14];
        Wk  = (const float*)d_in[15]; bk  = (const float*)d_in[16];
        Wv  = (const float*)d_in[17]; bv  = (const float*)d_in[18];
        ln1g= (const float*)d_in[19]; ln1b= (const float*)d_in[20];
        ffW1= (const float*)d_in[21]; ffb1= (const float*)d_in[22];
        ffW2= (const float*)d_in[23]; ffb2= (const float*)d_in[24];
        ln2g= (const float*)d_in[25]; ln2b= (const float*)d_in[26];
        fcW = (const float*)d_in[27]; fcb = (const float*)d_in[28];
    } else {
        Wq  = (const float*)d_in[13]; Wk  = (const float*)d_in[14];
        Wv  = (const float*)d_in[15]; ffW1= (const float*)d_in[16];
        ffW2= (const float*)d_in[17]; bq  = (const float*)d_in[18];
        bk  = (const float*)d_in[19]; bv  = (const float*)d_in[20];
        ffb1= (const float*)d_in[21]; ffb2= (const float*)d_in[22];
        ln1g= (const float*)d_in[23]; ln1b= (const float*)d_in[24];
        ln2g= (const float*)d_in[25]; ln2b= (const float*)d_in[26];
        fcW = (const float*)d_in[27]; fcb = (const float*)d_in[28];
    }

    float *p_gW,*p_gb,*p_uW,*p_ub,*p_cg,*p_cu,*p_mxt,*p_xt0t;
    float *p_hs0,*p_hs1,*p_hv,*p_q,*p_k,*p_v,*p_o,*p_val,*p_ff1,*p_ffo,*p_out2;
    cudaGetSymbolAddress((void**)&p_gW, g_gW);
    cudaGetSymbolAddress((void**)&p_gb, g_gb);
    cudaGetSymbolAddress((void**)&p_uW, g_uW);
    cudaGetSymbolAddress((void**)&p_ub, g_ub);
    cudaGetSymbolAddress((void**)&p_cg, g_cg);
    cudaGetSymbolAddress((void**)&p_cu, g_cu);
    cudaGetSymbolAddress((void**)&p_mxt, g_mxt);
    cudaGetSymbolAddress((void**)&p_xt0t, g_xt0t);
    cudaGetSymbolAddress((void**)&p_hs0, g_hs0);
    cudaGetSymbolAddress((void**)&p_hs1, g_hs1);
    cudaGetSymbolAddress((void**)&p_hv, g_hv);
    cudaGetSymbolAddress((void**)&p_q, g_q);
    cudaGetSymbolAddress((void**)&p_k, g_k);
    cudaGetSymbolAddress((void**)&p_v, g_v);
    cudaGetSymbolAddress((void**)&p_o, g_o);
    cudaGetSymbolAddress((void**)&p_val, g_val);
    cudaGetSymbolAddress((void**)&p_ff1, g_ff1);
    cudaGetSymbolAddress((void**)&p_ffo, g_ffo);
    cudaGetSymbolAddress((void**)&p_out2, g_out2);

    cudaFuncSetAttribute(k_recur, cudaFuncAttributeMaxDynamicSharedMemorySize, RECUR_SMEM);

    k_adj<<<NN, 256>>>(emb);

    for (int layer = 0; layer < 2; ++layer) {
        int Cin = (layer == 0) ? 2 : 64;
        int C = Cin + HH;
        float* hs_out;
        if (layer == 0) {
            int s;
            s = 2*C*128/4; k_matpool4<<<(NN*s+255)/256, 256>>>(emb, gwp0, p_gW, s);
            s = 128/4;     k_matpool4<<<(NN*s+255)/256, 256>>>(emb, gbp0, p_gb, s);
            s = 2*C*64/4;  k_matpool4<<<(NN*s+255)/256, 256>>>(emb, uwp0, p_uW, s);
            s = 64/4;      k_matpool4<<<(NN*s+255)/256, 256>>>(emb, ubp0, p_ub, s);
            k_transp0<<<(ZT*NN*2 + 255)/256, 256>>>(src, p_xt0t);
            k_mix64<<<dim3(8, (ZT*2)/64), 256>>>(p_xt0t, p_mxt);
            k_precomp<<<dim3(NN, 6), 192>>>(src, p_mxt, p_gW, p_uW, p_gb, p_ub, p_cg, p_cu, Cin);
            hs_out = p_hs0;
        } else {
            int s;
            s = 2*C*128/4; k_matpool4<<<(NN*s+255)/256, 256>>>(emb, gwp1, p_gW, s);
            s = 128/4;     k_matpool4<<<(NN*s+255)/256, 256>>>(emb, gbp1, p_gb, s);
            s = 2*C*64/4;  k_matpool4<<<(NN*s+255)/256, 256>>>(emb, ubp1 ? uwp1 : uwp1, p_uW, s);
            s = 64/4;      k_matpool4<<<(NN*s+255)/256, 256>>>(emb, ubp1, p_ub, s);
            k_mix64<<<dim3(8, ZT), 256>>>(p_hs0, p_mxt);
            k_precomp_mma<<<dim3(NN, 3), 256>>>(p_hs0, p_mxt, p_gW, p_uW, p_gb, p_ub, p_cg, p_cu);
            hs_out = p_hs1;
        }
        unsigned nbar0 = (layer == 0) ? 0u : 45u;   // 1 + 11*4 barriers per layer
        k_recur<<<GRID_P, 256, RECUR_SMEM>>>(p_gW, p_uW, p_cg, p_cu, hs_out, C, Cin, nbar0);
    }

    k_hyp_mma<<<dim3(4, 16), 256>>>(hypW);
    k_hyp_fin<<<(NN*TT + 255)/256, 256>>>(hypb);
    k_copy_last<<<(BB*NN*HH + 255)/256, 256>>>();

    k_gemm64_mma<<<BTN/128, 256>>>(p_hs1, Wq, bq, p_q, 0);
    k_gemm64_mma<<<BTN/128, 256>>>(p_hs1, Wk, bk, p_k, 0);
    k_gemm64_mma<<<BB*NN/128, 256>>>(p_hv, Wv, nullptr, p_v, 0);

    k_attn<<<BB*NN, 128>>>(bv);

    k_lnres_w<<<BTN/8, 256>>>(p_o, p_hs1, ln1g, ln1b, p_val);
    k_gemm64_mma<<<BTN/128, 256>>>(p_val, ffW1, ffb1, p_ff1, 1);
    k_gemm64_mma<<<BTN/128, 256>>>(p_ff1, ffW2, ffb2, p_ffo, 0);
    k_lnres_w<<<BTN/8, 256>>>(p_ffo, p_val, ln2g, ln2b, p_out2);
    k_fc_w<<<BTN/8, 256>>>(p_out2, fcW, fcb, (float*)d_out);
}